// round 12
// baseline (speedup 1.0000x reference)
#include <cuda_runtime.h>
#include <cuda_fp16.h>
#include <cstdint>

#define BATCH 4
#define CH 256
#define HH 128
#define WW 128
#define HP 32
#define WP 32
#define LL 1024
#define NHEAD 8
#define DH 32
#define C2 512
#define NPIX (BATCH*HH*WW)
#define NROWS (2*NPIX)
#define EPSF 1e-5f
#define TSCALE 0.17677669529663687f
#define NEGINF (-3.402823466e38f)
#define NTILES 16

// ---------------- scratch ----------------
__device__ float  g_p[2][BATCH*CH*LL];
__device__ float  g_lnps[2*BATCH*8*LL];
__device__ float  g_lnpq[2*BATCH*8*LL];
__device__ float  g_mu1[2*BATCH*LL];
__device__ float  g_rs1[2*BATCH*LL];
__device__ __half g_qh[2][(size_t)BATCH*LL*CH];        // q/k heads fp16
__device__ __half g_vh[2][(size_t)BATCH*LL*CH];        // v heads fp16
__device__ __half g_qkh[(size_t)BATCH*NHEAD*LL*LL];    // fp16 logits
__device__ __half g_s2t[(size_t)BATCH*NHEAD*LL*LL];    // S2 transposed [h][s][l]
__device__ float  g_pmax[(size_t)BATCH*NHEAD*LL*NTILES];
__device__ float  g_psum[(size_t)BATCH*NHEAD*LL*NTILES];
__device__ float  g_rmax[BATCH*NHEAD*LL];
__device__ float  g_rinv[BATCH*NHEAD*LL];
__device__ __half g_m[2][(size_t)BATCH*LL*CH];
__device__ float  g_mm[2][(size_t)BATCH*LL*CH];
__device__ __half g_u[(size_t)NROWS*C2];
__device__ __half g_z1[(size_t)NROWS*C2];
__device__ __half g_z2h[(size_t)NROWS*CH];             // fp16 now
__device__ __half g_mwh[CH*CH];
__device__ __half g_w1h[C2*C2];
__device__ __half g_w2h[CH*C2];

// ================= helpers =================
__device__ __forceinline__ uint32_t smem_u32(const void* p) {
    uint32_t a;
    asm("{ .reg .u64 t; cvta.to.shared.u64 t, %1; cvt.u32.u64 %0, t; }" : "=r"(a) : "l"(p));
    return a;
}
#define CP_ASYNC16(dst, src) \
    asm volatile("cp.async.cg.shared.global [%0], [%1], 16;" :: "r"(dst), "l"(src) : "memory")
#define CP_COMMIT() asm volatile("cp.async.commit_group;" ::: "memory")
#define CP_WAIT(n)  asm volatile("cp.async.wait_group %0;" :: "n"(n) : "memory")
#define LDSM_X4(r0, r1, r2, r3, addr) \
    asm volatile("ldmatrix.sync.aligned.m8n8.x4.shared.b16 {%0,%1,%2,%3}, [%4];" \
        : "=r"(r0), "=r"(r1), "=r"(r2), "=r"(r3) : "r"(addr))
#define LDSM_X4_T(r0, r1, r2, r3, addr) \
    asm volatile("ldmatrix.sync.aligned.m8n8.x4.trans.shared.b16 {%0,%1,%2,%3}, [%4];" \
        : "=r"(r0), "=r"(r1), "=r"(r2), "=r"(r3) : "r"(addr))

__device__ __forceinline__ void mma_f16(float* d, const uint32_t* a, uint32_t b0, uint32_t b1) {
    asm volatile(
        "mma.sync.aligned.m16n8k16.row.col.f32.f16.f16.f32 "
        "{%0,%1,%2,%3}, {%4,%5,%6,%7}, {%8,%9}, {%0,%1,%2,%3};"
        : "+f"(d[0]), "+f"(d[1]), "+f"(d[2]), "+f"(d[3])
        : "r"(a[0]), "r"(a[1]), "r"(a[2]), "r"(a[3]), "r"(b0), "r"(b1));
}

// ===== fp16 mma GEMM: CTA 256x128, warp tile 64x64, BK=64, 3-stage cp.async =====
#define PADH 72
#define TILE_A_BYTES (256*PADH*2)      /* 36864 */
#define TILE_B_BYTES (128*PADH*2)      /* 18432 */
#define STAGE_BYTES  (TILE_A_BYTES + TILE_B_BYTES)   /* 55296 */
#define GEMM_SMEM    (3*STAGE_BYTES)   /* 165888 */

__global__ __launch_bounds__(256) void hgemm_kernel(
        const __half* __restrict__ A, const __half* __restrict__ Bw, void* __restrict__ C,
        int M, int N, int K, int relu, int outHalf) {
    extern __shared__ __half smh[];
    int tid = threadIdx.x, wid = tid >> 5, lane = tid & 31;
    int g = lane >> 2, t = lane & 3;
    int r = lane & 7, quad = lane >> 3;
    int wm = wid >> 1, wn = wid & 1;               // warp tile (wm*64, wn*64)
    size_t am0 = (size_t)blockIdx.y * 256;
    size_t bn0 = (size_t)blockIdx.x * 128;
    uint32_t smembase = smem_u32(smh);

    uint32_t a_off[4], b_off[4];
    #pragma unroll
    for (int mt = 0; mt < 4; mt++)
        a_off[mt] = (uint32_t)(((wm*64 + mt*16 + (quad&1)*8 + r)*PADH + (quad>>1)*8) * 2);
    #pragma unroll
    for (int p = 0; p < 4; p++)
        b_off[p] = (uint32_t)(((wn*64 + p*16 + (quad>>1)*8 + r)*PADH + (quad&1)*8) * 2);

    int nchunk = K >> 6;
    float acc[4][8][4];
    #pragma unroll
    for (int mt = 0; mt < 4; mt++)
        #pragma unroll
        for (int nt = 0; nt < 8; nt++)
            #pragma unroll
            for (int i = 0; i < 4; i++) acc[mt][nt][i] = 0.f;

    auto issue = [&](int ch, int st) {
        const __half* Ag = A + am0 * K + ch*64;
        const __half* Bg = Bw + bn0 * K + ch*64;
        uint32_t base = smembase + st*STAGE_BYTES;
        #pragma unroll
        for (int j = 0; j < 8; j++) {                 // A: 256 rows x 8 segs
            int idx = tid + j * 256;
            int row = idx >> 3, seg = idx & 7;
            CP_ASYNC16(base + (uint32_t)((row*PADH + seg*8)*2), Ag + (size_t)row*K + seg*8);
        }
        #pragma unroll
        for (int j = 0; j < 4; j++) {                 // B: 128 rows x 8 segs
            int idx = tid + j * 256;
            int row = idx >> 3, seg = idx & 7;
            CP_ASYNC16(base + TILE_A_BYTES + (uint32_t)((row*PADH + seg*8)*2),
                       Bg + (size_t)row*K + seg*8);
        }
        CP_COMMIT();
    };

    issue(0, 0);
    if (nchunk > 1) issue(1, 1);

    for (int i = 0; i < nchunk; i++) {
        int s = i % 3;
        if (i + 2 < nchunk) { issue(i + 2, (i + 2) % 3); CP_WAIT(2); }
        else if (i + 1 < nchunk) { CP_WAIT(1); }
        else { CP_WAIT(0); }
        __syncthreads();

        uint32_t abase = smembase + s*STAGE_BYTES;
        uint32_t bbase = abase + TILE_A_BYTES;
        #pragma unroll
        for (int ks = 0; ks < 4; ks++) {
            uint32_t koff = (uint32_t)(ks * 32);
            uint32_t af[4][4];
            #pragma unroll
            for (int mt = 0; mt < 4; mt++)
                LDSM_X4(af[mt][0], af[mt][1], af[mt][2], af[mt][3], abase + a_off[mt] + koff);
            #pragma unroll
            for (int p = 0; p < 4; p++) {
                uint32_t b0, b1, b2, b3;
                LDSM_X4(b0, b1, b2, b3, bbase + b_off[p] + koff);
                #pragma unroll
                for (int mt = 0; mt < 4; mt++) {
                    mma_f16(acc[mt][2*p],   af[mt], b0, b1);
                    mma_f16(acc[mt][2*p+1], af[mt], b2, b3);
                }
            }
        }
        __syncthreads();
    }

    #pragma unroll
    for (int mt = 0; mt < 4; mt++) {
        size_t row = am0 + wm*64 + mt*16 + g;
        #pragma unroll
        for (int nt = 0; nt < 8; nt++) {
            size_t col = bn0 + wn*64 + nt*8 + 2*t;
            float v0 = acc[mt][nt][0], v1 = acc[mt][nt][1];
            float v2 = acc[mt][nt][2], v3 = acc[mt][nt][3];
            if (relu) {
                v0 = fmaxf(v0,0.f); v1 = fmaxf(v1,0.f);
                v2 = fmaxf(v2,0.f); v3 = fmaxf(v3,0.f);
            }
            if (outHalf) {
                __half* Ch = (__half*)C;
                *(__half2*)(Ch + row*N + col)     = __floats2half2_rn(v0, v1);
                *(__half2*)(Ch + (row+8)*N + col) = __floats2half2_rn(v2, v3);
            } else {
                float* Cf = (float*)C;
                *(float2*)(Cf + row*N + col)     = make_float2(v0, v1);
                *(float2*)(Cf + (row+8)*N + col) = make_float2(v2, v3);
            }
        }
    }
}

// ================= QK tensor-core GEMM: logits + softmax partials =================
#define PADQ 40
__global__ __launch_bounds__(256) void qkmma_kernel() {
    __shared__ __half qs[2][128*PADQ];
    int tid = threadIdx.x, wid = tid >> 5, lane = tid & 31;
    int g = lane >> 2, t = lane & 3;
    int r = lane & 7, quad = lane >> 3;
    int wm = wid >> 1, wn = wid & 1;
    int n = blockIdx.z >> 3, h = blockIdx.z & 7;
    int l0 = blockIdx.y * 128, s0 = blockIdx.x * 128;
    uint32_t abase = smem_u32(qs[0]);
    uint32_t bbase = smem_u32(qs[1]);

    #pragma unroll
    for (int j = 0; j < 2; j++) {
        int idx = tid + j*256;
        int row = idx >> 2, seg = idx & 3;
        uint32_t d = (uint32_t)((row*PADQ + seg*8) * 2);
        const __half* Aq = g_qh[0] + ((size_t)(n*LL + l0 + row))*CH + h*DH + seg*8;
        const __half* Bq = g_qh[1] + ((size_t)(n*LL + s0 + row))*CH + h*DH + seg*8;
        CP_ASYNC16(abase + d, Aq);
        CP_ASYNC16(bbase + d, Bq);
    }
    CP_COMMIT();
    CP_WAIT(0);
    __syncthreads();

    uint32_t a_off[2], b_off[4];
    #pragma unroll
    for (int mt = 0; mt < 2; mt++)
        a_off[mt] = (uint32_t)(((wm*32 + mt*16 + (quad&1)*8 + r)*PADQ + (quad>>1)*8) * 2);
    #pragma unroll
    for (int p = 0; p < 4; p++)
        b_off[p] = (uint32_t)(((wn*64 + p*16 + (quad>>1)*8 + r)*PADQ + (quad&1)*8) * 2);

    float acc[2][8][4];
    #pragma unroll
    for (int mt = 0; mt < 2; mt++)
        #pragma unroll
        for (int nt = 0; nt < 8; nt++)
            #pragma unroll
            for (int i = 0; i < 4; i++) acc[mt][nt][i] = 0.f;

    #pragma unroll
    for (int ks = 0; ks < 2; ks++) {
        uint32_t koff = (uint32_t)(ks * 32);
        uint32_t af[2][4];
        LDSM_X4(af[0][0], af[0][1], af[0][2], af[0][3], abase + a_off[0] + koff);
        LDSM_X4(af[1][0], af[1][1], af[1][2], af[1][3], abase + a_off[1] + koff);
        #pragma unroll
        for (int p = 0; p < 4; p++) {
            uint32_t b0, b1, b2, b3;
            LDSM_X4(b0, b1, b2, b3, bbase + b_off[p] + koff);
            mma_f16(acc[0][2*p],   af[0], b0, b1);
            mma_f16(acc[1][2*p],   af[1], b0, b1);
            mma_f16(acc[0][2*p+1], af[0], b2, b3);
            mma_f16(acc[1][2*p+1], af[1], b2, b3);
        }
    }

    size_t qkbase = ((size_t)(n*NHEAD + h))*LL;
    int tile = blockIdx.x*2 + wn;
    #pragma unroll
    for (int mt = 0; mt < 2; mt++) {
        int row0 = l0 + wm*32 + mt*16 + g;
        float mx0 = NEGINF, mx1 = NEGINF;
        float vals[8][4];
        #pragma unroll
        for (int nt = 0; nt < 8; nt++) {
            #pragma unroll
            for (int i = 0; i < 4; i++) vals[nt][i] = TSCALE*acc[mt][nt][i];
            int col = s0 + wn*64 + nt*8 + 2*t;
            *(__half2*)(g_qkh + (qkbase + row0)*LL + col)   = __floats2half2_rn(vals[nt][0], vals[nt][1]);
            *(__half2*)(g_qkh + (qkbase + row0+8)*LL + col) = __floats2half2_rn(vals[nt][2], vals[nt][3]);
            mx0 = fmaxf(mx0, fmaxf(vals[nt][0], vals[nt][1]));
            mx1 = fmaxf(mx1, fmaxf(vals[nt][2], vals[nt][3]));
        }
        #pragma unroll
        for (int off = 1; off <= 2; off <<= 1) {
            mx0 = fmaxf(mx0, __shfl_xor_sync(0xffffffffu, mx0, off));
            mx1 = fmaxf(mx1, __shfl_xor_sync(0xffffffffu, mx1, off));
        }
        float sm0 = 0.f, sm1 = 0.f;
        #pragma unroll
        for (int nt = 0; nt < 8; nt++) {
            sm0 += __expf(vals[nt][0]-mx0) + __expf(vals[nt][1]-mx0);
            sm1 += __expf(vals[nt][2]-mx1) + __expf(vals[nt][3]-mx1);
        }
        #pragma unroll
        for (int off = 1; off <= 2; off <<= 1) {
            sm0 += __shfl_xor_sync(0xffffffffu, sm0, off);
            sm1 += __shfl_xor_sync(0xffffffffu, sm1, off);
        }
        if (t == 0) {
            g_pmax[(qkbase + row0)*NTILES + tile]   = mx0;
            g_psum[(qkbase + row0)*NTILES + tile]   = sm0;
            g_pmax[(qkbase + row0+8)*NTILES + tile] = mx1;
            g_psum[(qkbase + row0+8)*NTILES + tile] = sm1;
        }
    }
}

// ================= unified AV tensor-core GEMM (m1 / m2) =================
#define PADA 72
#define PADB 40
__global__ __launch_bounds__(256) void av_kernel(int which) {
    __shared__ __half As[128*PADA];
    __shared__ __half Bs[64*PADB];
    __shared__ float mxs[128], ris[128];
    int t = threadIdx.x, wid = t >> 5, lane = t & 31;
    int r = lane & 7, quad = lane >> 3;
    int n = blockIdx.y >> 3, h = blockIdx.y & 7;
    int m0 = blockIdx.x * 128;
    size_t lbase = ((size_t)(n*NHEAD + h))*LL + m0;
    const __half* Asrc = (which == 0 ? g_qkh : g_s2t);
    const __half* Bsrc = g_vh[which ^ 1] + ((size_t)(n*LL))*CH + h*DH;
    uint32_t asm_b = smem_u32(As), bsm_b = smem_u32(Bs);

    if (which == 0 && t < 128) {
        mxs[t] = g_rmax[lbase + t];
        ris[t] = g_rinv[lbase + t];
    }
    __syncthreads();

    uint32_t a_off = (uint32_t)(((wid*16 + (quad&1)*8 + r)*PADA + (quad>>1)*8) * 2);
    float acc[4][4];
    #pragma unroll
    for (int nt = 0; nt < 4; nt++)
        #pragma unroll
        for (int i = 0; i < 4; i++) acc[nt][i] = 0.f;

    for (int k0 = 0; k0 < LL; k0 += 64) {
        {
            int row = t >> 1, half0 = (t & 1)*32;
            const __half* src = Asrc + (lbase + row)*LL + k0 + half0;
            __half* dst = As + row*PADA + half0;
            if (which == 0) {
                float mx = mxs[row], ri = ris[row];
                #pragma unroll
                for (int j = 0; j < 4; j++) {
                    uint4 raw = *(const uint4*)(src + j*8);
                    __half2* hp = (__half2*)&raw;
                    __half2 o[4];
                    #pragma unroll
                    for (int q = 0; q < 4; q++) {
                        float2 f = __half22float2(hp[q]);
                        o[q] = __floats2half2_rn(__expf(f.x - mx)*ri, __expf(f.y - mx)*ri);
                    }
                    *(uint4*)(dst + j*8) = *(uint4*)o;
                }
            } else {
                #pragma unroll
                for (int j = 0; j < 4; j++)
                    *(uint4*)(dst + j*8) = *(const uint4*)(src + j*8);
            }
        }
        {
            int row = t >> 2, seg = (t & 3)*8;
            *(uint4*)(Bs + row*PADB + seg) = *(const uint4*)(Bsrc + (size_t)(k0 + row)*CH + seg);
        }
        __syncthreads();

        #pragma unroll
        for (int ks = 0; ks < 4; ks++) {
            uint32_t af[4];
            LDSM_X4(af[0], af[1], af[2], af[3], asm_b + a_off + (uint32_t)(ks*32));
            #pragma unroll
            for (int p = 0; p < 2; p++) {
                uint32_t b0, b1, b2, b3;
                uint32_t boff = (uint32_t)(((ks*16 + (quad&1)*8 + r)*PADB + p*16 + (quad>>1)*8) * 2);
                LDSM_X4_T(b0, b1, b2, b3, bsm_b + boff);
                mma_f16(acc[2*p],   af, b0, b1);
                mma_f16(acc[2*p+1], af, b2, b3);
            }
        }
        __syncthreads();
    }

    int rrow = lane >> 2, ccol = (lane & 3)*2;
    #pragma unroll
    for (int nt = 0; nt < 4; nt++) {
        size_t orow = (size_t)(n*LL + m0 + wid*16 + rrow);
        __half* dst = g_m[which] + orow*CH + h*DH + nt*8 + ccol;
        *(__half2*)dst            = __floats2half2_rn(acc[nt][0], acc[nt][1]);
        *(__half2*)(dst + 8*CH)   = __floats2half2_rn(acc[nt][2], acc[nt][3]);
    }
}

// ---------------- merged weight fp16 prepass ----------------
__global__ void roundh3_kernel(const float* __restrict__ mw, const float* __restrict__ w1,
                               const float* __restrict__ w2,
                               __half* __restrict__ mwh, __half* __restrict__ w1h,
                               __half* __restrict__ w2h) {
    int i = blockIdx.x*256 + threadIdx.x;
    if (i < CH*CH) mwh[i] = __float2half_rn(mw[i]);
    if (i < C2*C2) w1h[i] = __float2half_rn(w1[i]);
    if (i < CH*C2) w2h[i] = __float2half_rn(w2[i]);
}

// ---------------- 1. fused maxpool + xcopy + LN partials ----------------
#define PUX_PITCH 516
#define PUX_SMEM ((32*PUX_PITCH + 32*33)*4)
__global__ __launch_bounds__(256) void pux_kernel(const float* __restrict__ x1,
                                                  const float* __restrict__ x2) {
    extern __shared__ float sh[];
    float* po = sh + 32*PUX_PITCH;
    int ct = blockIdx.x;
    int y4 = blockIdx.y;
    int n  = blockIdx.z & 3;
    int o  = blockIdx.z >> 2;
    const float* xs = o ? x2 : x1;
    int tid = threadIdx.x;
    int c0 = ct*32;
    #pragma unroll
    for (int i = 0; i < 16; i++) {
        int f = tid + i*256;
        int cc = f >> 7, rem = f & 127;
        int yy = rem >> 5, c4 = rem & 31;
        float4 v = *(const float4*)(xs +
            (((size_t)(n*CH + c0+cc))*HH + y4*4+yy)*WW + c4*4);
        *(float4*)&sh[cc*PUX_PITCH + yy*128 + c4*4] = v;
    }
    __syncthreads();
    {
        int c = tid >> 3, xo = (tid & 7)*4;
        float4 out;
        float* pov = &out.x;
        #pragma unroll
        for (int k = 0; k < 4; k++) {
            int px = xo + k;
            float m = NEGINF;
            #pragma unroll
            for (int yy = 0; yy < 4; yy++) {
                float4 v = *(const float4*)&sh[c*PUX_PITCH + yy*128 + px*4];
                m = fmaxf(m, fmaxf(fmaxf(v.x, v.y), fmaxf(v.z, v.w)));
            }
            pov[k] = m;
            po[c*33 + px] = m;
        }
        *(float4*)(g_p[o] + ((size_t)(n*CH + c0 + c))*LL + y4*32 + xo) = out;
    }
    __syncthreads();
    if (tid < 32) {
        float s = 0.f, sq = 0.f;
        #pragma unroll
        for (int c = 0; c < 32; c++) { float v = po[c*33 + tid]; s += v; sq += v*v; }
        int sp = y4*32 + tid;
        size_t pidx = (((size_t)(o*BATCH + n))*8 + ct)*LL + sp;
        g_lnps[pidx] = s;
        g_lnpq[pidx] = sq;
    }
    size_t rbase = (size_t)o*NPIX + (size_t)n*HH*WW + (size_t)(y4*4)*WW;
    #pragma unroll
    for (int j = 0; j < 2; j++) {
        int p = tid + j*256;
        __half2 hb[16];
        #pragma unroll
        for (int cc = 0; cc < 32; cc += 2)
            hb[cc>>1] = __floats2half2_rn(sh[cc*PUX_PITCH + p], sh[(cc+1)*PUX_PITCH + p]);
        uint4* dst = (uint4*)(g_u + (rbase + p)*C2 + c0);
        const uint4* src = (const uint4*)hb;
        dst[0] = src[0]; dst[1] = src[1]; dst[2] = src[2]; dst[3] = src[3];
    }
}

// ---------------- 2. finalize LN stats ----------------
__global__ void lnfin_kernel() {
    int gi = blockIdx.x*256 + threadIdx.x;
    int on = gi / LL, sp = gi % LL;
    float s = 0.f, sq = 0.f;
    #pragma unroll
    for (int ctt = 0; ctt < 8; ctt++) {
        size_t pidx = (((size_t)on)*8 + ctt)*LL + sp;
        s += g_lnps[pidx]; sq += g_lnpq[pidx];
    }
    float mu = s * (1.0f/CH);
    g_mu1[gi] = mu;
    g_rs1[gi] = rsqrtf(sq * (1.0f/CH) - mu*mu + EPSF);
}

// ---------------- 3. dwconv3x3 + BN (LN inline), q/k/v fp16 out ----------------
__global__ __launch_bounds__(256) void dwbn2_kernel(
        const float* __restrict__ qw, const float* __restrict__ qg, const float* __restrict__ qb,
        const float* __restrict__ qm, const float* __restrict__ qvv,
        const float* __restrict__ vw, const float* __restrict__ vg, const float* __restrict__ vb,
        const float* __restrict__ vm, const float* __restrict__ vvv,
        const float* __restrict__ l1g, const float* __restrict__ l1b) {
    int c0 = blockIdx.x * 8;
    int n  = blockIdx.y;
    int o  = blockIdx.z;
    __shared__ float sp[8*1028];
    int t = threadIdx.x;
    const float* mub = g_mu1 + (size_t)(o*BATCH + n)*LL;
    const float* rsb = g_rs1 + (size_t)(o*BATCH + n)*LL;
    #pragma unroll
    for (int cc = 0; cc < 8; cc++) {
        float gc = l1g[c0+cc], bc = l1b[c0+cc];
        #pragma unroll
        for (int it = 0; it < 4; it++) {
            int spi = t + it*256;
            float raw = g_p[o][((size_t)(n*CH + c0+cc))*LL + spi];
            sp[cc*1028 + spi] = gc*(raw - mub[spi])*rsb[spi] + bc;
        }
    }
    __syncthreads();

    int cc = t & 7, jq = t >> 3;
    int c = c0 + cc;
    float wq[9], wv[9];
    #pragma unroll
    for (int k = 0; k < 9; k++) { wq[k] = qw[c*9+k]; wv[k] = vw[c*9+k]; }
    float scq = qg[c]*rsqrtf(qvv[c]+EPSF), bq = qb[c] - scq*qm[c];
    float scv = vg[c]*rsqrtf(vvv[c]+EPSF), bv = vb[c] - scv*vm[c];
    const float* s = sp + cc*1028;
    __half* oq = g_qh[o] + (size_t)(n*LL)*CH + c;
    __half* ov = g_vh[o] + (size_t)(n*LL)*CH + c;

    for (int i = 0; i < 32; i++) {
        float aq = 0.f, av = 0.f;
        #pragma unroll
        for (int di = 0; di < 3; di++) {
            int ii = i + di - 1;
            if (ii < 0 || ii >= HP) continue;
            #pragma unroll
            for (int dj = 0; dj < 3; dj++) {
                int jj = jq + dj - 1;
                if (jj < 0 || jj >= WP) continue;
                float x = s[ii*32 + jj];
                aq += wq[di*3+dj]*x;
                av += wv[di*3+dj]*x;
            }
        }
        int l = i*32 + jq;
        oq[(size_t)l*CH] = __float2half_rn(scq*aq + bq);
        ov[(size_t)l*CH] = __float2half_rn(scv*av + bv);
    }
}

// ---------------- 5. combine tile partials ----------------
__global__ void rowstat2_kernel() {
    int r = blockIdx.x*256 + threadIdx.x;
    float pm[NTILES];
    float m = NEGINF;
    #pragma unroll
    for (int i = 0; i < NTILES; i++) {
        pm[i] = g_pmax[(size_t)r*NTILES + i];
        m = fmaxf(m, pm[i]);
    }
    float sum = 0.f;
    #pragma unroll
    for (int i = 0; i < NTILES; i++)
        sum += g_psum[(size_t)r*NTILES + i] * __expf(pm[i] - m);
    g_rmax[r] = m;
    g_rinv[r] = 1.f/sum;
}

// ---------------- 7. S2 softmax over heads + transpose ----------------
__global__ __launch_bounds__(256) void s2t_kernel() {
    __shared__ __half sm[8][32][36];
    int t = threadIdx.x;
    int s0 = blockIdx.x*32, l0 = blockIdx.y*32, n = blockIdx.z;
    int row = t >> 3, seg = t & 7;
    #pragma unroll
    for (int h = 0; h < NHEAD; h++) {
        uint2 v = *(const uint2*)(g_qkh +
            (((size_t)(n*NHEAD + h))*LL + l0 + row)*LL + s0 + seg*4);
        *(uint2*)&sm[h][row][seg*4] = v;
    }
    __syncthreads();
    #pragma unroll
    for (int j = 0; j < 4; j++) {
        int e = t*4 + j;
        int l = e >> 5, s = e & 31;
        float v[NHEAD];
        float mx = NEGINF;
        #pragma unroll
        for (int h = 0; h < NHEAD; h++) {
            v[h] = __half2float(sm[h][l][s]);
            mx = fmaxf(mx, v[h]);
        }
        float smm = 0.f;
        #pragma unroll
        for (int h = 0; h < NHEAD; h++) { v[h] = __expf(v[h]-mx); smm += v[h]; }
        float ri = 1.f/smm;
        #pragma unroll
        for (int h = 0; h < NHEAD; h++)
            sm[h][l][s] = __float2half_rn(v[h]*ri);
    }
    __syncthreads();
    #pragma unroll
    for (int h = 0; h < NHEAD; h++) {
        __half tmp[4];
        #pragma unroll
        for (int jj = 0; jj < 4; jj++) tmp[jj] = sm[h][seg*4+jj][row];
        *(uint2*)(g_s2t + (((size_t)(n*NHEAD + h))*LL + s0 + row)*LL + l0 + seg*4) =
            *(uint2*)tmp;
    }
}

// ---------------- 9. bilinear x4 upsample into U[:, 256:512] ----------------
__global__ void upsample_kernel() {
    int tid = threadIdx.x;
    int pix = blockIdx.x*4 + (tid >> 6);
    int cg = (tid & 63) * 4;
    int x = pix % WW;
    int y = (pix / WW) % HH;
    int n = (pix / (WW*HH)) % BATCH;
    int o =  pix / (WW*HH*BATCH);
    float sy = (y + 0.5f)*0.25f - 0.5f;
    float sx = (x + 0.5f)*0.25f - 0.5f;
    int y0 = (int)floorf(sy), x0 = (int)floorf(sx);
    float fy = sy - (float)y0, fx = sx - (float)x0;
    int y0c = min(max(y0, 0), HP-1), y1c = min(max(y0+1, 0), HP-1);
    int x0c = min(max(x0, 0), WP-1), x1c = min(max(x0+1, 0), WP-1);
    const float* mm = g_mm[o] + (size_t)n*LL*CH;
    float4 v00 = *(const float4*)(mm + (size_t)(y0c*WP + x0c)*CH + cg);
    float4 v01 = *(const float4*)(mm + (size_t)(y0c*WP + x1c)*CH + cg);
    float4 v10 = *(const float4*)(mm + (size_t)(y1c*WP + x0c)*CH + cg);
    float4 v11 = *(const float4*)(mm + (size_t)(y1c*WP + x1c)*CH + cg);
    float w00 = (1.f-fy)*(1.f-fx), w01 = (1.f-fy)*fx, w10 = fy*(1.f-fx), w11 = fy*fx;
    __half2 h0 = __floats2half2_rn(w00*v00.x + w01*v01.x + w10*v10.x + w11*v11.x,
                                   w00*v00.y + w01*v01.y + w10*v10.y + w11*v11.y);
    __half2 h1 = __floats2half2_rn(w00*v00.z + w01*v01.z + w10*v10.z + w11*v11.z,
                                   w00*v00.w + w01*v01.w + w10*v10.w + w11*v11.w);
    __half2* dst = (__half2*)(g_u + (size_t)pix*C2 + CH + cg);
    dst[0] = h0; dst[1] = h1;
}

// ---------------- 10. fused LN stats + apply + residual + write-out ----------------
__global__ __launch_bounds__(256) void out_fused_kernel(
        const float* __restrict__ x1, const float* __restrict__ x2,
        const float* __restrict__ lg, const float* __restrict__ lb,
        float* __restrict__ out) {
    int xt = blockIdx.x;
    int y  = blockIdx.y;
    int n  = blockIdx.z % BATCH;
    int o  = blockIdx.z / BATCH;
    __shared__ float zsh[32][257];
    __shared__ float smu[32], srs[32];
    int tid = threadIdx.x;
    size_t rbase = (size_t)o*NPIX + (size_t)n*HH*WW + (size_t)y*WW + xt*32;
    #pragma unroll
    for (int j = 0; j < 4; j++) {
        int px = j*8 + (tid >> 5);
        int c = (tid & 31) * 8;
        uint4 raw = *(const uint4*)(g_z2h + (rbase + px)*CH + c);
        const __half2* hp = (const __half2*)&raw;
        #pragma unroll
        for (int q = 0; q < 4; q++) {
            float2 f = __half22float2(hp[q]);
            zsh[px][c + 2*q]     = f.x;
            zsh[px][c + 2*q + 1] = f.y;
        }
    }
    __syncthreads();
    int w = tid >> 5, lane = tid & 31;
    #pragma unroll
    for (int i = 0; i < 4; i++) {
        int px = w*4 + i;
        float s = 0.f, sq = 0.f;
        #pragma unroll
        for (int k = 0; k < 8; k++) { float v = zsh[px][lane + k*32]; s += v; sq += v*v; }
        #pragma unroll
        for (int off = 16; off; off >>= 1) {
            s  += __shfl_xor_sync(0xffffffffu, s,  off);
            sq += __shfl_xor_sync(0xffffffffu, sq, off);
        }
        if (!lane) {
            float mu = s * (1.0f/CH);
            smu[px] = mu;
            srs[px] = rsqrtf(sq * (1.0f/CH) - mu*mu + EPSF);
        }
    }
    __syncthreads();
    const float* xs = o ? x2 : x1;
    int cth = tid >> 5, tx = tid & 31;
    float mu = smu[tx], rs = srs[tx];
    size_t xbase = ((size_t)(n*CH))*HH*WW + (size_t)y*WW + xt*32 + tx;
    float* outb = out + (size_t)o*NPIX*CH;
    #pragma unroll 8
    for (int cc = 0; cc < 32; cc++) {
        int c = cc*8 + cth;
        float val = lg[c]*(zsh[tx][c] - mu)*rs + lb[c];
        size_t gi = xbase + (size_t)c*HH*WW;
        outb[gi] = xs[gi] + val;
    }
}

// ---------------- launch ----------------
extern "C" void kernel_launch(void* const* d_in, const int* in_sizes, int n_in,
                              void* d_out, int out_size) {
    const float* x1     = (const float*)d_in[0];
    const float* x2     = (const float*)d_in[1];
    const float* qk_w   = (const float*)d_in[2];
    const float* qk_g   = (const float*)d_in[3];
    const float* qk_b   = (const float*)d_in[4];
    const float* qk_m   = (const float*)d_in[5];
    const float* qk_v   = (const float*)d_in[6];
    const float* v_w    = (const float*)d_in[7];
    const float* v_g    = (const float*)d_in[8];
    const float* v_b    = (const float*)d_in[9];
    const float* v_m    = (const float*)d_in[10];
    const float* v_v    = (const float*)d_in[11];
    const float* ln1_g  = (const float*)d_in[12];
    const float* ln1_b  = (const float*)d_in[13];
    const float* ln2_g  = (const float*)d_in[14];
    const float* ln2_b  = (const float*)d_in[15];
    const float* merge_w= (const float*)d_in[16];
    const float* mlp_w1 = (const float*)d_in[17];
    const float* mlp_w2 = (const float*)d_in[18];
    float* out = (float*)d_out;

    __half *pm, *pu, *pz1, *pz2h, *pmw, *pw1, *pw2;
    float *pmm;
    cudaGetSymbolAddress((void**)&pm,  g_m);
    cudaGetSymbolAddress((void**)&pmm, g_mm);
    cudaGetSymbolAddress((void**)&pu,  g_u);
    cudaGetSymbolAddress((void**)&pz1, g_z1);
    cudaGetSymbolAddress((void**)&pz2h, g_z2h);
    cudaGetSymbolAddress((void**)&pmw, g_mwh);
    cudaGetSymbolAddress((void**)&pw1, g_w1h);
    cudaGetSymbolAddress((void**)&pw2, g_w2h);

    cudaFuncSetAttribute(hgemm_kernel, cudaFuncAttributeMaxDynamicSharedMemorySize, GEMM_SMEM);
    cudaFuncSetAttribute(pux_kernel,   cudaFuncAttributeMaxDynamicSharedMemorySize, PUX_SMEM);

    roundh3_kernel<<<(C2*C2+255)/256, 256>>>(merge_w, mlp_w1, mlp_w2, pmw, pw1, pw2);

    pux_kernel<<<dim3(CH/32, HP, 2*BATCH), 256, PUX_SMEM>>>(x1, x2);
    lnfin_kernel<<<(2*BATCH*LL)/256, 256>>>();

    dwbn2_kernel<<<dim3(CH/8, BATCH, 2), 256>>>(qk_w, qk_g, qk_b, qk_m, qk_v,
                                                v_w, v_g, v_b, v_m, v_v, ln1_g, ln1_b);

    // attention (all tensor-core)
    qkmma_kernel<<<dim3(LL/128, LL/128, BATCH*NHEAD), 256>>>();
    rowstat2_kernel<<<BATCH*NHEAD*LL/256, 256>>>();
    av_kernel<<<dim3(LL/128, BATCH*NHEAD), 256>>>(0);   // m1
    s2t_kernel<<<dim3(LL/32, LL/32, BATCH), 256>>>();
    av_kernel<<<dim3(LL/128, BATCH*NHEAD), 256>>>(1);   // m2

    // merge linear (CTA 256x128)
    hgemm_kernel<<<dim3(CH/128, (2*BATCH*LL)/256), 256, GEMM_SMEM>>>(
        pm, pmw, pmm, 2*BATCH*LL, CH, CH, 0, 0);

    upsample_kernel<<<NROWS/4, 256>>>();

    // MLP
    hgemm_kernel<<<dim3(C2/128, NROWS/256), 256, GEMM_SMEM>>>(
        pu, pw1, pz1, NROWS, C2, C2, 1, 1);
    hgemm_kernel<<<dim3(CH/128, NROWS/256), 256, GEMM_SMEM>>>(
        pz1, pw2, pz2h, NROWS, CH, C2, 0, 1);

    out_fused_kernel<<<dim3(WW/32, HH, 2*BATCH), 256>>>(x1, x2, ln2_g, ln2_b, out);
}

// round 13
// speedup vs baseline: 1.0629x; 1.0629x over previous
#include <cuda_runtime.h>
#include <cuda_fp16.h>
#include <cstdint>

#define BATCH 4
#define CH 256
#define HH 128
#define WW 128
#define HP 32
#define WP 32
#define LL 1024
#define NHEAD 8
#define DH 32
#define C2 512
#define NPIX (BATCH*HH*WW)
#define NROWS (2*NPIX)
#define EPSF 1e-5f
#define TSCALE 0.17677669529663687f
#define NEGINF (-3.402823466e38f)
#define NTILES 16

// ---------------- scratch ----------------
__device__ float  g_p[2][BATCH*CH*LL];
__device__ float  g_lnps[2*BATCH*8*LL];
__device__ float  g_lnpq[2*BATCH*8*LL];
__device__ float  g_mu1[2*BATCH*LL];
__device__ float  g_rs1[2*BATCH*LL];
__device__ __half g_qh[2][(size_t)BATCH*LL*CH];        // q/k heads fp16
__device__ __half g_vh[2][(size_t)BATCH*LL*CH];        // v heads fp16
__device__ __half g_qkh[(size_t)BATCH*NHEAD*LL*LL];    // fp16 logits
__device__ __half g_s2t[(size_t)BATCH*NHEAD*LL*LL];    // S2 transposed [h][s][l]
__device__ float  g_pmax[(size_t)BATCH*NHEAD*LL*NTILES];
__device__ float  g_psum[(size_t)BATCH*NHEAD*LL*NTILES];
__device__ float  g_rmax[BATCH*NHEAD*LL];
__device__ float  g_rinv[BATCH*NHEAD*LL];
__device__ __half g_m[2][(size_t)BATCH*LL*CH];
__device__ float  g_mm[2][(size_t)BATCH*LL*CH];
__device__ __half g_u[(size_t)NROWS*C2];
__device__ __half g_z1[(size_t)NROWS*C2];
__device__ __half g_z2h[(size_t)NROWS*CH];             // fp16
__device__ __half g_mwh[CH*CH];
__device__ __half g_w1h[C2*C2];
__device__ __half g_w2h[CH*C2];

// ================= helpers =================
__device__ __forceinline__ uint32_t smem_u32(const void* p) {
    uint32_t a;
    asm("{ .reg .u64 t; cvta.to.shared.u64 t, %1; cvt.u32.u64 %0, t; }" : "=r"(a) : "l"(p));
    return a;
}
#define CP_ASYNC16(dst, src) \
    asm volatile("cp.async.cg.shared.global [%0], [%1], 16;" :: "r"(dst), "l"(src) : "memory")
#define CP_COMMIT() asm volatile("cp.async.commit_group;" ::: "memory")
#define CP_WAIT(n)  asm volatile("cp.async.wait_group %0;" :: "n"(n) : "memory")
#define LDSM_X4(r0, r1, r2, r3, addr) \
    asm volatile("ldmatrix.sync.aligned.m8n8.x4.shared.b16 {%0,%1,%2,%3}, [%4];" \
        : "=r"(r0), "=r"(r1), "=r"(r2), "=r"(r3) : "r"(addr))
#define LDSM_X4_T(r0, r1, r2, r3, addr) \
    asm volatile("ldmatrix.sync.aligned.m8n8.x4.trans.shared.b16 {%0,%1,%2,%3}, [%4];" \
        : "=r"(r0), "=r"(r1), "=r"(r2), "=r"(r3) : "r"(addr))

__device__ __forceinline__ void mma_f16(float* d, const uint32_t* a, uint32_t b0, uint32_t b1) {
    asm volatile(
        "mma.sync.aligned.m16n8k16.row.col.f32.f16.f16.f32 "
        "{%0,%1,%2,%3}, {%4,%5,%6,%7}, {%8,%9}, {%0,%1,%2,%3};"
        : "+f"(d[0]), "+f"(d[1]), "+f"(d[2]), "+f"(d[3])
        : "r"(a[0]), "r"(a[1]), "r"(a[2]), "r"(a[3]), "r"(b0), "r"(b1));
}

// ================= fp16 mma GEMM (validated R11 config: CTA 128x128, 3-stage) =================
#define BKH 64
#define PADH 72
#define TILEH (128*PADH)
#define TILE_BYTES (TILEH*2)
#define STAGE_BYTES (2*TILE_BYTES)
#define GEMM_SMEM (3*STAGE_BYTES)

__global__ __launch_bounds__(256) void hgemm_kernel(
        const __half* __restrict__ A, const __half* __restrict__ Bw, void* __restrict__ C,
        int M, int N, int K, int relu, int outHalf) {
    extern __shared__ __half smh[];
    int tid = threadIdx.x, wid = tid >> 5, lane = tid & 31;
    int g = lane >> 2, t = lane & 3;
    int r = lane & 7, quad = lane >> 3;
    int wm = wid >> 1, wn = wid & 1;
    size_t am0 = (size_t)blockIdx.y * 128;
    size_t bn0 = (size_t)blockIdx.x * 128;
    uint32_t smembase = smem_u32(smh);

    uint32_t a_off[2], b_off[4];
    #pragma unroll
    for (int mt = 0; mt < 2; mt++)
        a_off[mt] = (uint32_t)(((wm*32 + mt*16 + (quad&1)*8 + r)*PADH + (quad>>1)*8) * 2);
    #pragma unroll
    for (int p = 0; p < 4; p++)
        b_off[p] = (uint32_t)(((wn*64 + p*16 + (quad>>1)*8 + r)*PADH + (quad&1)*8) * 2);

    int nchunk = K >> 6;
    float acc[2][8][4];
    #pragma unroll
    for (int mt = 0; mt < 2; mt++)
        #pragma unroll
        for (int nt = 0; nt < 8; nt++)
            #pragma unroll
            for (int i = 0; i < 4; i++) acc[mt][nt][i] = 0.f;

    auto issue = [&](int ch, int st) {
        const __half* Ag = A + am0 * K + ch*BKH;
        const __half* Bg = Bw + bn0 * K + ch*BKH;
        uint32_t base = smembase + st*STAGE_BYTES;
        #pragma unroll
        for (int j = 0; j < 4; j++) {
            int idx = tid + j * 256;
            int row = idx >> 3, seg = idx & 7;
            uint32_t d = (uint32_t)((row*PADH + seg*8) * 2);
            CP_ASYNC16(base + d,              Ag + (size_t)row*K + seg*8);
            CP_ASYNC16(base + TILE_BYTES + d, Bg + (size_t)row*K + seg*8);
        }
        CP_COMMIT();
    };

    issue(0, 0);
    if (nchunk > 1) issue(1, 1);

    for (int i = 0; i < nchunk; i++) {
        int s = i % 3;
        if (i + 2 < nchunk) { issue(i + 2, (i + 2) % 3); CP_WAIT(2); }
        else if (i + 1 < nchunk) { CP_WAIT(1); }
        else { CP_WAIT(0); }
        __syncthreads();

        uint32_t abase = smembase + s*STAGE_BYTES;
        uint32_t bbase = abase + TILE_BYTES;
        #pragma unroll
        for (int ks = 0; ks < 4; ks++) {
            uint32_t koff = (uint32_t)(ks * 32);
            uint32_t af[2][4];
            LDSM_X4(af[0][0], af[0][1], af[0][2], af[0][3], abase + a_off[0] + koff);
            LDSM_X4(af[1][0], af[1][1], af[1][2], af[1][3], abase + a_off[1] + koff);
            #pragma unroll
            for (int p = 0; p < 4; p++) {
                uint32_t b0, b1, b2, b3;
                LDSM_X4(b0, b1, b2, b3, bbase + b_off[p] + koff);
                mma_f16(acc[0][2*p],   af[0], b0, b1);
                mma_f16(acc[1][2*p],   af[1], b0, b1);
                mma_f16(acc[0][2*p+1], af[0], b2, b3);
                mma_f16(acc[1][2*p+1], af[1], b2, b3);
            }
        }
        __syncthreads();
    }

    #pragma unroll
    for (int mt = 0; mt < 2; mt++) {
        size_t row = am0 + wm*32 + mt*16 + g;
        #pragma unroll
        for (int nt = 0; nt < 8; nt++) {
            size_t col = bn0 + wn*64 + nt*8 + 2*t;
            float v0 = acc[mt][nt][0], v1 = acc[mt][nt][1];
            float v2 = acc[mt][nt][2], v3 = acc[mt][nt][3];
            if (relu) {
                v0 = fmaxf(v0,0.f); v1 = fmaxf(v1,0.f);
                v2 = fmaxf(v2,0.f); v3 = fmaxf(v3,0.f);
            }
            if (outHalf) {
                __half* Ch = (__half*)C;
                *(__half2*)(Ch + row*N + col)     = __floats2half2_rn(v0, v1);
                *(__half2*)(Ch + (row+8)*N + col) = __floats2half2_rn(v2, v3);
            } else {
                float* Cf = (float*)C;
                *(float2*)(Cf + row*N + col)     = make_float2(v0, v1);
                *(float2*)(Cf + (row+8)*N + col) = make_float2(v2, v3);
            }
        }
    }
}

// ================= QK tensor-core GEMM: logits + softmax partials =================
#define PADQ 40
__global__ __launch_bounds__(256) void qkmma_kernel() {
    __shared__ __half qs[2][128*PADQ];
    int tid = threadIdx.x, wid = tid >> 5, lane = tid & 31;
    int g = lane >> 2, t = lane & 3;
    int r = lane & 7, quad = lane >> 3;
    int wm = wid >> 1, wn = wid & 1;
    int n = blockIdx.z >> 3, h = blockIdx.z & 7;
    int l0 = blockIdx.y * 128, s0 = blockIdx.x * 128;
    uint32_t abase = smem_u32(qs[0]);
    uint32_t bbase = smem_u32(qs[1]);

    #pragma unroll
    for (int j = 0; j < 2; j++) {
        int idx = tid + j*256;
        int row = idx >> 2, seg = idx & 3;
        uint32_t d = (uint32_t)((row*PADQ + seg*8) * 2);
        const __half* Aq = g_qh[0] + ((size_t)(n*LL + l0 + row))*CH + h*DH + seg*8;
        const __half* Bq = g_qh[1] + ((size_t)(n*LL + s0 + row))*CH + h*DH + seg*8;
        CP_ASYNC16(abase + d, Aq);
        CP_ASYNC16(bbase + d, Bq);
    }
    CP_COMMIT();
    CP_WAIT(0);
    __syncthreads();

    uint32_t a_off[2], b_off[4];
    #pragma unroll
    for (int mt = 0; mt < 2; mt++)
        a_off[mt] = (uint32_t)(((wm*32 + mt*16 + (quad&1)*8 + r)*PADQ + (quad>>1)*8) * 2);
    #pragma unroll
    for (int p = 0; p < 4; p++)
        b_off[p] = (uint32_t)(((wn*64 + p*16 + (quad>>1)*8 + r)*PADQ + (quad&1)*8) * 2);

    float acc[2][8][4];
    #pragma unroll
    for (int mt = 0; mt < 2; mt++)
        #pragma unroll
        for (int nt = 0; nt < 8; nt++)
            #pragma unroll
            for (int i = 0; i < 4; i++) acc[mt][nt][i] = 0.f;

    #pragma unroll
    for (int ks = 0; ks < 2; ks++) {
        uint32_t koff = (uint32_t)(ks * 32);
        uint32_t af[2][4];
        LDSM_X4(af[0][0], af[0][1], af[0][2], af[0][3], abase + a_off[0] + koff);
        LDSM_X4(af[1][0], af[1][1], af[1][2], af[1][3], abase + a_off[1] + koff);
        #pragma unroll
        for (int p = 0; p < 4; p++) {
            uint32_t b0, b1, b2, b3;
            LDSM_X4(b0, b1, b2, b3, bbase + b_off[p] + koff);
            mma_f16(acc[0][2*p],   af[0], b0, b1);
            mma_f16(acc[1][2*p],   af[1], b0, b1);
            mma_f16(acc[0][2*p+1], af[0], b2, b3);
            mma_f16(acc[1][2*p+1], af[1], b2, b3);
        }
    }

    size_t qkbase = ((size_t)(n*NHEAD + h))*LL;
    int tile = blockIdx.x*2 + wn;
    #pragma unroll
    for (int mt = 0; mt < 2; mt++) {
        int row0 = l0 + wm*32 + mt*16 + g;
        float mx0 = NEGINF, mx1 = NEGINF;
        float vals[8][4];
        #pragma unroll
        for (int nt = 0; nt < 8; nt++) {
            #pragma unroll
            for (int i = 0; i < 4; i++) vals[nt][i] = TSCALE*acc[mt][nt][i];
            int col = s0 + wn*64 + nt*8 + 2*t;
            *(__half2*)(g_qkh + (qkbase + row0)*LL + col)   = __floats2half2_rn(vals[nt][0], vals[nt][1]);
            *(__half2*)(g_qkh + (qkbase + row0+8)*LL + col) = __floats2half2_rn(vals[nt][2], vals[nt][3]);
            mx0 = fmaxf(mx0, fmaxf(vals[nt][0], vals[nt][1]));
            mx1 = fmaxf(mx1, fmaxf(vals[nt][2], vals[nt][3]));
        }
        #pragma unroll
        for (int off = 1; off <= 2; off <<= 1) {
            mx0 = fmaxf(mx0, __shfl_xor_sync(0xffffffffu, mx0, off));
            mx1 = fmaxf(mx1, __shfl_xor_sync(0xffffffffu, mx1, off));
        }
        float sm0 = 0.f, sm1 = 0.f;
        #pragma unroll
        for (int nt = 0; nt < 8; nt++) {
            sm0 += __expf(vals[nt][0]-mx0) + __expf(vals[nt][1]-mx0);
            sm1 += __expf(vals[nt][2]-mx1) + __expf(vals[nt][3]-mx1);
        }
        #pragma unroll
        for (int off = 1; off <= 2; off <<= 1) {
            sm0 += __shfl_xor_sync(0xffffffffu, sm0, off);
            sm1 += __shfl_xor_sync(0xffffffffu, sm1, off);
        }
        if (t == 0) {
            g_pmax[(qkbase + row0)*NTILES + tile]   = mx0;
            g_psum[(qkbase + row0)*NTILES + tile]   = sm0;
            g_pmax[(qkbase + row0+8)*NTILES + tile] = mx1;
            g_psum[(qkbase + row0+8)*NTILES + tile] = sm1;
        }
    }
}

// ================= unified AV tensor-core GEMM (m1 / m2) =================
#define PADA 72
#define PADB 40
__global__ __launch_bounds__(256) void av_kernel(int which) {
    __shared__ __half As[128*PADA];
    __shared__ __half Bs[64*PADB];
    __shared__ float mxs[128], ris[128];
    int t = threadIdx.x, wid = t >> 5, lane = t & 31;
    int r = lane & 7, quad = lane >> 3;
    int n = blockIdx.y >> 3, h = blockIdx.y & 7;
    int m0 = blockIdx.x * 128;
    size_t lbase = ((size_t)(n*NHEAD + h))*LL + m0;
    const __half* Asrc = (which == 0 ? g_qkh : g_s2t);
    const __half* Bsrc = g_vh[which ^ 1] + ((size_t)(n*LL))*CH + h*DH;
    uint32_t asm_b = smem_u32(As), bsm_b = smem_u32(Bs);

    if (which == 0 && t < 128) {
        mxs[t] = g_rmax[lbase + t];
        ris[t] = g_rinv[lbase + t];
    }
    __syncthreads();

    uint32_t a_off = (uint32_t)(((wid*16 + (quad&1)*8 + r)*PADA + (quad>>1)*8) * 2);
    float acc[4][4];
    #pragma unroll
    for (int nt = 0; nt < 4; nt++)
        #pragma unroll
        for (int i = 0; i < 4; i++) acc[nt][i] = 0.f;

    for (int k0 = 0; k0 < LL; k0 += 64) {
        {
            int row = t >> 1, half0 = (t & 1)*32;
            const __half* src = Asrc + (lbase + row)*LL + k0 + half0;
            __half* dst = As + row*PADA + half0;
            if (which == 0) {
                float mx = mxs[row], ri = ris[row];
                #pragma unroll
                for (int j = 0; j < 4; j++) {
                    uint4 raw = *(const uint4*)(src + j*8);
                    __half2* hp = (__half2*)&raw;
                    __half2 o[4];
                    #pragma unroll
                    for (int q = 0; q < 4; q++) {
                        float2 f = __half22float2(hp[q]);
                        o[q] = __floats2half2_rn(__expf(f.x - mx)*ri, __expf(f.y - mx)*ri);
                    }
                    *(uint4*)(dst + j*8) = *(uint4*)o;
                }
            } else {
                #pragma unroll
                for (int j = 0; j < 4; j++)
                    *(uint4*)(dst + j*8) = *(const uint4*)(src + j*8);
            }
        }
        {
            int row = t >> 2, seg = (t & 3)*8;
            *(uint4*)(Bs + row*PADB + seg) = *(const uint4*)(Bsrc + (size_t)(k0 + row)*CH + seg);
        }
        __syncthreads();

        #pragma unroll
        for (int ks = 0; ks < 4; ks++) {
            uint32_t af[4];
            LDSM_X4(af[0], af[1], af[2], af[3], asm_b + a_off + (uint32_t)(ks*32));
            #pragma unroll
            for (int p = 0; p < 2; p++) {
                uint32_t b0, b1, b2, b3;
                uint32_t boff = (uint32_t)(((ks*16 + (quad&1)*8 + r)*PADB + p*16 + (quad>>1)*8) * 2);
                LDSM_X4_T(b0, b1, b2, b3, bsm_b + boff);
                mma_f16(acc[2*p],   af, b0, b1);
                mma_f16(acc[2*p+1], af, b2, b3);
            }
        }
        __syncthreads();
    }

    int rrow = lane >> 2, ccol = (lane & 3)*2;
    #pragma unroll
    for (int nt = 0; nt < 4; nt++) {
        size_t orow = (size_t)(n*LL + m0 + wid*16 + rrow);
        __half* dst = g_m[which] + orow*CH + h*DH + nt*8 + ccol;
        *(__half2*)dst            = __floats2half2_rn(acc[nt][0], acc[nt][1]);
        *(__half2*)(dst + 8*CH)   = __floats2half2_rn(acc[nt][2], acc[nt][3]);
    }
}

// ---------------- merged weight fp16 prepass ----------------
__global__ void roundh3_kernel(const float* __restrict__ mw, const float* __restrict__ w1,
                               const float* __restrict__ w2,
                               __half* __restrict__ mwh, __half* __restrict__ w1h,
                               __half* __restrict__ w2h) {
    int i = blockIdx.x*256 + threadIdx.x;
    if (i < CH*CH) mwh[i] = __float2half_rn(mw[i]);
    if (i < C2*C2) w1h[i] = __float2half_rn(w1[i]);
    if (i < CH*C2) w2h[i] = __float2half_rn(w2[i]);
}

// ---------------- 1. fused maxpool + xcopy + LN partials ----------------
#define PUX_PITCH 516
#define PUX_SMEM ((32*PUX_PITCH + 32*33)*4)
__global__ __launch_bounds__(256) void pux_kernel(const float* __restrict__ x1,
                                                  const float* __restrict__ x2) {
    extern __shared__ float sh[];
    float* po = sh + 32*PUX_PITCH;
    int ct = blockIdx.x;
    int y4 = blockIdx.y;
    int n  = blockIdx.z & 3;
    int o  = blockIdx.z >> 2;
    const float* xs = o ? x2 : x1;
    int tid = threadIdx.x;
    int c0 = ct*32;
    #pragma unroll
    for (int i = 0; i < 16; i++) {
        int f = tid + i*256;
        int cc = f >> 7, rem = f & 127;
        int yy = rem >> 5, c4 = rem & 31;
        float4 v = *(const float4*)(xs +
            (((size_t)(n*CH + c0+cc))*HH + y4*4+yy)*WW + c4*4);
        *(float4*)&sh[cc*PUX_PITCH + yy*128 + c4*4] = v;
    }
    __syncthreads();
    {
        int c = tid >> 3, xo = (tid & 7)*4;
        float4 out;
        float* pov = &out.x;
        #pragma unroll
        for (int k = 0; k < 4; k++) {
            int px = xo + k;
            float m = NEGINF;
            #pragma unroll
            for (int yy = 0; yy < 4; yy++) {
                float4 v = *(const float4*)&sh[c*PUX_PITCH + yy*128 + px*4];
                m = fmaxf(m, fmaxf(fmaxf(v.x, v.y), fmaxf(v.z, v.w)));
            }
            pov[k] = m;
            po[c*33 + px] = m;
        }
        *(float4*)(g_p[o] + ((size_t)(n*CH + c0 + c))*LL + y4*32 + xo) = out;
    }
    __syncthreads();
    if (tid < 32) {
        float s = 0.f, sq = 0.f;
        #pragma unroll
        for (int c = 0; c < 32; c++) { float v = po[c*33 + tid]; s += v; sq += v*v; }
        int sp = y4*32 + tid;
        size_t pidx = (((size_t)(o*BATCH + n))*8 + ct)*LL + sp;
        g_lnps[pidx] = s;
        g_lnpq[pidx] = sq;
    }
    size_t rbase = (size_t)o*NPIX + (size_t)n*HH*WW + (size_t)(y4*4)*WW;
    #pragma unroll
    for (int j = 0; j < 2; j++) {
        int p = tid + j*256;
        __half2 hb[16];
        #pragma unroll
        for (int cc = 0; cc < 32; cc += 2)
            hb[cc>>1] = __floats2half2_rn(sh[cc*PUX_PITCH + p], sh[(cc+1)*PUX_PITCH + p]);
        uint4* dst = (uint4*)(g_u + (rbase + p)*C2 + c0);
        const uint4* src = (const uint4*)hb;
        dst[0] = src[0]; dst[1] = src[1]; dst[2] = src[2]; dst[3] = src[3];
    }
}

// ---------------- 2. finalize LN stats ----------------
__global__ void lnfin_kernel() {
    int gi = blockIdx.x*256 + threadIdx.x;
    int on = gi / LL, sp = gi % LL;
    float s = 0.f, sq = 0.f;
    #pragma unroll
    for (int ctt = 0; ctt < 8; ctt++) {
        size_t pidx = (((size_t)on)*8 + ctt)*LL + sp;
        s += g_lnps[pidx]; sq += g_lnpq[pidx];
    }
    float mu = s * (1.0f/CH);
    g_mu1[gi] = mu;
    g_rs1[gi] = rsqrtf(sq * (1.0f/CH) - mu*mu + EPSF);
}

// ---------------- 3. dwconv3x3 + BN (LN inline), q/k/v fp16 out ----------------
__global__ __launch_bounds__(256) void dwbn2_kernel(
        const float* __restrict__ qw, const float* __restrict__ qg, const float* __restrict__ qb,
        const float* __restrict__ qm, const float* __restrict__ qvv,
        const float* __restrict__ vw, const float* __restrict__ vg, const float* __restrict__ vb,
        const float* __restrict__ vm, const float* __restrict__ vvv,
        const float* __restrict__ l1g, const float* __restrict__ l1b) {
    int c0 = blockIdx.x * 8;
    int n  = blockIdx.y;
    int o  = blockIdx.z;
    __shared__ float sp[8*1028];
    int t = threadIdx.x;
    const float* mub = g_mu1 + (size_t)(o*BATCH + n)*LL;
    const float* rsb = g_rs1 + (size_t)(o*BATCH + n)*LL;
    #pragma unroll
    for (int cc = 0; cc < 8; cc++) {
        float gc = l1g[c0+cc], bc = l1b[c0+cc];
        #pragma unroll
        for (int it = 0; it < 4; it++) {
            int spi = t + it*256;
            float raw = g_p[o][((size_t)(n*CH + c0+cc))*LL + spi];
            sp[cc*1028 + spi] = gc*(raw - mub[spi])*rsb[spi] + bc;
        }
    }
    __syncthreads();

    int cc = t & 7, jq = t >> 3;
    int c = c0 + cc;
    float wq[9], wv[9];
    #pragma unroll
    for (int k = 0; k < 9; k++) { wq[k] = qw[c*9+k]; wv[k] = vw[c*9+k]; }
    float scq = qg[c]*rsqrtf(qvv[c]+EPSF), bq = qb[c] - scq*qm[c];
    float scv = vg[c]*rsqrtf(vvv[c]+EPSF), bv = vb[c] - scv*vm[c];
    const float* s = sp + cc*1028;
    __half* oq = g_qh[o] + (size_t)(n*LL)*CH + c;
    __half* ov = g_vh[o] + (size_t)(n*LL)*CH + c;

    for (int i = 0; i < 32; i++) {
        float aq = 0.f, av = 0.f;
        #pragma unroll
        for (int di = 0; di < 3; di++) {
            int ii = i + di - 1;
            if (ii < 0 || ii >= HP) continue;
            #pragma unroll
            for (int dj = 0; dj < 3; dj++) {
                int jj = jq + dj - 1;
                if (jj < 0 || jj >= WP) continue;
                float x = s[ii*32 + jj];
                aq += wq[di*3+dj]*x;
                av += wv[di*3+dj]*x;
            }
        }
        int l = i*32 + jq;
        oq[(size_t)l*CH] = __float2half_rn(scq*aq + bq);
        ov[(size_t)l*CH] = __float2half_rn(scv*av + bv);
    }
}

// ---------------- 5. combine tile partials ----------------
__global__ void rowstat2_kernel() {
    int r = blockIdx.x*256 + threadIdx.x;
    float pm[NTILES];
    float m = NEGINF;
    #pragma unroll
    for (int i = 0; i < NTILES; i++) {
        pm[i] = g_pmax[(size_t)r*NTILES + i];
        m = fmaxf(m, pm[i]);
    }
    float sum = 0.f;
    #pragma unroll
    for (int i = 0; i < NTILES; i++)
        sum += g_psum[(size_t)r*NTILES + i] * __expf(pm[i] - m);
    g_rmax[r] = m;
    g_rinv[r] = 1.f/sum;
}

// ---------------- 7. S2 softmax over heads + transpose ----------------
__global__ __launch_bounds__(256) void s2t_kernel() {
    __shared__ __half sm[8][32][36];
    int t = threadIdx.x;
    int s0 = blockIdx.x*32, l0 = blockIdx.y*32, n = blockIdx.z;
    int row = t >> 3, seg = t & 7;
    #pragma unroll
    for (int h = 0; h < NHEAD; h++) {
        uint2 v = *(const uint2*)(g_qkh +
            (((size_t)(n*NHEAD + h))*LL + l0 + row)*LL + s0 + seg*4);
        *(uint2*)&sm[h][row][seg*4] = v;
    }
    __syncthreads();
    #pragma unroll
    for (int j = 0; j < 4; j++) {
        int e = t*4 + j;
        int l = e >> 5, s = e & 31;
        float v[NHEAD];
        float mx = NEGINF;
        #pragma unroll
        for (int h = 0; h < NHEAD; h++) {
            v[h] = __half2float(sm[h][l][s]);
            mx = fmaxf(mx, v[h]);
        }
        float smm = 0.f;
        #pragma unroll
        for (int h = 0; h < NHEAD; h++) { v[h] = __expf(v[h]-mx); smm += v[h]; }
        float ri = 1.f/smm;
        #pragma unroll
        for (int h = 0; h < NHEAD; h++)
            sm[h][l][s] = __float2half_rn(v[h]*ri);
    }
    __syncthreads();
    #pragma unroll
    for (int h = 0; h < NHEAD; h++) {
        __half tmp[4];
        #pragma unroll
        for (int jj = 0; jj < 4; jj++) tmp[jj] = sm[h][seg*4+jj][row];
        *(uint2*)(g_s2t + (((size_t)(n*NHEAD + h))*LL + s0 + row)*LL + l0 + seg*4) =
            *(uint2*)tmp;
    }
}

// ---------------- 9. bilinear x4 upsample into U[:, 256:512] ----------------
__global__ void upsample_kernel() {
    int tid = threadIdx.x;
    int pix = blockIdx.x*4 + (tid >> 6);
    int cg = (tid & 63) * 4;
    int x = pix % WW;
    int y = (pix / WW) % HH;
    int n = (pix / (WW*HH)) % BATCH;
    int o =  pix / (WW*HH*BATCH);
    float sy = (y + 0.5f)*0.25f - 0.5f;
    float sx = (x + 0.5f)*0.25f - 0.5f;
    int y0 = (int)floorf(sy), x0 = (int)floorf(sx);
    float fy = sy - (float)y0, fx = sx - (float)x0;
    int y0c = min(max(y0, 0), HP-1), y1c = min(max(y0+1, 0), HP-1);
    int x0c = min(max(x0, 0), WP-1), x1c = min(max(x0+1, 0), WP-1);
    const float* mm = g_mm[o] + (size_t)n*LL*CH;
    float4 v00 = *(const float4*)(mm + (size_t)(y0c*WP + x0c)*CH + cg);
    float4 v01 = *(const float4*)(mm + (size_t)(y0c*WP + x1c)*CH + cg);
    float4 v10 = *(const float4*)(mm + (size_t)(y1c*WP + x0c)*CH + cg);
    float4 v11 = *(const float4*)(mm + (size_t)(y1c*WP + x1c)*CH + cg);
    float w00 = (1.f-fy)*(1.f-fx), w01 = (1.f-fy)*fx, w10 = fy*(1.f-fx), w11 = fy*fx;
    __half2 h0 = __floats2half2_rn(w00*v00.x + w01*v01.x + w10*v10.x + w11*v11.x,
                                   w00*v00.y + w01*v01.y + w10*v10.y + w11*v11.y);
    __half2 h1 = __floats2half2_rn(w00*v00.z + w01*v01.z + w10*v10.z + w11*v11.z,
                                   w00*v00.w + w01*v01.w + w10*v10.w + w11*v11.w);
    __half2* dst = (__half2*)(g_u + (size_t)pix*C2 + CH + cg);
    dst[0] = h0; dst[1] = h1;
}

// ---------------- 10. fused LN stats + apply + residual + write-out ----------------
__global__ __launch_bounds__(256) void out_fused_kernel(
        const float* __restrict__ x1, const float* __restrict__ x2,
        const float* __restrict__ lg, const float* __restrict__ lb,
        float* __restrict__ out) {
    int xt = blockIdx.x;
    int y  = blockIdx.y;
    int n  = blockIdx.z % BATCH;
    int o  = blockIdx.z / BATCH;
    __shared__ float zsh[32][257];
    __shared__ float smu[32], srs[32];
    int tid = threadIdx.x;
    size_t rbase = (size_t)o*NPIX + (size_t)n*HH*WW + (size_t)y*WW + xt*32;
    #pragma unroll
    for (int j = 0; j < 4; j++) {
        int px = j*8 + (tid >> 5);
        int c = (tid & 31) * 8;
        uint4 raw = *(const uint4*)(g_z2h + (rbase + px)*CH + c);
        const __half2* hp = (const __half2*)&raw;
        #pragma unroll
        for (int q = 0; q < 4; q++) {
            float2 f = __half22float2(hp[q]);
            zsh[px][c + 2*q]     = f.x;
            zsh[px][c + 2*q + 1] = f.y;
        }
    }
    __syncthreads();
    int w = tid >> 5, lane = tid & 31;
    #pragma unroll
    for (int i = 0; i < 4; i++) {
        int px = w*4 + i;
        float s = 0.f, sq = 0.f;
        #pragma unroll
        for (int k = 0; k < 8; k++) { float v = zsh[px][lane + k*32]; s += v; sq += v*v; }
        #pragma unroll
        for (int off = 16; off; off >>= 1) {
            s  += __shfl_xor_sync(0xffffffffu, s,  off);
            sq += __shfl_xor_sync(0xffffffffu, sq, off);
        }
        if (!lane) {
            float mu = s * (1.0f/CH);
            smu[px] = mu;
            srs[px] = rsqrtf(sq * (1.0f/CH) - mu*mu + EPSF);
        }
    }
    __syncthreads();
    const float* xs = o ? x2 : x1;
    int cth = tid >> 5, tx = tid & 31;
    float mu = smu[tx], rs = srs[tx];
    size_t xbase = ((size_t)(n*CH))*HH*WW + (size_t)y*WW + xt*32 + tx;
    float* outb = out + (size_t)o*NPIX*CH;
    #pragma unroll 8
    for (int cc = 0; cc < 32; cc++) {
        int c = cc*8 + cth;
        float val = lg[c]*(zsh[tx][c] - mu)*rs + lb[c];
        size_t gi = xbase + (size_t)c*HH*WW;
        outb[gi] = xs[gi] + val;
    }
}

// ---------------- launch ----------------
extern "C" void kernel_launch(void* const* d_in, const int* in_sizes, int n_in,
                              void* d_out, int out_size) {
    const float* x1     = (const float*)d_in[0];
    const float* x2     = (const float*)d_in[1];
    const float* qk_w   = (const float*)d_in[2];
    const float* qk_g   = (const float*)d_in[3];
    const float* qk_b   = (const float*)d_in[4];
    const float* qk_m   = (const float*)d_in[5];
    const float* qk_v   = (const float*)d_in[6];
    const float* v_w    = (const float*)d_in[7];
    const float* v_g    = (const float*)d_in[8];
    const float* v_b    = (const float*)d_in[9];
    const float* v_m    = (const float*)d_in[10];
    const float* v_v    = (const float*)d_in[11];
    const float* ln1_g  = (const float*)d_in[12];
    const float* ln1_b  = (const float*)d_in[13];
    const float* ln2_g  = (const float*)d_in[14];
    const float* ln2_b  = (const float*)d_in[15];
    const float* merge_w= (const float*)d_in[16];
    const float* mlp_w1 = (const float*)d_in[17];
    const float* mlp_w2 = (const float*)d_in[18];
    float* out = (float*)d_out;

    __half *pm, *pu, *pz1, *pz2h, *pmw, *pw1, *pw2;
    float *pmm;
    cudaGetSymbolAddress((void**)&pm,  g_m);
    cudaGetSymbolAddress((void**)&pmm, g_mm);
    cudaGetSymbolAddress((void**)&pu,  g_u);
    cudaGetSymbolAddress((void**)&pz1, g_z1);
    cudaGetSymbolAddress((void**)&pz2h, g_z2h);
    cudaGetSymbolAddress((void**)&pmw, g_mwh);
    cudaGetSymbolAddress((void**)&pw1, g_w1h);
    cudaGetSymbolAddress((void**)&pw2, g_w2h);

    cudaFuncSetAttribute(hgemm_kernel, cudaFuncAttributeMaxDynamicSharedMemorySize, GEMM_SMEM);
    cudaFuncSetAttribute(pux_kernel,   cudaFuncAttributeMaxDynamicSharedMemorySize, PUX_SMEM);

    roundh3_kernel<<<(C2*C2+255)/256, 256>>>(merge_w, mlp_w1, mlp_w2, pmw, pw1, pw2);

    pux_kernel<<<dim3(CH/32, HP, 2*BATCH), 256, PUX_SMEM>>>(x1, x2);
    lnfin_kernel<<<(2*BATCH*LL)/256, 256>>>();

    dwbn2_kernel<<<dim3(CH/8, BATCH, 2), 256>>>(qk_w, qk_g, qk_b, qk_m, qk_v,
                                                v_w, v_g, v_b, v_m, v_v, ln1_g, ln1_b);

    // attention (all tensor-core)
    qkmma_kernel<<<dim3(LL/128, LL/128, BATCH*NHEAD), 256>>>();
    rowstat2_kernel<<<BATCH*NHEAD*LL/256, 256>>>();
    av_kernel<<<dim3(LL/128, BATCH*NHEAD), 256>>>(0);   // m1
    s2t_kernel<<<dim3(LL/32, LL/32, BATCH), 256>>>();
    av_kernel<<<dim3(LL/128, BATCH*NHEAD), 256>>>(1);   // m2

    // merge linear
    hgemm_kernel<<<dim3(CH/128, (2*BATCH*LL)/128), 256, GEMM_SMEM>>>(
        pm, pmw, pmm, 2*BATCH*LL, CH, CH, 0, 0);

    upsample_kernel<<<NROWS/4, 256>>>();

    // MLP (z2 emitted fp16)
    hgemm_kernel<<<dim3(C2/128, NROWS/128), 256, GEMM_SMEM>>>(
        pu, pw1, pz1, NROWS, C2, C2, 1, 1);
    hgemm_kernel<<<dim3(CH/128, NROWS/128), 256, GEMM_SMEM>>>(
        pz1, pw2, pz2h, NROWS, CH, C2, 0, 1);

    out_fused_kernel<<<dim3(WW/32, HH, 2*BATCH), 256>>>(x1, x2, ln2_g, ln2_b, out);
}

// round 14
// speedup vs baseline: 1.0926x; 1.0279x over previous
#include <cuda_runtime.h>
#include <cuda_fp16.h>
#include <cstdint>

#define BATCH 4
#define CH 256
#define HH 128
#define WW 128
#define HP 32
#define WP 32
#define LL 1024
#define NHEAD 8
#define DH 32
#define C2 512
#define NPIX (BATCH*HH*WW)
#define NROWS (2*NPIX)
#define EPSF 1e-5f
#define TSCALE 0.17677669529663687f
#define NEGINF (-3.402823466e38f)
#define NTILES 16

// ---------------- scratch ----------------
__device__ float  g_p[2][BATCH*CH*LL];
__device__ float  g_lnps[2*BATCH*8*LL];
__device__ float  g_lnpq[2*BATCH*8*LL];
__device__ float  g_mu1[2*BATCH*LL];
__device__ float  g_rs1[2*BATCH*LL];
__device__ __half g_qh[2][(size_t)BATCH*LL*CH];
__device__ __half g_vh[2][(size_t)BATCH*LL*CH];
__device__ __half g_qkh[(size_t)BATCH*NHEAD*LL*LL];
__device__ __half g_s2t[(size_t)BATCH*NHEAD*LL*LL];
__device__ float  g_pmax[(size_t)BATCH*NHEAD*LL*NTILES];
__device__ float  g_psum[(size_t)BATCH*NHEAD*LL*NTILES];
__device__ float  g_rmax[BATCH*NHEAD*LL];
__device__ float  g_rinv[BATCH*NHEAD*LL];
__device__ __half g_m[2][(size_t)BATCH*LL*CH];
__device__ __half g_mmh[(size_t)2*BATCH*LL*CH];        // merge output fp16
__device__ __half g_mmw[(size_t)2*BATCH*LL*C2];        // mm @ W1b^T  (pooled-res)
__device__ __half g_u[(size_t)NROWS*CH];               // x-transposed only (256 wide)
__device__ __half g_z1[(size_t)NROWS*C2];
__device__ __half g_z2h[(size_t)NROWS*CH];
__device__ __half g_mwh[CH*CH];
__device__ __half g_w1a[C2*CH];                        // W1[:, 0:256]
__device__ __half g_w1b[C2*CH];                        // W1[:, 256:512]
__device__ __half g_w2h[CH*C2];

// ================= helpers =================
__device__ __forceinline__ uint32_t smem_u32(const void* p) {
    uint32_t a;
    asm("{ .reg .u64 t; cvta.to.shared.u64 t, %1; cvt.u32.u64 %0, t; }" : "=r"(a) : "l"(p));
    return a;
}
#define CP_ASYNC16(dst, src) \
    asm volatile("cp.async.cg.shared.global [%0], [%1], 16;" :: "r"(dst), "l"(src) : "memory")
#define CP_COMMIT() asm volatile("cp.async.commit_group;" ::: "memory")
#define CP_WAIT(n)  asm volatile("cp.async.wait_group %0;" :: "n"(n) : "memory")
#define LDSM_X4(r0, r1, r2, r3, addr) \
    asm volatile("ldmatrix.sync.aligned.m8n8.x4.shared.b16 {%0,%1,%2,%3}, [%4];" \
        : "=r"(r0), "=r"(r1), "=r"(r2), "=r"(r3) : "r"(addr))
#define LDSM_X4_T(r0, r1, r2, r3, addr) \
    asm volatile("ldmatrix.sync.aligned.m8n8.x4.trans.shared.b16 {%0,%1,%2,%3}, [%4];" \
        : "=r"(r0), "=r"(r1), "=r"(r2), "=r"(r3) : "r"(addr))

__device__ __forceinline__ void mma_f16(float* d, const uint32_t* a, uint32_t b0, uint32_t b1) {
    asm volatile(
        "mma.sync.aligned.m16n8k16.row.col.f32.f16.f16.f32 "
        "{%0,%1,%2,%3}, {%4,%5,%6,%7}, {%8,%9}, {%0,%1,%2,%3};"
        : "+f"(d[0]), "+f"(d[1]), "+f"(d[2]), "+f"(d[3])
        : "r"(a[0]), "r"(a[1]), "r"(a[2]), "r"(a[3]), "r"(b0), "r"(b1));
}

// ================= fp16 mma GEMM (validated: CTA 128x128, 3-stage) =================
#define BKH 64
#define PADH 72
#define TILEH (128*PADH)
#define TILE_BYTES (TILEH*2)
#define STAGE_BYTES (2*TILE_BYTES)
#define GEMM_SMEM (3*STAGE_BYTES)

__global__ __launch_bounds__(256) void hgemm_kernel(
        const __half* __restrict__ A, const __half* __restrict__ Bw, void* __restrict__ C,
        int M, int N, int K, int relu, int outHalf) {
    extern __shared__ __half smh[];
    int tid = threadIdx.x, wid = tid >> 5, lane = tid & 31;
    int g = lane >> 2, t = lane & 3;
    int r = lane & 7, quad = lane >> 3;
    int wm = wid >> 1, wn = wid & 1;
    size_t am0 = (size_t)blockIdx.y * 128;
    size_t bn0 = (size_t)blockIdx.x * 128;
    uint32_t smembase = smem_u32(smh);

    uint32_t a_off[2], b_off[4];
    #pragma unroll
    for (int mt = 0; mt < 2; mt++)
        a_off[mt] = (uint32_t)(((wm*32 + mt*16 + (quad&1)*8 + r)*PADH + (quad>>1)*8) * 2);
    #pragma unroll
    for (int p = 0; p < 4; p++)
        b_off[p] = (uint32_t)(((wn*64 + p*16 + (quad>>1)*8 + r)*PADH + (quad&1)*8) * 2);

    int nchunk = K >> 6;
    float acc[2][8][4];
    #pragma unroll
    for (int mt = 0; mt < 2; mt++)
        #pragma unroll
        for (int nt = 0; nt < 8; nt++)
            #pragma unroll
            for (int i = 0; i < 4; i++) acc[mt][nt][i] = 0.f;

    auto issue = [&](int ch, int st) {
        const __half* Ag = A + am0 * K + ch*BKH;
        const __half* Bg = Bw + bn0 * K + ch*BKH;
        uint32_t base = smembase + st*STAGE_BYTES;
        #pragma unroll
        for (int j = 0; j < 4; j++) {
            int idx = tid + j * 256;
            int row = idx >> 3, seg = idx & 7;
            uint32_t d = (uint32_t)((row*PADH + seg*8) * 2);
            CP_ASYNC16(base + d,              Ag + (size_t)row*K + seg*8);
            CP_ASYNC16(base + TILE_BYTES + d, Bg + (size_t)row*K + seg*8);
        }
        CP_COMMIT();
    };

    issue(0, 0);
    if (nchunk > 1) issue(1, 1);

    for (int i = 0; i < nchunk; i++) {
        int s = i % 3;
        if (i + 2 < nchunk) { issue(i + 2, (i + 2) % 3); CP_WAIT(2); }
        else if (i + 1 < nchunk) { CP_WAIT(1); }
        else { CP_WAIT(0); }
        __syncthreads();

        uint32_t abase = smembase + s*STAGE_BYTES;
        uint32_t bbase = abase + TILE_BYTES;
        #pragma unroll
        for (int ks = 0; ks < 4; ks++) {
            uint32_t koff = (uint32_t)(ks * 32);
            uint32_t af[2][4];
            LDSM_X4(af[0][0], af[0][1], af[0][2], af[0][3], abase + a_off[0] + koff);
            LDSM_X4(af[1][0], af[1][1], af[1][2], af[1][3], abase + a_off[1] + koff);
            #pragma unroll
            for (int p = 0; p < 4; p++) {
                uint32_t b0, b1, b2, b3;
                LDSM_X4(b0, b1, b2, b3, bbase + b_off[p] + koff);
                mma_f16(acc[0][2*p],   af[0], b0, b1);
                mma_f16(acc[1][2*p],   af[1], b0, b1);
                mma_f16(acc[0][2*p+1], af[0], b2, b3);
                mma_f16(acc[1][2*p+1], af[1], b2, b3);
            }
        }
        __syncthreads();
    }

    #pragma unroll
    for (int mt = 0; mt < 2; mt++) {
        size_t row = am0 + wm*32 + mt*16 + g;
        #pragma unroll
        for (int nt = 0; nt < 8; nt++) {
            size_t col = bn0 + wn*64 + nt*8 + 2*t;
            float v0 = acc[mt][nt][0], v1 = acc[mt][nt][1];
            float v2 = acc[mt][nt][2], v3 = acc[mt][nt][3];
            if (relu) {
                v0 = fmaxf(v0,0.f); v1 = fmaxf(v1,0.f);
                v2 = fmaxf(v2,0.f); v3 = fmaxf(v3,0.f);
            }
            if (outHalf) {
                __half* Ch = (__half*)C;
                *(__half2*)(Ch + row*N + col)     = __floats2half2_rn(v0, v1);
                *(__half2*)(Ch + (row+8)*N + col) = __floats2half2_rn(v2, v3);
            } else {
                float* Cf = (float*)C;
                *(float2*)(Cf + row*N + col)     = make_float2(v0, v1);
                *(float2*)(Cf + (row+8)*N + col) = make_float2(v2, v3);
            }
        }
    }
}

// ===== MLP1 GEMM with upsample-add epilogue: z1 = relu(Ux @ W1a^T + up(mmw)) =====
// A = g_u [NROWS][256], B = g_w1a [512][256], K=256 (4 chunks). grid (4, NROWS/128).
// CTA row block = one image row y of one (o,n) -> 2 pooled rows of g_mmw staged in smem.
#define UP_SMEM (2*32*128*2)               /* 16384 bytes */
#define GEMMUP_SMEM (GEMM_SMEM + UP_SMEM)
__global__ __launch_bounds__(256) void hgemm_up_kernel() {
    extern __shared__ __half smh[];
    __half* S0 = smh + 3*STAGE_BYTES/2;    // [32][128]
    __half* S1 = S0 + 32*128;
    int tid = threadIdx.x, wid = tid >> 5, lane = tid & 31;
    int g = lane >> 2, t = lane & 3;
    int r = lane & 7, quad = lane >> 3;
    int wm = wid >> 1, wn = wid & 1;
    size_t am0 = (size_t)blockIdx.y * 128;
    size_t bn0 = (size_t)blockIdx.x * 128;
    uint32_t smembase = smem_u32(smh);

    // decode pixel block: rows = (o, n, y, x=0..127)
    int o = blockIdx.y >> 9;
    int n = (blockIdx.y >> 7) & 3;
    int y = blockIdx.y & 127;
    float sy = (y + 0.5f)*0.25f - 0.5f;
    int yy0 = (int)floorf(sy);
    float fy = sy - (float)yy0;
    int y0c = min(max(yy0, 0), HP-1), y1c = min(max(yy0+1, 0), HP-1);

    // stage upsample sources: mmw rows (y0c, xp) and (y1c, xp), cols bn0..bn0+127
    {
        const __half* mb = g_mmw + ((size_t)(o*BATCH + n))*LL*C2 + bn0;
        #pragma unroll
        for (int j = 0; j < 4; j++) {
            int idx = tid*4 + j;              // 1024 uint4 total
            int which = idx >> 9, rem = idx & 511;
            int xp = rem >> 4, cseg = (rem & 15)*8;
            int yc = which ? y1c : y0c;
            __half* dst = (which ? S1 : S0) + xp*128 + cseg;
            *(uint4*)dst = *(const uint4*)(mb + (size_t)(yc*WP + xp)*C2 + cseg);
        }
    }

    uint32_t a_off[2], b_off[4];
    #pragma unroll
    for (int mt = 0; mt < 2; mt++)
        a_off[mt] = (uint32_t)(((wm*32 + mt*16 + (quad&1)*8 + r)*PADH + (quad>>1)*8) * 2);
    #pragma unroll
    for (int p = 0; p < 4; p++)
        b_off[p] = (uint32_t)(((wn*64 + p*16 + (quad>>1)*8 + r)*PADH + (quad&1)*8) * 2);

    float acc[2][8][4];
    #pragma unroll
    for (int mt = 0; mt < 2; mt++)
        #pragma unroll
        for (int nt = 0; nt < 8; nt++)
            #pragma unroll
            for (int i = 0; i < 4; i++) acc[mt][nt][i] = 0.f;

    auto issue = [&](int ch, int st) {
        const __half* Ag = g_u + am0 * CH + ch*BKH;
        const __half* Bg = g_w1a + bn0 * CH + ch*BKH;
        uint32_t base = smembase + st*STAGE_BYTES;
        #pragma unroll
        for (int j = 0; j < 4; j++) {
            int idx = tid + j * 256;
            int row = idx >> 3, seg = idx & 7;
            uint32_t d = (uint32_t)((row*PADH + seg*8) * 2);
            CP_ASYNC16(base + d,              Ag + (size_t)row*CH + seg*8);
            CP_ASYNC16(base + TILE_BYTES + d, Bg + (size_t)row*CH + seg*8);
        }
        CP_COMMIT();
    };

    issue(0, 0);
    issue(1, 1);
    for (int i = 0; i < 4; i++) {
        int s = i % 3;
        if (i + 2 < 4) { issue(i + 2, (i + 2) % 3); CP_WAIT(2); }
        else if (i + 1 < 4) { CP_WAIT(1); }
        else { CP_WAIT(0); }
        __syncthreads();
        uint32_t abase = smembase + s*STAGE_BYTES;
        uint32_t bbase = abase + TILE_BYTES;
        #pragma unroll
        for (int ks = 0; ks < 4; ks++) {
            uint32_t koff = (uint32_t)(ks * 32);
            uint32_t af[2][4];
            LDSM_X4(af[0][0], af[0][1], af[0][2], af[0][3], abase + a_off[0] + koff);
            LDSM_X4(af[1][0], af[1][1], af[1][2], af[1][3], abase + a_off[1] + koff);
            #pragma unroll
            for (int p = 0; p < 4; p++) {
                uint32_t b0, b1, b2, b3;
                LDSM_X4(b0, b1, b2, b3, bbase + b_off[p] + koff);
                mma_f16(acc[0][2*p],   af[0], b0, b1);
                mma_f16(acc[1][2*p],   af[1], b0, b1);
                mma_f16(acc[0][2*p+1], af[0], b2, b3);
                mma_f16(acc[1][2*p+1], af[1], b2, b3);
            }
        }
        __syncthreads();
    }

    // epilogue: add bilinear(up) then relu, fp16 store
    float w00 = 1.f - fy, w10 = fy;
    #pragma unroll
    for (int mt = 0; mt < 2; mt++) {
        #pragma unroll
        for (int half = 0; half < 2; half++) {
            int x = wm*32 + mt*16 + g + half*8;      // pixel x = tile row
            float sx = (x + 0.5f)*0.25f - 0.5f;
            int xx0 = (int)floorf(sx);
            float fx = sx - (float)xx0;
            int x0c = min(max(xx0, 0), WP-1), x1c = min(max(xx0+1, 0), WP-1);
            size_t grow = am0 + x;
            #pragma unroll
            for (int nt = 0; nt < 8; nt++) {
                int col = wn*64 + nt*8 + 2*t;        // 0..127 within tile
                float a0 = acc[mt][nt][half*2+0], a1 = acc[mt][nt][half*2+1];
                float u00 = __half2float(S0[x0c*128 + col]);
                float u01 = __half2float(S0[x1c*128 + col]);
                float u10 = __half2float(S1[x0c*128 + col]);
                float u11 = __half2float(S1[x1c*128 + col]);
                float up0 = w00*((1.f-fx)*u00 + fx*u01) + w10*((1.f-fx)*u10 + fx*u11);
                u00 = __half2float(S0[x0c*128 + col+1]);
                u01 = __half2float(S0[x1c*128 + col+1]);
                u10 = __half2float(S1[x0c*128 + col+1]);
                u11 = __half2float(S1[x1c*128 + col+1]);
                float up1 = w00*((1.f-fx)*u00 + fx*u01) + w10*((1.f-fx)*u10 + fx*u11);
                a0 = fmaxf(a0 + up0, 0.f);
                a1 = fmaxf(a1 + up1, 0.f);
                *(__half2*)(g_z1 + grow*C2 + bn0 + col) = __floats2half2_rn(a0, a1);
            }
        }
    }
}

// ================= QK tensor-core GEMM: logits + softmax partials =================
#define PADQ 40
__global__ __launch_bounds__(256) void qkmma_kernel() {
    __shared__ __half qs[2][128*PADQ];
    int tid = threadIdx.x, wid = tid >> 5, lane = tid & 31;
    int g = lane >> 2, t = lane & 3;
    int r = lane & 7, quad = lane >> 3;
    int wm = wid >> 1, wn = wid & 1;
    int n = blockIdx.z >> 3, h = blockIdx.z & 7;
    int l0 = blockIdx.y * 128, s0 = blockIdx.x * 128;
    uint32_t abase = smem_u32(qs[0]);
    uint32_t bbase = smem_u32(qs[1]);

    #pragma unroll
    for (int j = 0; j < 2; j++) {
        int idx = tid + j*256;
        int row = idx >> 2, seg = idx & 3;
        uint32_t d = (uint32_t)((row*PADQ + seg*8) * 2);
        const __half* Aq = g_qh[0] + ((size_t)(n*LL + l0 + row))*CH + h*DH + seg*8;
        const __half* Bq = g_qh[1] + ((size_t)(n*LL + s0 + row))*CH + h*DH + seg*8;
        CP_ASYNC16(abase + d, Aq);
        CP_ASYNC16(bbase + d, Bq);
    }
    CP_COMMIT();
    CP_WAIT(0);
    __syncthreads();

    uint32_t a_off[2], b_off[4];
    #pragma unroll
    for (int mt = 0; mt < 2; mt++)
        a_off[mt] = (uint32_t)(((wm*32 + mt*16 + (quad&1)*8 + r)*PADQ + (quad>>1)*8) * 2);
    #pragma unroll
    for (int p = 0; p < 4; p++)
        b_off[p] = (uint32_t)(((wn*64 + p*16 + (quad>>1)*8 + r)*PADQ + (quad&1)*8) * 2);

    float acc[2][8][4];
    #pragma unroll
    for (int mt = 0; mt < 2; mt++)
        #pragma unroll
        for (int nt = 0; nt < 8; nt++)
            #pragma unroll
            for (int i = 0; i < 4; i++) acc[mt][nt][i] = 0.f;

    #pragma unroll
    for (int ks = 0; ks < 2; ks++) {
        uint32_t koff = (uint32_t)(ks * 32);
        uint32_t af[2][4];
        LDSM_X4(af[0][0], af[0][1], af[0][2], af[0][3], abase + a_off[0] + koff);
        LDSM_X4(af[1][0], af[1][1], af[1][2], af[1][3], abase + a_off[1] + koff);
        #pragma unroll
        for (int p = 0; p < 4; p++) {
            uint32_t b0, b1, b2, b3;
            LDSM_X4(b0, b1, b2, b3, bbase + b_off[p] + koff);
            mma_f16(acc[0][2*p],   af[0], b0, b1);
            mma_f16(acc[1][2*p],   af[1], b0, b1);
            mma_f16(acc[0][2*p+1], af[0], b2, b3);
            mma_f16(acc[1][2*p+1], af[1], b2, b3);
        }
    }

    size_t qkbase = ((size_t)(n*NHEAD + h))*LL;
    int tile = blockIdx.x*2 + wn;
    #pragma unroll
    for (int mt = 0; mt < 2; mt++) {
        int row0 = l0 + wm*32 + mt*16 + g;
        float mx0 = NEGINF, mx1 = NEGINF;
        float vals[8][4];
        #pragma unroll
        for (int nt = 0; nt < 8; nt++) {
            #pragma unroll
            for (int i = 0; i < 4; i++) vals[nt][i] = TSCALE*acc[mt][nt][i];
            int col = s0 + wn*64 + nt*8 + 2*t;
            *(__half2*)(g_qkh + (qkbase + row0)*LL + col)   = __floats2half2_rn(vals[nt][0], vals[nt][1]);
            *(__half2*)(g_qkh + (qkbase + row0+8)*LL + col) = __floats2half2_rn(vals[nt][2], vals[nt][3]);
            mx0 = fmaxf(mx0, fmaxf(vals[nt][0], vals[nt][1]));
            mx1 = fmaxf(mx1, fmaxf(vals[nt][2], vals[nt][3]));
        }
        #pragma unroll
        for (int off = 1; off <= 2; off <<= 1) {
            mx0 = fmaxf(mx0, __shfl_xor_sync(0xffffffffu, mx0, off));
            mx1 = fmaxf(mx1, __shfl_xor_sync(0xffffffffu, mx1, off));
        }
        float sm0 = 0.f, sm1 = 0.f;
        #pragma unroll
        for (int nt = 0; nt < 8; nt++) {
            sm0 += __expf(vals[nt][0]-mx0) + __expf(vals[nt][1]-mx0);
            sm1 += __expf(vals[nt][2]-mx1) + __expf(vals[nt][3]-mx1);
        }
        #pragma unroll
        for (int off = 1; off <= 2; off <<= 1) {
            sm0 += __shfl_xor_sync(0xffffffffu, sm0, off);
            sm1 += __shfl_xor_sync(0xffffffffu, sm1, off);
        }
        if (t == 0) {
            g_pmax[(qkbase + row0)*NTILES + tile]   = mx0;
            g_psum[(qkbase + row0)*NTILES + tile]   = sm0;
            g_pmax[(qkbase + row0+8)*NTILES + tile] = mx1;
            g_psum[(qkbase + row0+8)*NTILES + tile] = sm1;
        }
    }
}

// ================= unified AV tensor-core GEMM (m1 / m2) =================
#define PADA 72
#define PADB 40
__global__ __launch_bounds__(256) void av_kernel(int which) {
    __shared__ __half As[128*PADA];
    __shared__ __half Bs[64*PADB];
    __shared__ float mxs[128], ris[128];
    int t = threadIdx.x, wid = t >> 5, lane = t & 31;
    int r = lane & 7, quad = lane >> 3;
    int n = blockIdx.y >> 3, h = blockIdx.y & 7;
    int m0 = blockIdx.x * 128;
    size_t lbase = ((size_t)(n*NHEAD + h))*LL + m0;
    const __half* Asrc = (which == 0 ? g_qkh : g_s2t);
    const __half* Bsrc = g_vh[which ^ 1] + ((size_t)(n*LL))*CH + h*DH;
    uint32_t asm_b = smem_u32(As), bsm_b = smem_u32(Bs);

    if (which == 0 && t < 128) {
        mxs[t] = g_rmax[lbase + t];
        ris[t] = g_rinv[lbase + t];
    }
    __syncthreads();

    uint32_t a_off = (uint32_t)(((wid*16 + (quad&1)*8 + r)*PADA + (quad>>1)*8) * 2);
    float acc[4][4];
    #pragma unroll
    for (int nt = 0; nt < 4; nt++)
        #pragma unroll
        for (int i = 0; i < 4; i++) acc[nt][i] = 0.f;

    for (int k0 = 0; k0 < LL; k0 += 64) {
        {
            int row = t >> 1, half0 = (t & 1)*32;
            const __half* src = Asrc + (lbase + row)*LL + k0 + half0;
            __half* dst = As + row*PADA + half0;
            if (which == 0) {
                float mx = mxs[row], ri = ris[row];
                #pragma unroll
                for (int j = 0; j < 4; j++) {
                    uint4 raw = *(const uint4*)(src + j*8);
                    __half2* hp = (__half2*)&raw;
                    __half2 o[4];
                    #pragma unroll
                    for (int q = 0; q < 4; q++) {
                        float2 f = __half22float2(hp[q]);
                        o[q] = __floats2half2_rn(__expf(f.x - mx)*ri, __expf(f.y - mx)*ri);
                    }
                    *(uint4*)(dst + j*8) = *(uint4*)o;
                }
            } else {
                #pragma unroll
                for (int j = 0; j < 4; j++)
                    *(uint4*)(dst + j*8) = *(const uint4*)(src + j*8);
            }
        }
        {
            int row = t >> 2, seg = (t & 3)*8;
            *(uint4*)(Bs + row*PADB + seg) = *(const uint4*)(Bsrc + (size_t)(k0 + row)*CH + seg);
        }
        __syncthreads();

        #pragma unroll
        for (int ks = 0; ks < 4; ks++) {
            uint32_t af[4];
            LDSM_X4(af[0], af[1], af[2], af[3], asm_b + a_off + (uint32_t)(ks*32));
            #pragma unroll
            for (int p = 0; p < 2; p++) {
                uint32_t b0, b1, b2, b3;
                uint32_t boff = (uint32_t)(((ks*16 + (quad&1)*8 + r)*PADB + p*16 + (quad>>1)*8) * 2);
                LDSM_X4_T(b0, b1, b2, b3, bsm_b + boff);
                mma_f16(acc[2*p],   af, b0, b1);
                mma_f16(acc[2*p+1], af, b2, b3);
            }
        }
        __syncthreads();
    }

    int rrow = lane >> 2, ccol = (lane & 3)*2;
    #pragma unroll
    for (int nt = 0; nt < 4; nt++) {
        size_t orow = (size_t)(n*LL + m0 + wid*16 + rrow);
        __half* dst = g_m[which] + orow*CH + h*DH + nt*8 + ccol;
        *(__half2*)dst            = __floats2half2_rn(acc[nt][0], acc[nt][1]);
        *(__half2*)(dst + 8*CH)   = __floats2half2_rn(acc[nt][2], acc[nt][3]);
    }
}

// ---------------- weight fp16 prepass (splits W1 halves) ----------------
__global__ void roundh3_kernel(const float* __restrict__ mw, const float* __restrict__ w1,
                               const float* __restrict__ w2) {
    int i = blockIdx.x*256 + threadIdx.x;
    if (i < CH*CH) g_mwh[i] = __float2half_rn(mw[i]);
    if (i < CH*C2) g_w2h[i] = __float2half_rn(w2[i]);
    if (i < C2*C2) {
        int nrow = i >> 9, k = i & 511;
        __half v = __float2half_rn(w1[i]);
        if (k < CH) g_w1a[nrow*CH + k] = v;
        else        g_w1b[nrow*CH + k - CH] = v;
    }
}

// ---------------- 1. fused maxpool + xcopy + LN partials ----------------
#define PUX_PITCH 516
#define PUX_SMEM ((32*PUX_PITCH + 32*33)*4)
__global__ __launch_bounds__(256) void pux_kernel(const float* __restrict__ x1,
                                                  const float* __restrict__ x2) {
    extern __shared__ float sh[];
    float* po = sh + 32*PUX_PITCH;
    int ct = blockIdx.x;
    int y4 = blockIdx.y;
    int n  = blockIdx.z & 3;
    int o  = blockIdx.z >> 2;
    const float* xs = o ? x2 : x1;
    int tid = threadIdx.x;
    int c0 = ct*32;
    #pragma unroll
    for (int i = 0; i < 16; i++) {
        int f = tid + i*256;
        int cc = f >> 7, rem = f & 127;
        int yy = rem >> 5, c4 = rem & 31;
        float4 v = *(const float4*)(xs +
            (((size_t)(n*CH + c0+cc))*HH + y4*4+yy)*WW + c4*4);
        *(float4*)&sh[cc*PUX_PITCH + yy*128 + c4*4] = v;
    }
    __syncthreads();
    {
        int c = tid >> 3, xo = (tid & 7)*4;
        float4 out;
        float* pov = &out.x;
        #pragma unroll
        for (int k = 0; k < 4; k++) {
            int px = xo + k;
            float m = NEGINF;
            #pragma unroll
            for (int yy = 0; yy < 4; yy++) {
                float4 v = *(const float4*)&sh[c*PUX_PITCH + yy*128 + px*4];
                m = fmaxf(m, fmaxf(fmaxf(v.x, v.y), fmaxf(v.z, v.w)));
            }
            pov[k] = m;
            po[c*33 + px] = m;
        }
        *(float4*)(g_p[o] + ((size_t)(n*CH + c0 + c))*LL + y4*32 + xo) = out;
    }
    __syncthreads();
    if (tid < 32) {
        float s = 0.f, sq = 0.f;
        #pragma unroll
        for (int c = 0; c < 32; c++) { float v = po[c*33 + tid]; s += v; sq += v*v; }
        int sp = y4*32 + tid;
        size_t pidx = (((size_t)(o*BATCH + n))*8 + ct)*LL + sp;
        g_lnps[pidx] = s;
        g_lnpq[pidx] = sq;
    }
    size_t rbase = (size_t)o*NPIX + (size_t)n*HH*WW + (size_t)(y4*4)*WW;
    #pragma unroll
    for (int j = 0; j < 2; j++) {
        int p = tid + j*256;
        __half2 hb[16];
        #pragma unroll
        for (int cc = 0; cc < 32; cc += 2)
            hb[cc>>1] = __floats2half2_rn(sh[cc*PUX_PITCH + p], sh[(cc+1)*PUX_PITCH + p]);
        uint4* dst = (uint4*)(g_u + (rbase + p)*CH + c0);
        const uint4* src = (const uint4*)hb;
        dst[0] = src[0]; dst[1] = src[1]; dst[2] = src[2]; dst[3] = src[3];
    }
}

// ---------------- 2. finalize LN stats ----------------
__global__ void lnfin_kernel() {
    int gi = blockIdx.x*256 + threadIdx.x;
    int on = gi / LL, sp = gi % LL;
    float s = 0.f, sq = 0.f;
    #pragma unroll
    for (int ctt = 0; ctt < 8; ctt++) {
        size_t pidx = (((size_t)on)*8 + ctt)*LL + sp;
        s += g_lnps[pidx]; sq += g_lnpq[pidx];
    }
    float mu = s * (1.0f/CH);
    g_mu1[gi] = mu;
    g_rs1[gi] = rsqrtf(sq * (1.0f/CH) - mu*mu + EPSF);
}

// ---------------- 3. dwconv3x3 + BN (LN inline), q/k/v fp16 out ----------------
__global__ __launch_bounds__(256) void dwbn2_kernel(
        const float* __restrict__ qw, const float* __restrict__ qg, const float* __restrict__ qb,
        const float* __restrict__ qm, const float* __restrict__ qvv,
        const float* __restrict__ vw, const float* __restrict__ vg, const float* __restrict__ vb,
        const float* __restrict__ vm, const float* __restrict__ vvv,
        const float* __restrict__ l1g, const float* __restrict__ l1b) {
    int c0 = blockIdx.x * 8;
    int n  = blockIdx.y;
    int o  = blockIdx.z;
    __shared__ float sp[8*1028];
    int t = threadIdx.x;
    const float* mub = g_mu1 + (size_t)(o*BATCH + n)*LL;
    const float* rsb = g_rs1 + (size_t)(o*BATCH + n)*LL;
    #pragma unroll
    for (int cc = 0; cc < 8; cc++) {
        float gc = l1g[c0+cc], bc = l1b[c0+cc];
        #pragma unroll
        for (int it = 0; it < 4; it++) {
            int spi = t + it*256;
            float raw = g_p[o][((size_t)(n*CH + c0+cc))*LL + spi];
            sp[cc*1028 + spi] = gc*(raw - mub[spi])*rsb[spi] + bc;
        }
    }
    __syncthreads();

    int cc = t & 7, jq = t >> 3;
    int c = c0 + cc;
    float wq[9], wv[9];
    #pragma unroll
    for (int k = 0; k < 9; k++) { wq[k] = qw[c*9+k]; wv[k] = vw[c*9+k]; }
    float scq = qg[c]*rsqrtf(qvv[c]+EPSF), bq = qb[c] - scq*qm[c];
    float scv = vg[c]*rsqrtf(vvv[c]+EPSF), bv = vb[c] - scv*vm[c];
    const float* s = sp + cc*1028;
    __half* oq = g_qh[o] + (size_t)(n*LL)*CH + c;
    __half* ov = g_vh[o] + (size_t)(n*LL)*CH + c;

    for (int i = 0; i < 32; i++) {
        float aq = 0.f, av = 0.f;
        #pragma unroll
        for (int di = 0; di < 3; di++) {
            int ii = i + di - 1;
            if (ii < 0 || ii >= HP) continue;
            #pragma unroll
            for (int dj = 0; dj < 3; dj++) {
                int jj = jq + dj - 1;
                if (jj < 0 || jj >= WP) continue;
                float x = s[ii*32 + jj];
                aq += wq[di*3+dj]*x;
                av += wv[di*3+dj]*x;
            }
        }
        int l = i*32 + jq;
        oq[(size_t)l*CH] = __float2half_rn(scq*aq + bq);
        ov[(size_t)l*CH] = __float2half_rn(scv*av + bv);
    }
}

// ---------------- 5. combine tile partials ----------------
__global__ void rowstat2_kernel() {
    int r = blockIdx.x*256 + threadIdx.x;
    float pm[NTILES];
    float m = NEGINF;
    #pragma unroll
    for (int i = 0; i < NTILES; i++) {
        pm[i] = g_pmax[(size_t)r*NTILES + i];
        m = fmaxf(m, pm[i]);
    }
    float sum = 0.f;
    #pragma unroll
    for (int i = 0; i < NTILES; i++)
        sum += g_psum[(size_t)r*NTILES + i] * __expf(pm[i] - m);
    g_rmax[r] = m;
    g_rinv[r] = 1.f/sum;
}

// ---------------- 7. S2 softmax over heads + transpose ----------------
__global__ __launch_bounds__(256) void s2t_kernel() {
    __shared__ __half sm[8][32][36];
    int t = threadIdx.x;
    int s0 = blockIdx.x*32, l0 = blockIdx.y*32, n = blockIdx.z;
    int row = t >> 3, seg = t & 7;
    #pragma unroll
    for (int h = 0; h < NHEAD; h++) {
        uint2 v = *(const uint2*)(g_qkh +
            (((size_t)(n*NHEAD + h))*LL + l0 + row)*LL + s0 + seg*4);
        *(uint2*)&sm[h][row][seg*4] = v;
    }
    __syncthreads();
    #pragma unroll
    for (int j = 0; j < 4; j++) {
        int e = t*4 + j;
        int l = e >> 5, s = e & 31;
        float v[NHEAD];
        float mx = NEGINF;
        #pragma unroll
        for (int h = 0; h < NHEAD; h++) {
            v[h] = __half2float(sm[h][l][s]);
            mx = fmaxf(mx, v[h]);
        }
        float smm = 0.f;
        #pragma unroll
        for (int h = 0; h < NHEAD; h++) { v[h] = __expf(v[h]-mx); smm += v[h]; }
        float ri = 1.f/smm;
        #pragma unroll
        for (int h = 0; h < NHEAD; h++)
            sm[h][l][s] = __float2half_rn(v[h]*ri);
    }
    __syncthreads();
    #pragma unroll
    for (int h = 0; h < NHEAD; h++) {
        __half tmp[4];
        #pragma unroll
        for (int jj = 0; jj < 4; jj++) tmp[jj] = sm[h][seg*4+jj][row];
        *(uint2*)(g_s2t + (((size_t)(n*NHEAD + h))*LL + s0 + row)*LL + l0 + seg*4) =
            *(uint2*)tmp;
    }
}

// ---------------- 10. fused LN stats + apply + residual + write-out ----------------
__global__ __launch_bounds__(256) void out_fused_kernel(
        const float* __restrict__ x1, const float* __restrict__ x2,
        const float* __restrict__ lg, const float* __restrict__ lb,
        float* __restrict__ out) {
    int xt = blockIdx.x;
    int y  = blockIdx.y;
    int n  = blockIdx.z % BATCH;
    int o  = blockIdx.z / BATCH;
    __shared__ float zsh[32][257];
    __shared__ float smu[32], srs[32];
    int tid = threadIdx.x;
    size_t rbase = (size_t)o*NPIX + (size_t)n*HH*WW + (size_t)y*WW + xt*32;
    #pragma unroll
    for (int j = 0; j < 4; j++) {
        int px = j*8 + (tid >> 5);
        int c = (tid & 31) * 8;
        uint4 raw = *(const uint4*)(g_z2h + (rbase + px)*CH + c);
        const __half2* hp = (const __half2*)&raw;
        #pragma unroll
        for (int q = 0; q < 4; q++) {
            float2 f = __half22float2(hp[q]);
            zsh[px][c + 2*q]     = f.x;
            zsh[px][c + 2*q + 1] = f.y;
        }
    }
    __syncthreads();
    int w = tid >> 5, lane = tid & 31;
    #pragma unroll
    for (int i = 0; i < 4; i++) {
        int px = w*4 + i;
        float s = 0.f, sq = 0.f;
        #pragma unroll
        for (int k = 0; k < 8; k++) { float v = zsh[px][lane + k*32]; s += v; sq += v*v; }
        #pragma unroll
        for (int off = 16; off; off >>= 1) {
            s  += __shfl_xor_sync(0xffffffffu, s,  off);
            sq += __shfl_xor_sync(0xffffffffu, sq, off);
        }
        if (!lane) {
            float mu = s * (1.0f/CH);
            smu[px] = mu;
            srs[px] = rsqrtf(sq * (1.0f/CH) - mu*mu + EPSF);
        }
    }
    __syncthreads();
    const float* xs = o ? x2 : x1;
    int cth = tid >> 5, tx = tid & 31;
    float mu = smu[tx], rs = srs[tx];
    size_t xbase = ((size_t)(n*CH))*HH*WW + (size_t)y*WW + xt*32 + tx;
    float* outb = out + (size_t)o*NPIX*CH;
    #pragma unroll 8
    for (int cc = 0; cc < 32; cc++) {
        int c = cc*8 + cth;
        float val = lg[c]*(zsh[tx][c] - mu)*rs + lb[c];
        size_t gi = xbase + (size_t)c*HH*WW;
        outb[gi] = xs[gi] + val;
    }
}

// ---------------- launch ----------------
extern "C" void kernel_launch(void* const* d_in, const int* in_sizes, int n_in,
                              void* d_out, int out_size) {
    const float* x1     = (const float*)d_in[0];
    const float* x2     = (const float*)d_in[1];
    const float* qk_w   = (const float*)d_in[2];
    const float* qk_g   = (const float*)d_in[3];
    const float* qk_b   = (const float*)d_in[4];
    const float* qk_m   = (const float*)d_in[5];
    const float* qk_v   = (const float*)d_in[6];
    const float* v_w    = (const float*)d_in[7];
    const float* v_g    = (const float*)d_in[8];
    const float* v_b    = (const float*)d_in[9];
    const float* v_m    = (const float*)d_in[10];
    const float* v_v    = (const float*)d_in[11];
    const float* ln1_g  = (const float*)d_in[12];
    const float* ln1_b  = (const float*)d_in[13];
    const float* ln2_g  = (const float*)d_in[14];
    const float* ln2_b  = (const float*)d_in[15];
    const float* merge_w= (const float*)d_in[16];
    const float* mlp_w1 = (const float*)d_in[17];
    const float* mlp_w2 = (const float*)d_in[18];
    float* out = (float*)d_out;

    __half *pm, *pmmh, *pmmw, *pu, *pz1, *pz2h, *pmw, *pw1b, *pw2;
    cudaGetSymbolAddress((void**)&pm,   g_m);
    cudaGetSymbolAddress((void**)&pmmh, g_mmh);
    cudaGetSymbolAddress((void**)&pmmw, g_mmw);
    cudaGetSymbolAddress((void**)&pu,   g_u);
    cudaGetSymbolAddress((void**)&pz1,  g_z1);
    cudaGetSymbolAddress((void**)&pz2h, g_z2h);
    cudaGetSymbolAddress((void**)&pmw,  g_mwh);
    cudaGetSymbolAddress((void**)&pw1b, g_w1b);
    cudaGetSymbolAddress((void**)&pw2,  g_w2h);

    cudaFuncSetAttribute(hgemm_kernel,    cudaFuncAttributeMaxDynamicSharedMemorySize, GEMM_SMEM);
    cudaFuncSetAttribute(hgemm_up_kernel, cudaFuncAttributeMaxDynamicSharedMemorySize, GEMMUP_SMEM);
    cudaFuncSetAttribute(pux_kernel,      cudaFuncAttributeMaxDynamicSharedMemorySize, PUX_SMEM);

    roundh3_kernel<<<(C2*C2+255)/256, 256>>>(merge_w, mlp_w1, mlp_w2);

    pux_kernel<<<dim3(CH/32, HP, 2*BATCH), 256, PUX_SMEM>>>(x1, x2);
    lnfin_kernel<<<(2*BATCH*LL)/256, 256>>>();

    dwbn2_kernel<<<dim3(CH/8, BATCH, 2), 256>>>(qk_w, qk_g, qk_b, qk_m, qk_v,
                                                v_w, v_g, v_b, v_m, v_v, ln1_g, ln1_b);

    // attention (all tensor-core)
    qkmma_kernel<<<dim3(LL/128, LL/128, BATCH*NHEAD), 256>>>();
    rowstat2_kernel<<<BATCH*NHEAD*LL/256, 256>>>();
    av_kernel<<<dim3(LL/128, BATCH*NHEAD), 256>>>(0);   // m1
    s2t_kernel<<<dim3(LL/32, LL/32, BATCH), 256>>>();
    av_kernel<<<dim3(LL/128, BATCH*NHEAD), 256>>>(1);   // m2

    // merge linear -> fp16 mm
    hgemm_kernel<<<dim3(CH/128, (2*BATCH*LL)/128), 256, GEMM_SMEM>>>(
        pm, pmw, pmmh, 2*BATCH*LL, CH, CH, 0, 1);
    // mmw = mm @ W1b^T  (pooled-resolution right-half contribution)
    hgemm_kernel<<<dim3(C2/128, (2*BATCH*LL)/128), 256, GEMM_SMEM>>>(
        pmmh, pw1b, pmmw, 2*BATCH*LL, C2, CH, 0, 1);

    // MLP1: x-half GEMM + upsample-add + relu (K=256)
    hgemm_up_kernel<<<dim3(C2/128, NROWS/128), 256, GEMMUP_SMEM>>>();
    // MLP2 (z2 fp16)
    hgemm_kernel<<<dim3(CH/128, NROWS/128), 256, GEMM_SMEM>>>(
        pz1, pw2, pz2h, NROWS, CH, C2, 0, 1);

    out_fused_kernel<<<dim3(WW/32, HH, 2*BATCH), 256>>>(x1, x2, ln2_g, ln2_b, out);
}

// round 15
// speedup vs baseline: 1.0999x; 1.0067x over previous
#include <cuda_runtime.h>
#include <cuda_fp16.h>
#include <cstdint>

#define BATCH 4
#define CH 256
#define HH 128
#define WW 128
#define HP 32
#define WP 32
#define LL 1024
#define NHEAD 8
#define DH 32
#define C2 512
#define NPIX (BATCH*HH*WW)
#define NROWS (2*NPIX)
#define EPSF 1e-5f
#define TSCALE 0.17677669529663687f
#define NEGINF (-3.402823466e38f)
#define NTILES 16

// ---------------- scratch ----------------
__device__ float  g_p[2][BATCH*CH*LL];
__device__ float  g_lnps[2*BATCH*8*LL];
__device__ float  g_lnpq[2*BATCH*8*LL];
__device__ float  g_mu1[2*BATCH*LL];
__device__ float  g_rs1[2*BATCH*LL];
__device__ __half g_qh[2][(size_t)BATCH*LL*CH];
__device__ __half g_vh[2][(size_t)BATCH*LL*CH];
__device__ __half g_qkh[(size_t)BATCH*NHEAD*LL*LL];
__device__ __half g_s2t[(size_t)BATCH*NHEAD*LL*LL];
__device__ float  g_pmax[(size_t)BATCH*NHEAD*LL*NTILES];
__device__ float  g_psum[(size_t)BATCH*NHEAD*LL*NTILES];
__device__ float  g_rmax[BATCH*NHEAD*LL];
__device__ float  g_rinv[BATCH*NHEAD*LL];
__device__ __half g_m[2][(size_t)BATCH*LL*CH];
__device__ __half g_mmh[(size_t)2*BATCH*LL*CH];        // merge output fp16
__device__ __half g_mmw[(size_t)2*BATCH*LL*C2];        // mm @ W1b^T  (pooled-res)
__device__ __half g_u[(size_t)NROWS*CH];               // x-transposed only (256 wide)
__device__ __half g_z1[(size_t)NROWS*C2];
__device__ __half g_z2h[(size_t)NROWS*CH];
__device__ __half g_mwh[CH*CH];
__device__ __half g_w1a[C2*CH];                        // W1[:, 0:256]
__device__ __half g_w1b[C2*CH];                        // W1[:, 256:512]
__device__ __half g_w2h[CH*C2];

// ================= helpers =================
__device__ __forceinline__ uint32_t smem_u32(const void* p) {
    uint32_t a;
    asm("{ .reg .u64 t; cvta.to.shared.u64 t, %1; cvt.u32.u64 %0, t; }" : "=r"(a) : "l"(p));
    return a;
}
#define CP_ASYNC16(dst, src) \
    asm volatile("cp.async.cg.shared.global [%0], [%1], 16;" :: "r"(dst), "l"(src) : "memory")
#define CP_COMMIT() asm volatile("cp.async.commit_group;" ::: "memory")
#define CP_WAIT(n)  asm volatile("cp.async.wait_group %0;" :: "n"(n) : "memory")
#define LDSM_X4(r0, r1, r2, r3, addr) \
    asm volatile("ldmatrix.sync.aligned.m8n8.x4.shared.b16 {%0,%1,%2,%3}, [%4];" \
        : "=r"(r0), "=r"(r1), "=r"(r2), "=r"(r3) : "r"(addr))
#define LDSM_X4_T(r0, r1, r2, r3, addr) \
    asm volatile("ldmatrix.sync.aligned.m8n8.x4.trans.shared.b16 {%0,%1,%2,%3}, [%4];" \
        : "=r"(r0), "=r"(r1), "=r"(r2), "=r"(r3) : "r"(addr))

__device__ __forceinline__ void mma_f16(float* d, const uint32_t* a, uint32_t b0, uint32_t b1) {
    asm volatile(
        "mma.sync.aligned.m16n8k16.row.col.f32.f16.f16.f32 "
        "{%0,%1,%2,%3}, {%4,%5,%6,%7}, {%8,%9}, {%0,%1,%2,%3};"
        : "+f"(d[0]), "+f"(d[1]), "+f"(d[2]), "+f"(d[3])
        : "r"(a[0]), "r"(a[1]), "r"(a[2]), "r"(a[3]), "r"(b0), "r"(b1));
}

// ================= fp16 mma GEMM (validated: CTA 128x128, 3-stage) =================
#define BKH 64
#define PADH 72
#define TILEH (128*PADH)
#define TILE_BYTES (TILEH*2)
#define STAGE_BYTES (2*TILE_BYTES)
#define GEMM_SMEM (3*STAGE_BYTES)

__global__ __launch_bounds__(256) void hgemm_kernel(
        const __half* __restrict__ A, const __half* __restrict__ Bw, void* __restrict__ C,
        int M, int N, int K, int relu, int outHalf) {
    extern __shared__ __half smh[];
    int tid = threadIdx.x, wid = tid >> 5, lane = tid & 31;
    int g = lane >> 2, t = lane & 3;
    int r = lane & 7, quad = lane >> 3;
    int wm = wid >> 1, wn = wid & 1;
    size_t am0 = (size_t)blockIdx.y * 128;
    size_t bn0 = (size_t)blockIdx.x * 128;
    uint32_t smembase = smem_u32(smh);

    uint32_t a_off[2], b_off[4];
    #pragma unroll
    for (int mt = 0; mt < 2; mt++)
        a_off[mt] = (uint32_t)(((wm*32 + mt*16 + (quad&1)*8 + r)*PADH + (quad>>1)*8) * 2);
    #pragma unroll
    for (int p = 0; p < 4; p++)
        b_off[p] = (uint32_t)(((wn*64 + p*16 + (quad>>1)*8 + r)*PADH + (quad&1)*8) * 2);

    int nchunk = K >> 6;
    float acc[2][8][4];
    #pragma unroll
    for (int mt = 0; mt < 2; mt++)
        #pragma unroll
        for (int nt = 0; nt < 8; nt++)
            #pragma unroll
            for (int i = 0; i < 4; i++) acc[mt][nt][i] = 0.f;

    auto issue = [&](int ch, int st) {
        const __half* Ag = A + am0 * K + ch*BKH;
        const __half* Bg = Bw + bn0 * K + ch*BKH;
        uint32_t base = smembase + st*STAGE_BYTES;
        #pragma unroll
        for (int j = 0; j < 4; j++) {
            int idx = tid + j * 256;
            int row = idx >> 3, seg = idx & 7;
            uint32_t d = (uint32_t)((row*PADH + seg*8) * 2);
            CP_ASYNC16(base + d,              Ag + (size_t)row*K + seg*8);
            CP_ASYNC16(base + TILE_BYTES + d, Bg + (size_t)row*K + seg*8);
        }
        CP_COMMIT();
    };

    issue(0, 0);
    if (nchunk > 1) issue(1, 1);

    for (int i = 0; i < nchunk; i++) {
        int s = i % 3;
        if (i + 2 < nchunk) { issue(i + 2, (i + 2) % 3); CP_WAIT(2); }
        else if (i + 1 < nchunk) { CP_WAIT(1); }
        else { CP_WAIT(0); }
        __syncthreads();

        uint32_t abase = smembase + s*STAGE_BYTES;
        uint32_t bbase = abase + TILE_BYTES;
        #pragma unroll
        for (int ks = 0; ks < 4; ks++) {
            uint32_t koff = (uint32_t)(ks * 32);
            uint32_t af[2][4];
            LDSM_X4(af[0][0], af[0][1], af[0][2], af[0][3], abase + a_off[0] + koff);
            LDSM_X4(af[1][0], af[1][1], af[1][2], af[1][3], abase + a_off[1] + koff);
            #pragma unroll
            for (int p = 0; p < 4; p++) {
                uint32_t b0, b1, b2, b3;
                LDSM_X4(b0, b1, b2, b3, bbase + b_off[p] + koff);
                mma_f16(acc[0][2*p],   af[0], b0, b1);
                mma_f16(acc[1][2*p],   af[1], b0, b1);
                mma_f16(acc[0][2*p+1], af[0], b2, b3);
                mma_f16(acc[1][2*p+1], af[1], b2, b3);
            }
        }
        __syncthreads();
    }

    #pragma unroll
    for (int mt = 0; mt < 2; mt++) {
        size_t row = am0 + wm*32 + mt*16 + g;
        #pragma unroll
        for (int nt = 0; nt < 8; nt++) {
            size_t col = bn0 + wn*64 + nt*8 + 2*t;
            float v0 = acc[mt][nt][0], v1 = acc[mt][nt][1];
            float v2 = acc[mt][nt][2], v3 = acc[mt][nt][3];
            if (relu) {
                v0 = fmaxf(v0,0.f); v1 = fmaxf(v1,0.f);
                v2 = fmaxf(v2,0.f); v3 = fmaxf(v3,0.f);
            }
            if (outHalf) {
                __half* Ch = (__half*)C;
                *(__half2*)(Ch + row*N + col)     = __floats2half2_rn(v0, v1);
                *(__half2*)(Ch + (row+8)*N + col) = __floats2half2_rn(v2, v3);
            } else {
                float* Cf = (float*)C;
                *(float2*)(Cf + row*N + col)     = make_float2(v0, v1);
                *(float2*)(Cf + (row+8)*N + col) = make_float2(v2, v3);
            }
        }
    }
}

// ===== MLP1 GEMM with upsample-add epilogue: z1 = relu(Ux @ W1a^T + up(mmw)) =====
// 2-STAGE pipeline (4 K-chunks): smem = 2*36864 + 16384 = 90112 -> 2 CTAs/SM.
#define UP_SMEM (2*32*128*2)               /* 16384 bytes */
#define GEMMUP_SMEM (2*STAGE_BYTES + UP_SMEM)
__global__ __launch_bounds__(256) void hgemm_up_kernel() {
    extern __shared__ __half smh[];
    __half* S0 = smh + STAGE_BYTES;        // after 2 stages (in halves: 2*STAGE_BYTES/2)
    S0 = smh + STAGE_BYTES;                // (STAGE_BYTES halves == 2 stages of bytes)
    __half* S1 = S0 + 32*128;
    int tid = threadIdx.x, wid = tid >> 5, lane = tid & 31;
    int g = lane >> 2, t = lane & 3;
    int r = lane & 7, quad = lane >> 3;
    int wm = wid >> 1, wn = wid & 1;
    size_t am0 = (size_t)blockIdx.y * 128;
    size_t bn0 = (size_t)blockIdx.x * 128;
    uint32_t smembase = smem_u32(smh);

    // decode pixel block: rows = (o, n, y, x=0..127)
    int o = blockIdx.y >> 9;
    int n = (blockIdx.y >> 7) & 3;
    int y = blockIdx.y & 127;
    float sy = (y + 0.5f)*0.25f - 0.5f;
    int yy0 = (int)floorf(sy);
    float fy = sy - (float)yy0;
    int y0c = min(max(yy0, 0), HP-1), y1c = min(max(yy0+1, 0), HP-1);

    // stage upsample sources
    {
        const __half* mb = g_mmw + ((size_t)(o*BATCH + n))*LL*C2 + bn0;
        #pragma unroll
        for (int j = 0; j < 4; j++) {
            int idx = tid*4 + j;
            int which = idx >> 9, rem = idx & 511;
            int xp = rem >> 4, cseg = (rem & 15)*8;
            int yc = which ? y1c : y0c;
            __half* dst = (which ? S1 : S0) + xp*128 + cseg;
            *(uint4*)dst = *(const uint4*)(mb + (size_t)(yc*WP + xp)*C2 + cseg);
        }
    }

    uint32_t a_off[2], b_off[4];
    #pragma unroll
    for (int mt = 0; mt < 2; mt++)
        a_off[mt] = (uint32_t)(((wm*32 + mt*16 + (quad&1)*8 + r)*PADH + (quad>>1)*8) * 2);
    #pragma unroll
    for (int p = 0; p < 4; p++)
        b_off[p] = (uint32_t)(((wn*64 + p*16 + (quad>>1)*8 + r)*PADH + (quad&1)*8) * 2);

    float acc[2][8][4];
    #pragma unroll
    for (int mt = 0; mt < 2; mt++)
        #pragma unroll
        for (int nt = 0; nt < 8; nt++)
            #pragma unroll
            for (int i = 0; i < 4; i++) acc[mt][nt][i] = 0.f;

    auto issue = [&](int ch, int st) {
        const __half* Ag = g_u + am0 * CH + ch*BKH;
        const __half* Bg = g_w1a + bn0 * CH + ch*BKH;
        uint32_t base = smembase + st*STAGE_BYTES;
        #pragma unroll
        for (int j = 0; j < 4; j++) {
            int idx = tid + j * 256;
            int row = idx >> 3, seg = idx & 7;
            uint32_t d = (uint32_t)((row*PADH + seg*8) * 2);
            CP_ASYNC16(base + d,              Ag + (size_t)row*CH + seg*8);
            CP_ASYNC16(base + TILE_BYTES + d, Bg + (size_t)row*CH + seg*8);
        }
        CP_COMMIT();
    };

    issue(0, 0);
    for (int i = 0; i < 4; i++) {
        int s = i & 1;
        if (i + 1 < 4) { issue(i + 1, (i + 1) & 1); CP_WAIT(1); }
        else { CP_WAIT(0); }
        __syncthreads();
        uint32_t abase = smembase + s*STAGE_BYTES;
        uint32_t bbase = abase + TILE_BYTES;
        #pragma unroll
        for (int ks = 0; ks < 4; ks++) {
            uint32_t koff = (uint32_t)(ks * 32);
            uint32_t af[2][4];
            LDSM_X4(af[0][0], af[0][1], af[0][2], af[0][3], abase + a_off[0] + koff);
            LDSM_X4(af[1][0], af[1][1], af[1][2], af[1][3], abase + a_off[1] + koff);
            #pragma unroll
            for (int p = 0; p < 4; p++) {
                uint32_t b0, b1, b2, b3;
                LDSM_X4(b0, b1, b2, b3, bbase + b_off[p] + koff);
                mma_f16(acc[0][2*p],   af[0], b0, b1);
                mma_f16(acc[1][2*p],   af[1], b0, b1);
                mma_f16(acc[0][2*p+1], af[0], b2, b3);
                mma_f16(acc[1][2*p+1], af[1], b2, b3);
            }
        }
        __syncthreads();
    }

    // epilogue: add bilinear(up) then relu, fp16 store
    float w00 = 1.f - fy, w10 = fy;
    #pragma unroll
    for (int mt = 0; mt < 2; mt++) {
        #pragma unroll
        for (int half = 0; half < 2; half++) {
            int x = wm*32 + mt*16 + g + half*8;
            float sx = (x + 0.5f)*0.25f - 0.5f;
            int xx0 = (int)floorf(sx);
            float fx = sx - (float)xx0;
            int x0c = min(max(xx0, 0), WP-1), x1c = min(max(xx0+1, 0), WP-1);
            size_t grow = am0 + x;
            #pragma unroll
            for (int nt = 0; nt < 8; nt++) {
                int col = wn*64 + nt*8 + 2*t;
                float a0 = acc[mt][nt][half*2+0], a1 = acc[mt][nt][half*2+1];
                float u00 = __half2float(S0[x0c*128 + col]);
                float u01 = __half2float(S0[x1c*128 + col]);
                float u10 = __half2float(S1[x0c*128 + col]);
                float u11 = __half2float(S1[x1c*128 + col]);
                float up0 = w00*((1.f-fx)*u00 + fx*u01) + w10*((1.f-fx)*u10 + fx*u11);
                u00 = __half2float(S0[x0c*128 + col+1]);
                u01 = __half2float(S0[x1c*128 + col+1]);
                u10 = __half2float(S1[x0c*128 + col+1]);
                u11 = __half2float(S1[x1c*128 + col+1]);
                float up1 = w00*((1.f-fx)*u00 + fx*u01) + w10*((1.f-fx)*u10 + fx*u11);
                a0 = fmaxf(a0 + up0, 0.f);
                a1 = fmaxf(a1 + up1, 0.f);
                *(__half2*)(g_z1 + grow*C2 + bn0 + col) = __floats2half2_rn(a0, a1);
            }
        }
    }
}

// ================= QK tensor-core GEMM: logits + softmax partials =================
#define PADQ 40
__global__ __launch_bounds__(256) void qkmma_kernel() {
    __shared__ __half qs[2][128*PADQ];
    int tid = threadIdx.x, wid = tid >> 5, lane = tid & 31;
    int g = lane >> 2, t = lane & 3;
    int r = lane & 7, quad = lane >> 3;
    int wm = wid >> 1, wn = wid & 1;
    int n = blockIdx.z >> 3, h = blockIdx.z & 7;
    int l0 = blockIdx.y * 128, s0 = blockIdx.x * 128;
    uint32_t abase = smem_u32(qs[0]);
    uint32_t bbase = smem_u32(qs[1]);

    #pragma unroll
    for (int j = 0; j < 2; j++) {
        int idx = tid + j*256;
        int row = idx >> 2, seg = idx & 3;
        uint32_t d = (uint32_t)((row*PADQ + seg*8) * 2);
        const __half* Aq = g_qh[0] + ((size_t)(n*LL + l0 + row))*CH + h*DH + seg*8;
        const __half* Bq = g_qh[1] + ((size_t)(n*LL + s0 + row))*CH + h*DH + seg*8;
        CP_ASYNC16(abase + d, Aq);
        CP_ASYNC16(bbase + d, Bq);
    }
    CP_COMMIT();
    CP_WAIT(0);
    __syncthreads();

    uint32_t a_off[2], b_off[4];
    #pragma unroll
    for (int mt = 0; mt < 2; mt++)
        a_off[mt] = (uint32_t)(((wm*32 + mt*16 + (quad&1)*8 + r)*PADQ + (quad>>1)*8) * 2);
    #pragma unroll
    for (int p = 0; p < 4; p++)
        b_off[p] = (uint32_t)(((wn*64 + p*16 + (quad>>1)*8 + r)*PADQ + (quad&1)*8) * 2);

    float acc[2][8][4];
    #pragma unroll
    for (int mt = 0; mt < 2; mt++)
        #pragma unroll
        for (int nt = 0; nt < 8; nt++)
            #pragma unroll
            for (int i = 0; i < 4; i++) acc[mt][nt][i] = 0.f;

    #pragma unroll
    for (int ks = 0; ks < 2; ks++) {
        uint32_t koff = (uint32_t)(ks * 32);
        uint32_t af[2][4];
        LDSM_X4(af[0][0], af[0][1], af[0][2], af[0][3], abase + a_off[0] + koff);
        LDSM_X4(af[1][0], af[1][1], af[1][2], af[1][3], abase + a_off[1] + koff);
        #pragma unroll
        for (int p = 0; p < 4; p++) {
            uint32_t b0, b1, b2, b3;
            LDSM_X4(b0, b1, b2, b3, bbase + b_off[p] + koff);
            mma_f16(acc[0][2*p],   af[0], b0, b1);
            mma_f16(acc[1][2*p],   af[1], b0, b1);
            mma_f16(acc[0][2*p+1], af[0], b2, b3);
            mma_f16(acc[1][2*p+1], af[1], b2, b3);
        }
    }

    size_t qkbase = ((size_t)(n*NHEAD + h))*LL;
    int tile = blockIdx.x*2 + wn;
    #pragma unroll
    for (int mt = 0; mt < 2; mt++) {
        int row0 = l0 + wm*32 + mt*16 + g;
        float mx0 = NEGINF, mx1 = NEGINF;
        float vals[8][4];
        #pragma unroll
        for (int nt = 0; nt < 8; nt++) {
            #pragma unroll
            for (int i = 0; i < 4; i++) vals[nt][i] = TSCALE*acc[mt][nt][i];
            int col = s0 + wn*64 + nt*8 + 2*t;
            *(__half2*)(g_qkh + (qkbase + row0)*LL + col)   = __floats2half2_rn(vals[nt][0], vals[nt][1]);
            *(__half2*)(g_qkh + (qkbase + row0+8)*LL + col) = __floats2half2_rn(vals[nt][2], vals[nt][3]);
            mx0 = fmaxf(mx0, fmaxf(vals[nt][0], vals[nt][1]));
            mx1 = fmaxf(mx1, fmaxf(vals[nt][2], vals[nt][3]));
        }
        #pragma unroll
        for (int off = 1; off <= 2; off <<= 1) {
            mx0 = fmaxf(mx0, __shfl_xor_sync(0xffffffffu, mx0, off));
            mx1 = fmaxf(mx1, __shfl_xor_sync(0xffffffffu, mx1, off));
        }
        float sm0 = 0.f, sm1 = 0.f;
        #pragma unroll
        for (int nt = 0; nt < 8; nt++) {
            sm0 += __expf(vals[nt][0]-mx0) + __expf(vals[nt][1]-mx0);
            sm1 += __expf(vals[nt][2]-mx1) + __expf(vals[nt][3]-mx1);
        }
        #pragma unroll
        for (int off = 1; off <= 2; off <<= 1) {
            sm0 += __shfl_xor_sync(0xffffffffu, sm0, off);
            sm1 += __shfl_xor_sync(0xffffffffu, sm1, off);
        }
        if (t == 0) {
            g_pmax[(qkbase + row0)*NTILES + tile]   = mx0;
            g_psum[(qkbase + row0)*NTILES + tile]   = sm0;
            g_pmax[(qkbase + row0+8)*NTILES + tile] = mx1;
            g_psum[(qkbase + row0+8)*NTILES + tile] = sm1;
        }
    }
}

// ================= unified AV tensor-core GEMM (m1 / m2) =================
#define PADA 72
#define PADB 40
__global__ __launch_bounds__(256) void av_kernel(int which) {
    __shared__ __half As[128*PADA];
    __shared__ __half Bs[64*PADB];
    __shared__ float mxs[128], ris[128];
    int t = threadIdx.x, wid = t >> 5, lane = t & 31;
    int r = lane & 7, quad = lane >> 3;
    int n = blockIdx.y >> 3, h = blockIdx.y & 7;
    int m0 = blockIdx.x * 128;
    size_t lbase = ((size_t)(n*NHEAD + h))*LL + m0;
    const __half* Asrc = (which == 0 ? g_qkh : g_s2t);
    const __half* Bsrc = g_vh[which ^ 1] + ((size_t)(n*LL))*CH + h*DH;
    uint32_t asm_b = smem_u32(As), bsm_b = smem_u32(Bs);

    if (which == 0 && t < 128) {
        mxs[t] = g_rmax[lbase + t];
        ris[t] = g_rinv[lbase + t];
    }
    __syncthreads();

    uint32_t a_off = (uint32_t)(((wid*16 + (quad&1)*8 + r)*PADA + (quad>>1)*8) * 2);
    float acc[4][4];
    #pragma unroll
    for (int nt = 0; nt < 4; nt++)
        #pragma unroll
        for (int i = 0; i < 4; i++) acc[nt][i] = 0.f;

    for (int k0 = 0; k0 < LL; k0 += 64) {
        {
            int row = t >> 1, half0 = (t & 1)*32;
            const __half* src = Asrc + (lbase + row)*LL + k0 + half0;
            __half* dst = As + row*PADA + half0;
            if (which == 0) {
                float mx = mxs[row], ri = ris[row];
                #pragma unroll
                for (int j = 0; j < 4; j++) {
                    uint4 raw = *(const uint4*)(src + j*8);
                    __half2* hp = (__half2*)&raw;
                    __half2 o[4];
                    #pragma unroll
                    for (int q = 0; q < 4; q++) {
                        float2 f = __half22float2(hp[q]);
                        o[q] = __floats2half2_rn(__expf(f.x - mx)*ri, __expf(f.y - mx)*ri);
                    }
                    *(uint4*)(dst + j*8) = *(uint4*)o;
                }
            } else {
                #pragma unroll
                for (int j = 0; j < 4; j++)
                    *(uint4*)(dst + j*8) = *(const uint4*)(src + j*8);
            }
        }
        {
            int row = t >> 2, seg = (t & 3)*8;
            *(uint4*)(Bs + row*PADB + seg) = *(const uint4*)(Bsrc + (size_t)(k0 + row)*CH + seg);
        }
        __syncthreads();

        #pragma unroll
        for (int ks = 0; ks < 4; ks++) {
            uint32_t af[4];
            LDSM_X4(af[0], af[1], af[2], af[3], asm_b + a_off + (uint32_t)(ks*32));
            #pragma unroll
            for (int p = 0; p < 2; p++) {
                uint32_t b0, b1, b2, b3;
                uint32_t boff = (uint32_t)(((ks*16 + (quad&1)*8 + r)*PADB + p*16 + (quad>>1)*8) * 2);
                LDSM_X4_T(b0, b1, b2, b3, bsm_b + boff);
                mma_f16(acc[2*p],   af, b0, b1);
                mma_f16(acc[2*p+1], af, b2, b3);
            }
        }
        __syncthreads();
    }

    int rrow = lane >> 2, ccol = (lane & 3)*2;
    #pragma unroll
    for (int nt = 0; nt < 4; nt++) {
        size_t orow = (size_t)(n*LL + m0 + wid*16 + rrow);
        __half* dst = g_m[which] + orow*CH + h*DH + nt*8 + ccol;
        *(__half2*)dst            = __floats2half2_rn(acc[nt][0], acc[nt][1]);
        *(__half2*)(dst + 8*CH)   = __floats2half2_rn(acc[nt][2], acc[nt][3]);
    }
}

// ---------------- weight fp16 prepass (splits W1 halves) ----------------
__global__ void roundh3_kernel(const float* __restrict__ mw, const float* __restrict__ w1,
                               const float* __restrict__ w2) {
    int i = blockIdx.x*256 + threadIdx.x;
    if (i < CH*CH) g_mwh[i] = __float2half_rn(mw[i]);
    if (i < CH*C2) g_w2h[i] = __float2half_rn(w2[i]);
    if (i < C2*C2) {
        int nrow = i >> 9, k = i & 511;
        __half v = __float2half_rn(w1[i]);
        if (k < CH) g_w1a[nrow*CH + k] = v;
        else        g_w1b[nrow*CH + k - CH] = v;
    }
}

// ---------------- 1. fused maxpool + xcopy + LN partials ----------------
#define PUX_PITCH 516
#define PUX_SMEM ((32*PUX_PITCH + 32*33)*4)
__global__ __launch_bounds__(256) void pux_kernel(const float* __restrict__ x1,
                                                  const float* __restrict__ x2) {
    extern __shared__ float sh[];
    float* po = sh + 32*PUX_PITCH;
    int ct = blockIdx.x;
    int y4 = blockIdx.y;
    int n  = blockIdx.z & 3;
    int o  = blockIdx.z >> 2;
    const float* xs = o ? x2 : x1;
    int tid = threadIdx.x;
    int c0 = ct*32;
    #pragma unroll
    for (int i = 0; i < 16; i++) {
        int f = tid + i*256;
        int cc = f >> 7, rem = f & 127;
        int yy = rem >> 5, c4 = rem & 31;
        float4 v = *(const float4*)(xs +
            (((size_t)(n*CH + c0+cc))*HH + y4*4+yy)*WW + c4*4);
        *(float4*)&sh[cc*PUX_PITCH + yy*128 + c4*4] = v;
    }
    __syncthreads();
    {
        int c = tid >> 3, xo = (tid & 7)*4;
        float4 out;
        float* pov = &out.x;
        #pragma unroll
        for (int k = 0; k < 4; k++) {
            int px = xo + k;
            float m = NEGINF;
            #pragma unroll
            for (int yy = 0; yy < 4; yy++) {
                float4 v = *(const float4*)&sh[c*PUX_PITCH + yy*128 + px*4];
                m = fmaxf(m, fmaxf(fmaxf(v.x, v.y), fmaxf(v.z, v.w)));
            }
            pov[k] = m;
            po[c*33 + px] = m;
        }
        *(float4*)(g_p[o] + ((size_t)(n*CH + c0 + c))*LL + y4*32 + xo) = out;
    }
    __syncthreads();
    if (tid < 32) {
        float s = 0.f, sq = 0.f;
        #pragma unroll
        for (int c = 0; c < 32; c++) { float v = po[c*33 + tid]; s += v; sq += v*v; }
        int sp = y4*32 + tid;
        size_t pidx = (((size_t)(o*BATCH + n))*8 + ct)*LL + sp;
        g_lnps[pidx] = s;
        g_lnpq[pidx] = sq;
    }
    size_t rbase = (size_t)o*NPIX + (size_t)n*HH*WW + (size_t)(y4*4)*WW;
    #pragma unroll
    for (int j = 0; j < 2; j++) {
        int p = tid + j*256;
        __half2 hb[16];
        #pragma unroll
        for (int cc = 0; cc < 32; cc += 2)
            hb[cc>>1] = __floats2half2_rn(sh[cc*PUX_PITCH + p], sh[(cc+1)*PUX_PITCH + p]);
        uint4* dst = (uint4*)(g_u + (rbase + p)*CH + c0);
        const uint4* src = (const uint4*)hb;
        dst[0] = src[0]; dst[1] = src[1]; dst[2] = src[2]; dst[3] = src[3];
    }
}

// ---------------- 2. finalize LN stats ----------------
__global__ void lnfin_kernel() {
    int gi = blockIdx.x*256 + threadIdx.x;
    int on = gi / LL, sp = gi % LL;
    float s = 0.f, sq = 0.f;
    #pragma unroll
    for (int ctt = 0; ctt < 8; ctt++) {
        size_t pidx = (((size_t)on)*8 + ctt)*LL + sp;
        s += g_lnps[pidx]; sq += g_lnpq[pidx];
    }
    float mu = s * (1.0f/CH);
    g_mu1[gi] = mu;
    g_rs1[gi] = rsqrtf(sq * (1.0f/CH) - mu*mu + EPSF);
}

// ---------------- 3. dwconv3x3 + BN (LN inline), q/k/v fp16 out ----------------
__global__ __launch_bounds__(256) void dwbn2_kernel(
        const float* __restrict__ qw, const float* __restrict__ qg, const float* __restrict__ qb,
        const float* __restrict__ qm, const float* __restrict__ qvv,
        const float* __restrict__ vw, const float* __restrict__ vg, const float* __restrict__ vb,
        const float* __restrict__ vm, const float* __restrict__ vvv,
        const float* __restrict__ l1g, const float* __restrict__ l1b) {
    int c0 = blockIdx.x * 8;
    int n  = blockIdx.y;
    int o  = blockIdx.z;
    __shared__ float sp[8*1028];
    int t = threadIdx.x;
    const float* mub = g_mu1 + (size_t)(o*BATCH + n)*LL;
    const float* rsb = g_rs1 + (size_t)(o*BATCH + n)*LL;
    #pragma unroll
    for (int cc = 0; cc < 8; cc++) {
        float gc = l1g[c0+cc], bc = l1b[c0+cc];
        #pragma unroll
        for (int it = 0; it < 4; it++) {
            int spi = t + it*256;
            float raw = g_p[o][((size_t)(n*CH + c0+cc))*LL + spi];
            sp[cc*1028 + spi] = gc*(raw - mub[spi])*rsb[spi] + bc;
        }
    }
    __syncthreads();

    int cc = t & 7, jq = t >> 3;
    int c = c0 + cc;
    float wq[9], wv[9];
    #pragma unroll
    for (int k = 0; k < 9; k++) { wq[k] = qw[c*9+k]; wv[k] = vw[c*9+k]; }
    float scq = qg[c]*rsqrtf(qvv[c]+EPSF), bq = qb[c] - scq*qm[c];
    float scv = vg[c]*rsqrtf(vvv[c]+EPSF), bv = vb[c] - scv*vm[c];
    const float* s = sp + cc*1028;
    __half* oq = g_qh[o] + (size_t)(n*LL)*CH + c;
    __half* ov = g_vh[o] + (size_t)(n*LL)*CH + c;

    for (int i = 0; i < 32; i++) {
        float aq = 0.f, av = 0.f;
        #pragma unroll
        for (int di = 0; di < 3; di++) {
            int ii = i + di - 1;
            if (ii < 0 || ii >= HP) continue;
            #pragma unroll
            for (int dj = 0; dj < 3; dj++) {
                int jj = jq + dj - 1;
                if (jj < 0 || jj >= WP) continue;
                float x = s[ii*32 + jj];
                aq += wq[di*3+dj]*x;
                av += wv[di*3+dj]*x;
            }
        }
        int l = i*32 + jq;
        oq[(size_t)l*CH] = __float2half_rn(scq*aq + bq);
        ov[(size_t)l*CH] = __float2half_rn(scv*av + bv);
    }
}

// ---------------- 5. combine tile partials ----------------
__global__ void rowstat2_kernel() {
    int r = blockIdx.x*256 + threadIdx.x;
    float pm[NTILES];
    float m = NEGINF;
    #pragma unroll
    for (int i = 0; i < NTILES; i++) {
        pm[i] = g_pmax[(size_t)r*NTILES + i];
        m = fmaxf(m, pm[i]);
    }
    float sum = 0.f;
    #pragma unroll
    for (int i = 0; i < NTILES; i++)
        sum += g_psum[(size_t)r*NTILES + i] * __expf(pm[i] - m);
    g_rmax[r] = m;
    g_rinv[r] = 1.f/sum;
}

// ---------------- 7. S2 softmax over heads + transpose ----------------
__global__ __launch_bounds__(256) void s2t_kernel() {
    __shared__ __half sm[8][32][36];
    int t = threadIdx.x;
    int s0 = blockIdx.x*32, l0 = blockIdx.y*32, n = blockIdx.z;
    int row = t >> 3, seg = t & 7;
    #pragma unroll
    for (int h = 0; h < NHEAD; h++) {
        uint2 v = *(const uint2*)(g_qkh +
            (((size_t)(n*NHEAD + h))*LL + l0 + row)*LL + s0 + seg*4);
        *(uint2*)&sm[h][row][seg*4] = v;
    }
    __syncthreads();
    #pragma unroll
    for (int j = 0; j < 4; j++) {
        int e = t*4 + j;
        int l = e >> 5, s = e & 31;
        float v[NHEAD];
        float mx = NEGINF;
        #pragma unroll
        for (int h = 0; h < NHEAD; h++) {
            v[h] = __half2float(sm[h][l][s]);
            mx = fmaxf(mx, v[h]);
        }
        float smm = 0.f;
        #pragma unroll
        for (int h = 0; h < NHEAD; h++) { v[h] = __expf(v[h]-mx); smm += v[h]; }
        float ri = 1.f/smm;
        #pragma unroll
        for (int h = 0; h < NHEAD; h++)
            sm[h][l][s] = __float2half_rn(v[h]*ri);
    }
    __syncthreads();
    #pragma unroll
    for (int h = 0; h < NHEAD; h++) {
        __half tmp[4];
        #pragma unroll
        for (int jj = 0; jj < 4; jj++) tmp[jj] = sm[h][seg*4+jj][row];
        *(uint2*)(g_s2t + (((size_t)(n*NHEAD + h))*LL + s0 + row)*LL + l0 + seg*4) =
            *(uint2*)tmp;
    }
}

// ---------------- 10. fused LN stats + apply + residual + write-out ----------------
__global__ __launch_bounds__(256) void out_fused_kernel(
        const float* __restrict__ x1, const float* __restrict__ x2,
        const float* __restrict__ lg, const float* __restrict__ lb,
        float* __restrict__ out) {
    int xt = blockIdx.x;
    int y  = blockIdx.y;
    int n  = blockIdx.z % BATCH;
    int o  = blockIdx.z / BATCH;
    __shared__ float zsh[32][257];
    __shared__ float smu[32], srs[32];
    int tid = threadIdx.x;
    size_t rbase = (size_t)o*NPIX + (size_t)n*HH*WW + (size_t)y*WW + xt*32;
    #pragma unroll
    for (int j = 0; j < 4; j++) {
        int px = j*8 + (tid >> 5);
        int c = (tid & 31) * 8;
        uint4 raw = *(const uint4*)(g_z2h + (rbase + px)*CH + c);
        const __half2* hp = (const __half2*)&raw;
        #pragma unroll
        for (int q = 0; q < 4; q++) {
            float2 f = __half22float2(hp[q]);
            zsh[px][c + 2*q]     = f.x;
            zsh[px][c + 2*q + 1] = f.y;
        }
    }
    __syncthreads();
    int w = tid >> 5, lane = tid & 31;
    #pragma unroll
    for (int i = 0; i < 4; i++) {
        int px = w*4 + i;
        float s = 0.f, sq = 0.f;
        #pragma unroll
        for (int k = 0; k < 8; k++) { float v = zsh[px][lane + k*32]; s += v; sq += v*v; }
        #pragma unroll
        for (int off = 16; off; off >>= 1) {
            s  += __shfl_xor_sync(0xffffffffu, s,  off);
            sq += __shfl_xor_sync(0xffffffffu, sq, off);
        }
        if (!lane) {
            float mu = s * (1.0f/CH);
            smu[px] = mu;
            srs[px] = rsqrtf(sq * (1.0f/CH) - mu*mu + EPSF);
        }
    }
    __syncthreads();
    const float* xs = o ? x2 : x1;
    int cth = tid >> 5, tx = tid & 31;
    float mu = smu[tx], rs = srs[tx];
    size_t xbase = ((size_t)(n*CH))*HH*WW + (size_t)y*WW + xt*32 + tx;
    float* outb = out + (size_t)o*NPIX*CH;
    #pragma unroll 8
    for (int cc = 0; cc < 32; cc++) {
        int c = cc*8 + cth;
        float val = lg[c]*(zsh[tx][c] - mu)*rs + lb[c];
        size_t gi = xbase + (size_t)c*HH*WW;
        outb[gi] = xs[gi] + val;
    }
}

// ---------------- launch ----------------
extern "C" void kernel_launch(void* const* d_in, const int* in_sizes, int n_in,
                              void* d_out, int out_size) {
    const float* x1     = (const float*)d_in[0];
    const float* x2     = (const float*)d_in[1];
    const float* qk_w   = (const float*)d_in[2];
    const float* qk_g   = (const float*)d_in[3];
    const float* qk_b   = (const float*)d_in[4];
    const float* qk_m   = (const float*)d_in[5];
    const float* qk_v   = (const float*)d_in[6];
    const float* v_w    = (const float*)d_in[7];
    const float* v_g    = (const float*)d_in[8];
    const float* v_b    = (const float*)d_in[9];
    const float* v_m    = (const float*)d_in[10];
    const float* v_v    = (const float*)d_in[11];
    const float* ln1_g  = (const float*)d_in[12];
    const float* ln1_b  = (const float*)d_in[13];
    const float* ln2_g  = (const float*)d_in[14];
    const float* ln2_b  = (const float*)d_in[15];
    const float* merge_w= (const float*)d_in[16];
    const float* mlp_w1 = (const float*)d_in[17];
    const float* mlp_w2 = (const float*)d_in[18];
    float* out = (float*)d_out;

    __half *pm, *pmmh, *pmmw, *pu, *pz1, *pz2h, *pmw, *pw1b, *pw2;
    cudaGetSymbolAddress((void**)&pm,   g_m);
    cudaGetSymbolAddress((void**)&pmmh, g_mmh);
    cudaGetSymbolAddress((void**)&pmmw, g_mmw);
    cudaGetSymbolAddress((void**)&pu,   g_u);
    cudaGetSymbolAddress((void**)&pz1,  g_z1);
    cudaGetSymbolAddress((void**)&pz2h, g_z2h);
    cudaGetSymbolAddress((void**)&pmw,  g_mwh);
    cudaGetSymbolAddress((void**)&pw1b, g_w1b);
    cudaGetSymbolAddress((void**)&pw2,  g_w2h);

    cudaFuncSetAttribute(hgemm_kernel,    cudaFuncAttributeMaxDynamicSharedMemorySize, GEMM_SMEM);
    cudaFuncSetAttribute(hgemm_up_kernel, cudaFuncAttributeMaxDynamicSharedMemorySize, GEMMUP_SMEM);
    cudaFuncSetAttribute(pux_kernel,      cudaFuncAttributeMaxDynamicSharedMemorySize, PUX_SMEM);

    roundh3_kernel<<<(C2*C2+255)/256, 256>>>(merge_w, mlp_w1, mlp_w2);

    pux_kernel<<<dim3(CH/32, HP, 2*BATCH), 256, PUX_SMEM>>>(x1, x2);
    lnfin_kernel<<<(2*BATCH*LL)/256, 256>>>();

    dwbn2_kernel<<<dim3(CH/8, BATCH, 2), 256>>>(qk_w, qk_g, qk_b, qk_m, qk_v,
                                                v_w, v_g, v_b, v_m, v_v, ln1_g, ln1_b);

    // attention (all tensor-core)
    qkmma_kernel<<<dim3(LL/128, LL/128, BATCH*NHEAD), 256>>>();
    rowstat2_kernel<<<BATCH*NHEAD*LL/256, 256>>>();
    av_kernel<<<dim3(LL/128, BATCH*NHEAD), 256>>>(0);   // m1
    s2t_kernel<<<dim3(LL/32, LL/32, BATCH), 256>>>();
    av_kernel<<<dim3(LL/128, BATCH*NHEAD), 256>>>(1);   // m2

    // merge linear -> fp16 mm
    hgemm_kernel<<<dim3(CH/128, (2*BATCH*LL)/128), 256, GEMM_SMEM>>>(
        pm, pmw, pmmh, 2*BATCH*LL, CH, CH, 0, 1);
    // mmw = mm @ W1b^T  (pooled-resolution right-half contribution)
    hgemm_kernel<<<dim3(C2/128, (2*BATCH*LL)/128), 256, GEMM_SMEM>>>(
        pmmh, pw1b, pmmw, 2*BATCH*LL, C2, CH, 0, 1);

    // MLP1: x-half GEMM + upsample-add + relu (K=256, 2-stage, 2 CTAs/SM)
    hgemm_up_kernel<<<dim3(C2/128, NROWS/128), 256, GEMMUP_SMEM>>>();
    // MLP2 (z2 fp16)
    hgemm_kernel<<<dim3(CH/128, NROWS/128), 256, GEMM_SMEM>>>(
        pz1, pw2, pz2h, NROWS, CH, C2, 0, 1);

    out_fused_kernel<<<dim3(WW/32, HH, 2*BATCH), 256>>>(x1, x2, ln2_g, ln2_b, out);
}

// round 16
// speedup vs baseline: 1.1258x; 1.0236x over previous
#include <cuda_runtime.h>
#include <cuda_fp16.h>
#include <cstdint>

#define BATCH 4
#define CH 256
#define HH 128
#define WW 128
#define HP 32
#define WP 32
#define LL 1024
#define NHEAD 8
#define DH 32
#define C2 512
#define NPIX (BATCH*HH*WW)
#define NROWS (2*NPIX)
#define EPSF 1e-5f
#define TSCALE 0.17677669529663687f
#define NEGINF (-3.402823466e38f)
#define NTILES 16

// ---------------- scratch ----------------
__device__ float  g_p[2][BATCH*CH*LL];
__device__ float  g_lnps[2*BATCH*8*LL];
__device__ float  g_lnpq[2*BATCH*8*LL];
__device__ float  g_mu1[2*BATCH*LL];
__device__ float  g_rs1[2*BATCH*LL];
__device__ __half g_qh[2][(size_t)BATCH*LL*CH];
__device__ __half g_vh[2][(size_t)BATCH*LL*CH];
__device__ __half g_qkh[(size_t)BATCH*NHEAD*LL*LL];
__device__ __half g_s2t[(size_t)BATCH*NHEAD*LL*LL];
__device__ float  g_pmax[(size_t)BATCH*NHEAD*LL*NTILES];
__device__ float  g_psum[(size_t)BATCH*NHEAD*LL*NTILES];
__device__ float  g_rmax[BATCH*NHEAD*LL];
__device__ float  g_rinv[BATCH*NHEAD*LL];
__device__ __half g_m[2][(size_t)BATCH*LL*CH];
__device__ __half g_mmh[(size_t)2*BATCH*LL*CH];
__device__ __half g_mmw[(size_t)2*BATCH*LL*C2];
__device__ __half g_u[(size_t)NROWS*CH];
__device__ __half g_z1[(size_t)NROWS*C2];
__device__ __half g_z2h[(size_t)NROWS*CH];
__device__ __half g_mwh[CH*CH];
__device__ __half g_w1a[C2*CH];
__device__ __half g_w1b[C2*CH];
__device__ __half g_w2h[CH*C2];

// ================= helpers =================
__device__ __forceinline__ uint32_t smem_u32(const void* p) {
    uint32_t a;
    asm("{ .reg .u64 t; cvta.to.shared.u64 t, %1; cvt.u32.u64 %0, t; }" : "=r"(a) : "l"(p));
    return a;
}
#define CP_ASYNC16(dst, src) \
    asm volatile("cp.async.cg.shared.global [%0], [%1], 16;" :: "r"(dst), "l"(src) : "memory")
#define CP_COMMIT() asm volatile("cp.async.commit_group;" ::: "memory")
#define CP_WAIT(n)  asm volatile("cp.async.wait_group %0;" :: "n"(n) : "memory")
#define LDSM_X4(r0, r1, r2, r3, addr) \
    asm volatile("ldmatrix.sync.aligned.m8n8.x4.shared.b16 {%0,%1,%2,%3}, [%4];" \
        : "=r"(r0), "=r"(r1), "=r"(r2), "=r"(r3) : "r"(addr))
#define LDSM_X4_T(r0, r1, r2, r3, addr) \
    asm volatile("ldmatrix.sync.aligned.m8n8.x4.trans.shared.b16 {%0,%1,%2,%3}, [%4];" \
        : "=r"(r0), "=r"(r1), "=r"(r2), "=r"(r3) : "r"(addr))

__device__ __forceinline__ void mma_f16(float* d, const uint32_t* a, uint32_t b0, uint32_t b1) {
    asm volatile(
        "mma.sync.aligned.m16n8k16.row.col.f32.f16.f16.f32 "
        "{%0,%1,%2,%3}, {%4,%5,%6,%7}, {%8,%9}, {%0,%1,%2,%3};"
        : "+f"(d[0]), "+f"(d[1]), "+f"(d[2]), "+f"(d[3])
        : "r"(a[0]), "r"(a[1]), "r"(a[2]), "r"(a[3]), "r"(b0), "r"(b1));
}

// ================= fp16 mma GEMM (validated: CTA 128x128, 3-stage) =================
#define BKH 64
#define PADH 72
#define TILEH (128*PADH)
#define TILE_BYTES (TILEH*2)
#define STAGE_BYTES (2*TILE_BYTES)
#define GEMM_SMEM (3*STAGE_BYTES)

__global__ __launch_bounds__(256) void hgemm_kernel(
        const __half* __restrict__ A, const __half* __restrict__ Bw, void* __restrict__ C,
        int M, int N, int K, int relu, int outHalf) {
    extern __shared__ __half smh[];
    int tid = threadIdx.x, wid = tid >> 5, lane = tid & 31;
    int g = lane >> 2, t = lane & 3;
    int r = lane & 7, quad = lane >> 3;
    int wm = wid >> 1, wn = wid & 1;
    size_t am0 = (size_t)blockIdx.y * 128;
    size_t bn0 = (size_t)blockIdx.x * 128;
    uint32_t smembase = smem_u32(smh);

    uint32_t a_off[2], b_off[4];
    #pragma unroll
    for (int mt = 0; mt < 2; mt++)
        a_off[mt] = (uint32_t)(((wm*32 + mt*16 + (quad&1)*8 + r)*PADH + (quad>>1)*8) * 2);
    #pragma unroll
    for (int p = 0; p < 4; p++)
        b_off[p] = (uint32_t)(((wn*64 + p*16 + (quad>>1)*8 + r)*PADH + (quad&1)*8) * 2);

    int nchunk = K >> 6;
    float acc[2][8][4];
    #pragma unroll
    for (int mt = 0; mt < 2; mt++)
        #pragma unroll
        for (int nt = 0; nt < 8; nt++)
            #pragma unroll
            for (int i = 0; i < 4; i++) acc[mt][nt][i] = 0.f;

    auto issue = [&](int ch, int st) {
        const __half* Ag = A + am0 * K + ch*BKH;
        const __half* Bg = Bw + bn0 * K + ch*BKH;
        uint32_t base = smembase + st*STAGE_BYTES;
        #pragma unroll
        for (int j = 0; j < 4; j++) {
            int idx = tid + j * 256;
            int row = idx >> 3, seg = idx & 7;
            uint32_t d = (uint32_t)((row*PADH + seg*8) * 2);
            CP_ASYNC16(base + d,              Ag + (size_t)row*K + seg*8);
            CP_ASYNC16(base + TILE_BYTES + d, Bg + (size_t)row*K + seg*8);
        }
        CP_COMMIT();
    };

    issue(0, 0);
    if (nchunk > 1) issue(1, 1);

    for (int i = 0; i < nchunk; i++) {
        int s = i % 3;
        if (i + 2 < nchunk) { issue(i + 2, (i + 2) % 3); CP_WAIT(2); }
        else if (i + 1 < nchunk) { CP_WAIT(1); }
        else { CP_WAIT(0); }
        __syncthreads();

        uint32_t abase = smembase + s*STAGE_BYTES;
        uint32_t bbase = abase + TILE_BYTES;
        #pragma unroll
        for (int ks = 0; ks < 4; ks++) {
            uint32_t koff = (uint32_t)(ks * 32);
            uint32_t af[2][4];
            LDSM_X4(af[0][0], af[0][1], af[0][2], af[0][3], abase + a_off[0] + koff);
            LDSM_X4(af[1][0], af[1][1], af[1][2], af[1][3], abase + a_off[1] + koff);
            #pragma unroll
            for (int p = 0; p < 4; p++) {
                uint32_t b0, b1, b2, b3;
                LDSM_X4(b0, b1, b2, b3, bbase + b_off[p] + koff);
                mma_f16(acc[0][2*p],   af[0], b0, b1);
                mma_f16(acc[1][2*p],   af[1], b0, b1);
                mma_f16(acc[0][2*p+1], af[0], b2, b3);
                mma_f16(acc[1][2*p+1], af[1], b2, b3);
            }
        }
        __syncthreads();
    }

    #pragma unroll
    for (int mt = 0; mt < 2; mt++) {
        size_t row = am0 + wm*32 + mt*16 + g;
        #pragma unroll
        for (int nt = 0; nt < 8; nt++) {
            size_t col = bn0 + wn*64 + nt*8 + 2*t;
            float v0 = acc[mt][nt][0], v1 = acc[mt][nt][1];
            float v2 = acc[mt][nt][2], v3 = acc[mt][nt][3];
            if (relu) {
                v0 = fmaxf(v0,0.f); v1 = fmaxf(v1,0.f);
                v2 = fmaxf(v2,0.f); v3 = fmaxf(v3,0.f);
            }
            if (outHalf) {
                __half* Ch = (__half*)C;
                *(__half2*)(Ch + row*N + col)     = __floats2half2_rn(v0, v1);
                *(__half2*)(Ch + (row+8)*N + col) = __floats2half2_rn(v2, v3);
            } else {
                float* Cf = (float*)C;
                *(float2*)(Cf + row*N + col)     = make_float2(v0, v1);
                *(float2*)(Cf + (row+8)*N + col) = make_float2(v2, v3);
            }
        }
    }
}

// ===== MLP1 GEMM with upsample-add epilogue (2-stage, 2 CTAs/SM) =====
#define UP_SMEM (2*32*128*2)
#define GEMMUP_SMEM (2*STAGE_BYTES + UP_SMEM)
__global__ __launch_bounds__(256) void hgemm_up_kernel() {
    extern __shared__ __half smh[];
    __half* S0 = smh + STAGE_BYTES;
    __half* S1 = S0 + 32*128;
    int tid = threadIdx.x, wid = tid >> 5, lane = tid & 31;
    int g = lane >> 2, t = lane & 3;
    int r = lane & 7, quad = lane >> 3;
    int wm = wid >> 1, wn = wid & 1;
    size_t am0 = (size_t)blockIdx.y * 128;
    size_t bn0 = (size_t)blockIdx.x * 128;
    uint32_t smembase = smem_u32(smh);

    int o = blockIdx.y >> 9;
    int n = (blockIdx.y >> 7) & 3;
    int y = blockIdx.y & 127;
    float sy = (y + 0.5f)*0.25f - 0.5f;
    int yy0 = (int)floorf(sy);
    float fy = sy - (float)yy0;
    int y0c = min(max(yy0, 0), HP-1), y1c = min(max(yy0+1, 0), HP-1);

    {
        const __half* mb = g_mmw + ((size_t)(o*BATCH + n))*LL*C2 + bn0;
        #pragma unroll
        for (int j = 0; j < 4; j++) {
            int idx = tid*4 + j;
            int which = idx >> 9, rem = idx & 511;
            int xp = rem >> 4, cseg = (rem & 15)*8;
            int yc = which ? y1c : y0c;
            __half* dst = (which ? S1 : S0) + xp*128 + cseg;
            *(uint4*)dst = *(const uint4*)(mb + (size_t)(yc*WP + xp)*C2 + cseg);
        }
    }

    uint32_t a_off[2], b_off[4];
    #pragma unroll
    for (int mt = 0; mt < 2; mt++)
        a_off[mt] = (uint32_t)(((wm*32 + mt*16 + (quad&1)*8 + r)*PADH + (quad>>1)*8) * 2);
    #pragma unroll
    for (int p = 0; p < 4; p++)
        b_off[p] = (uint32_t)(((wn*64 + p*16 + (quad>>1)*8 + r)*PADH + (quad&1)*8) * 2);

    float acc[2][8][4];
    #pragma unroll
    for (int mt = 0; mt < 2; mt++)
        #pragma unroll
        for (int nt = 0; nt < 8; nt++)
            #pragma unroll
            for (int i = 0; i < 4; i++) acc[mt][nt][i] = 0.f;

    auto issue = [&](int ch, int st) {
        const __half* Ag = g_u + am0 * CH + ch*BKH;
        const __half* Bg = g_w1a + bn0 * CH + ch*BKH;
        uint32_t base = smembase + st*STAGE_BYTES;
        #pragma unroll
        for (int j = 0; j < 4; j++) {
            int idx = tid + j * 256;
            int row = idx >> 3, seg = idx & 7;
            uint32_t d = (uint32_t)((row*PADH + seg*8) * 2);
            CP_ASYNC16(base + d,              Ag + (size_t)row*CH + seg*8);
            CP_ASYNC16(base + TILE_BYTES + d, Bg + (size_t)row*CH + seg*8);
        }
        CP_COMMIT();
    };

    issue(0, 0);
    for (int i = 0; i < 4; i++) {
        int s = i & 1;
        if (i + 1 < 4) { issue(i + 1, (i + 1) & 1); CP_WAIT(1); }
        else { CP_WAIT(0); }
        __syncthreads();
        uint32_t abase = smembase + s*STAGE_BYTES;
        uint32_t bbase = abase + TILE_BYTES;
        #pragma unroll
        for (int ks = 0; ks < 4; ks++) {
            uint32_t koff = (uint32_t)(ks * 32);
            uint32_t af[2][4];
            LDSM_X4(af[0][0], af[0][1], af[0][2], af[0][3], abase + a_off[0] + koff);
            LDSM_X4(af[1][0], af[1][1], af[1][2], af[1][3], abase + a_off[1] + koff);
            #pragma unroll
            for (int p = 0; p < 4; p++) {
                uint32_t b0, b1, b2, b3;
                LDSM_X4(b0, b1, b2, b3, bbase + b_off[p] + koff);
                mma_f16(acc[0][2*p],   af[0], b0, b1);
                mma_f16(acc[1][2*p],   af[1], b0, b1);
                mma_f16(acc[0][2*p+1], af[0], b2, b3);
                mma_f16(acc[1][2*p+1], af[1], b2, b3);
            }
        }
        __syncthreads();
    }

    float w00 = 1.f - fy, w10 = fy;
    #pragma unroll
    for (int mt = 0; mt < 2; mt++) {
        #pragma unroll
        for (int half = 0; half < 2; half++) {
            int x = wm*32 + mt*16 + g + half*8;
            float sx = (x + 0.5f)*0.25f - 0.5f;
            int xx0 = (int)floorf(sx);
            float fx = sx - (float)xx0;
            int x0c = min(max(xx0, 0), WP-1), x1c = min(max(xx0+1, 0), WP-1);
            size_t grow = am0 + x;
            #pragma unroll
            for (int nt = 0; nt < 8; nt++) {
                int col = wn*64 + nt*8 + 2*t;
                float a0 = acc[mt][nt][half*2+0], a1 = acc[mt][nt][half*2+1];
                float u00 = __half2float(S0[x0c*128 + col]);
                float u01 = __half2float(S0[x1c*128 + col]);
                float u10 = __half2float(S1[x0c*128 + col]);
                float u11 = __half2float(S1[x1c*128 + col]);
                float up0 = w00*((1.f-fx)*u00 + fx*u01) + w10*((1.f-fx)*u10 + fx*u11);
                u00 = __half2float(S0[x0c*128 + col+1]);
                u01 = __half2float(S0[x1c*128 + col+1]);
                u10 = __half2float(S1[x0c*128 + col+1]);
                u11 = __half2float(S1[x1c*128 + col+1]);
                float up1 = w00*((1.f-fx)*u00 + fx*u01) + w10*((1.f-fx)*u10 + fx*u11);
                a0 = fmaxf(a0 + up0, 0.f);
                a1 = fmaxf(a1 + up1, 0.f);
                *(__half2*)(g_z1 + grow*C2 + bn0 + col) = __floats2half2_rn(a0, a1);
            }
        }
    }
}

// ================= QK tensor-core GEMM: logits + softmax partials =================
#define PADQ 40
__global__ __launch_bounds__(256) void qkmma_kernel() {
    __shared__ __half qs[2][128*PADQ];
    int tid = threadIdx.x, wid = tid >> 5, lane = tid & 31;
    int g = lane >> 2, t = lane & 3;
    int r = lane & 7, quad = lane >> 3;
    int wm = wid >> 1, wn = wid & 1;
    int n = blockIdx.z >> 3, h = blockIdx.z & 7;
    int l0 = blockIdx.y * 128, s0 = blockIdx.x * 128;
    uint32_t abase = smem_u32(qs[0]);
    uint32_t bbase = smem_u32(qs[1]);

    #pragma unroll
    for (int j = 0; j < 2; j++) {
        int idx = tid + j*256;
        int row = idx >> 2, seg = idx & 3;
        uint32_t d = (uint32_t)((row*PADQ + seg*8) * 2);
        const __half* Aq = g_qh[0] + ((size_t)(n*LL + l0 + row))*CH + h*DH + seg*8;
        const __half* Bq = g_qh[1] + ((size_t)(n*LL + s0 + row))*CH + h*DH + seg*8;
        CP_ASYNC16(abase + d, Aq);
        CP_ASYNC16(bbase + d, Bq);
    }
    CP_COMMIT();
    CP_WAIT(0);
    __syncthreads();

    uint32_t a_off[2], b_off[4];
    #pragma unroll
    for (int mt = 0; mt < 2; mt++)
        a_off[mt] = (uint32_t)(((wm*32 + mt*16 + (quad&1)*8 + r)*PADQ + (quad>>1)*8) * 2);
    #pragma unroll
    for (int p = 0; p < 4; p++)
        b_off[p] = (uint32_t)(((wn*64 + p*16 + (quad>>1)*8 + r)*PADQ + (quad&1)*8) * 2);

    float acc[2][8][4];
    #pragma unroll
    for (int mt = 0; mt < 2; mt++)
        #pragma unroll
        for (int nt = 0; nt < 8; nt++)
            #pragma unroll
            for (int i = 0; i < 4; i++) acc[mt][nt][i] = 0.f;

    #pragma unroll
    for (int ks = 0; ks < 2; ks++) {
        uint32_t koff = (uint32_t)(ks * 32);
        uint32_t af[2][4];
        LDSM_X4(af[0][0], af[0][1], af[0][2], af[0][3], abase + a_off[0] + koff);
        LDSM_X4(af[1][0], af[1][1], af[1][2], af[1][3], abase + a_off[1] + koff);
        #pragma unroll
        for (int p = 0; p < 4; p++) {
            uint32_t b0, b1, b2, b3;
            LDSM_X4(b0, b1, b2, b3, bbase + b_off[p] + koff);
            mma_f16(acc[0][2*p],   af[0], b0, b1);
            mma_f16(acc[1][2*p],   af[1], b0, b1);
            mma_f16(acc[0][2*p+1], af[0], b2, b3);
            mma_f16(acc[1][2*p+1], af[1], b2, b3);
        }
    }

    size_t qkbase = ((size_t)(n*NHEAD + h))*LL;
    int tile = blockIdx.x*2 + wn;
    #pragma unroll
    for (int mt = 0; mt < 2; mt++) {
        int row0 = l0 + wm*32 + mt*16 + g;
        float mx0 = NEGINF, mx1 = NEGINF;
        float vals[8][4];
        #pragma unroll
        for (int nt = 0; nt < 8; nt++) {
            #pragma unroll
            for (int i = 0; i < 4; i++) vals[nt][i] = TSCALE*acc[mt][nt][i];
            int col = s0 + wn*64 + nt*8 + 2*t;
            *(__half2*)(g_qkh + (qkbase + row0)*LL + col)   = __floats2half2_rn(vals[nt][0], vals[nt][1]);
            *(__half2*)(g_qkh + (qkbase + row0+8)*LL + col) = __floats2half2_rn(vals[nt][2], vals[nt][3]);
            mx0 = fmaxf(mx0, fmaxf(vals[nt][0], vals[nt][1]));
            mx1 = fmaxf(mx1, fmaxf(vals[nt][2], vals[nt][3]));
        }
        #pragma unroll
        for (int off = 1; off <= 2; off <<= 1) {
            mx0 = fmaxf(mx0, __shfl_xor_sync(0xffffffffu, mx0, off));
            mx1 = fmaxf(mx1, __shfl_xor_sync(0xffffffffu, mx1, off));
        }
        float sm0 = 0.f, sm1 = 0.f;
        #pragma unroll
        for (int nt = 0; nt < 8; nt++) {
            sm0 += __expf(vals[nt][0]-mx0) + __expf(vals[nt][1]-mx0);
            sm1 += __expf(vals[nt][2]-mx1) + __expf(vals[nt][3]-mx1);
        }
        #pragma unroll
        for (int off = 1; off <= 2; off <<= 1) {
            sm0 += __shfl_xor_sync(0xffffffffu, sm0, off);
            sm1 += __shfl_xor_sync(0xffffffffu, sm1, off);
        }
        if (t == 0) {
            g_pmax[(qkbase + row0)*NTILES + tile]   = mx0;
            g_psum[(qkbase + row0)*NTILES + tile]   = sm0;
            g_pmax[(qkbase + row0+8)*NTILES + tile] = mx1;
            g_psum[(qkbase + row0+8)*NTILES + tile] = sm1;
        }
    }
}

// ================= unified AV tensor-core GEMM (m1 / m2) =================
#define PADA 72
#define PADB 40
__global__ __launch_bounds__(256) void av_kernel(int which) {
    __shared__ __half As[128*PADA];
    __shared__ __half Bs[64*PADB];
    __shared__ float mxs[128], ris[128];
    int t = threadIdx.x, wid = t >> 5, lane = t & 31;
    int r = lane & 7, quad = lane >> 3;
    int n = blockIdx.y >> 3, h = blockIdx.y & 7;
    int m0 = blockIdx.x * 128;
    size_t lbase = ((size_t)(n*NHEAD + h))*LL + m0;
    const __half* Asrc = (which == 0 ? g_qkh : g_s2t);
    const __half* Bsrc = g_vh[which ^ 1] + ((size_t)(n*LL))*CH + h*DH;
    uint32_t asm_b = smem_u32(As), bsm_b = smem_u32(Bs);

    if (which == 0 && t < 128) {
        mxs[t] = g_rmax[lbase + t];
        ris[t] = g_rinv[lbase + t];
    }
    __syncthreads();

    uint32_t a_off = (uint32_t)(((wid*16 + (quad&1)*8 + r)*PADA + (quad>>1)*8) * 2);
    float acc[4][4];
    #pragma unroll
    for (int nt = 0; nt < 4; nt++)
        #pragma unroll
        for (int i = 0; i < 4; i++) acc[nt][i] = 0.f;

    for (int k0 = 0; k0 < LL; k0 += 64) {
        {
            int row = t >> 1, half0 = (t & 1)*32;
            const __half* src = Asrc + (lbase + row)*LL + k0 + half0;
            __half* dst = As + row*PADA + half0;
            if (which == 0) {
                float mx = mxs[row], ri = ris[row];
                #pragma unroll
                for (int j = 0; j < 4; j++) {
                    uint4 raw = *(const uint4*)(src + j*8);
                    __half2* hp = (__half2*)&raw;
                    __half2 o[4];
                    #pragma unroll
                    for (int q = 0; q < 4; q++) {
                        float2 f = __half22float2(hp[q]);
                        o[q] = __floats2half2_rn(__expf(f.x - mx)*ri, __expf(f.y - mx)*ri);
                    }
                    *(uint4*)(dst + j*8) = *(uint4*)o;
                }
            } else {
                #pragma unroll
                for (int j = 0; j < 4; j++)
                    *(uint4*)(dst + j*8) = *(const uint4*)(src + j*8);
            }
        }
        {
            int row = t >> 2, seg = (t & 3)*8;
            *(uint4*)(Bs + row*PADB + seg) = *(const uint4*)(Bsrc + (size_t)(k0 + row)*CH + seg);
        }
        __syncthreads();

        #pragma unroll
        for (int ks = 0; ks < 4; ks++) {
            uint32_t af[4];
            LDSM_X4(af[0], af[1], af[2], af[3], asm_b + a_off + (uint32_t)(ks*32));
            #pragma unroll
            for (int p = 0; p < 2; p++) {
                uint32_t b0, b1, b2, b3;
                uint32_t boff = (uint32_t)(((ks*16 + (quad&1)*8 + r)*PADB + p*16 + (quad>>1)*8) * 2);
                LDSM_X4_T(b0, b1, b2, b3, bsm_b + boff);
                mma_f16(acc[2*p],   af, b0, b1);
                mma_f16(acc[2*p+1], af, b2, b3);
            }
        }
        __syncthreads();
    }

    int rrow = lane >> 2, ccol = (lane & 3)*2;
    #pragma unroll
    for (int nt = 0; nt < 4; nt++) {
        size_t orow = (size_t)(n*LL + m0 + wid*16 + rrow);
        __half* dst = g_m[which] + orow*CH + h*DH + nt*8 + ccol;
        *(__half2*)dst            = __floats2half2_rn(acc[nt][0], acc[nt][1]);
        *(__half2*)(dst + 8*CH)   = __floats2half2_rn(acc[nt][2], acc[nt][3]);
    }
}

// ---------------- weight fp16 prepass (splits W1 halves) ----------------
__global__ void roundh3_kernel(const float* __restrict__ mw, const float* __restrict__ w1,
                               const float* __restrict__ w2) {
    int i = blockIdx.x*256 + threadIdx.x;
    if (i < CH*CH) g_mwh[i] = __float2half_rn(mw[i]);
    if (i < CH*C2) g_w2h[i] = __float2half_rn(w2[i]);
    if (i < C2*C2) {
        int nrow = i >> 9, k = i & 511;
        __half v = __float2half_rn(w1[i]);
        if (k < CH) g_w1a[nrow*CH + k] = v;
        else        g_w1b[nrow*CH + k - CH] = v;
    }
}

// ---------------- 1. fused maxpool + xcopy + LN partials ----------------
#define PUX_PITCH 516
#define PUX_SMEM ((32*PUX_PITCH + 32*33)*4)
__global__ __launch_bounds__(256) void pux_kernel(const float* __restrict__ x1,
                                                  const float* __restrict__ x2) {
    extern __shared__ float sh[];
    float* po = sh + 32*PUX_PITCH;
    int ct = blockIdx.x;
    int y4 = blockIdx.y;
    int n  = blockIdx.z & 3;
    int o  = blockIdx.z >> 2;
    const float* xs = o ? x2 : x1;
    int tid = threadIdx.x;
    int c0 = ct*32;
    #pragma unroll
    for (int i = 0; i < 16; i++) {
        int f = tid + i*256;
        int cc = f >> 7, rem = f & 127;
        int yy = rem >> 5, c4 = rem & 31;
        float4 v = *(const float4*)(xs +
            (((size_t)(n*CH + c0+cc))*HH + y4*4+yy)*WW + c4*4);
        *(float4*)&sh[cc*PUX_PITCH + yy*128 + c4*4] = v;
    }
    __syncthreads();
    {
        int c = tid >> 3, xo = (tid & 7)*4;
        float4 out;
        float* pov = &out.x;
        #pragma unroll
        for (int k = 0; k < 4; k++) {
            int px = xo + k;
            float m = NEGINF;
            #pragma unroll
            for (int yy = 0; yy < 4; yy++) {
                float4 v = *(const float4*)&sh[c*PUX_PITCH + yy*128 + px*4];
                m = fmaxf(m, fmaxf(fmaxf(v.x, v.y), fmaxf(v.z, v.w)));
            }
            pov[k] = m;
            po[c*33 + px] = m;
        }
        *(float4*)(g_p[o] + ((size_t)(n*CH + c0 + c))*LL + y4*32 + xo) = out;
    }
    __syncthreads();
    if (tid < 32) {
        float s = 0.f, sq = 0.f;
        #pragma unroll
        for (int c = 0; c < 32; c++) { float v = po[c*33 + tid]; s += v; sq += v*v; }
        int sp = y4*32 + tid;
        size_t pidx = (((size_t)(o*BATCH + n))*8 + ct)*LL + sp;
        g_lnps[pidx] = s;
        g_lnpq[pidx] = sq;
    }
    size_t rbase = (size_t)o*NPIX + (size_t)n*HH*WW + (size_t)(y4*4)*WW;
    #pragma unroll
    for (int j = 0; j < 2; j++) {
        int p = tid + j*256;
        __half2 hb[16];
        #pragma unroll
        for (int cc = 0; cc < 32; cc += 2)
            hb[cc>>1] = __floats2half2_rn(sh[cc*PUX_PITCH + p], sh[(cc+1)*PUX_PITCH + p]);
        uint4* dst = (uint4*)(g_u + (rbase + p)*CH + c0);
        const uint4* src = (const uint4*)hb;
        dst[0] = src[0]; dst[1] = src[1]; dst[2] = src[2]; dst[3] = src[3];
    }
}

// ---------------- 2. finalize LN stats ----------------
__global__ void lnfin_kernel() {
    int gi = blockIdx.x*256 + threadIdx.x;
    int on = gi / LL, sp = gi % LL;
    float s = 0.f, sq = 0.f;
    #pragma unroll
    for (int ctt = 0; ctt < 8; ctt++) {
        size_t pidx = (((size_t)on)*8 + ctt)*LL + sp;
        s += g_lnps[pidx]; sq += g_lnpq[pidx];
    }
    float mu = s * (1.0f/CH);
    g_mu1[gi] = mu;
    g_rs1[gi] = rsqrtf(sq * (1.0f/CH) - mu*mu + EPSF);
}

// ---------------- 3. dwconv3x3 + BN (LN inline), q/k/v fp16 out ----------------
__global__ __launch_bounds__(256) void dwbn2_kernel(
        const float* __restrict__ qw, const float* __restrict__ qg, const float* __restrict__ qb,
        const float* __restrict__ qm, const float* __restrict__ qvv,
        const float* __restrict__ vw, const float* __restrict__ vg, const float* __restrict__ vb,
        const float* __restrict__ vm, const float* __restrict__ vvv,
        const float* __restrict__ l1g, const float* __restrict__ l1b) {
    int c0 = blockIdx.x * 8;
    int n  = blockIdx.y;
    int o  = blockIdx.z;
    __shared__ float sp[8*1028];
    int t = threadIdx.x;
    const float* mub = g_mu1 + (size_t)(o*BATCH + n)*LL;
    const float* rsb = g_rs1 + (size_t)(o*BATCH + n)*LL;
    #pragma unroll
    for (int cc = 0; cc < 8; cc++) {
        float gc = l1g[c0+cc], bc = l1b[c0+cc];
        #pragma unroll
        for (int it = 0; it < 4; it++) {
            int spi = t + it*256;
            float raw = g_p[o][((size_t)(n*CH + c0+cc))*LL + spi];
            sp[cc*1028 + spi] = gc*(raw - mub[spi])*rsb[spi] + bc;
        }
    }
    __syncthreads();

    int cc = t & 7, jq = t >> 3;
    int c = c0 + cc;
    float wq[9], wv[9];
    #pragma unroll
    for (int k = 0; k < 9; k++) { wq[k] = qw[c*9+k]; wv[k] = vw[c*9+k]; }
    float scq = qg[c]*rsqrtf(qvv[c]+EPSF), bq = qb[c] - scq*qm[c];
    float scv = vg[c]*rsqrtf(vvv[c]+EPSF), bv = vb[c] - scv*vm[c];
    const float* s = sp + cc*1028;
    __half* oq = g_qh[o] + (size_t)(n*LL)*CH + c;
    __half* ov = g_vh[o] + (size_t)(n*LL)*CH + c;

    for (int i = 0; i < 32; i++) {
        float aq = 0.f, av = 0.f;
        #pragma unroll
        for (int di = 0; di < 3; di++) {
            int ii = i + di - 1;
            if (ii < 0 || ii >= HP) continue;
            #pragma unroll
            for (int dj = 0; dj < 3; dj++) {
                int jj = jq + dj - 1;
                if (jj < 0 || jj >= WP) continue;
                float x = s[ii*32 + jj];
                aq += wq[di*3+dj]*x;
                av += wv[di*3+dj]*x;
            }
        }
        int l = i*32 + jq;
        oq[(size_t)l*CH] = __float2half_rn(scq*aq + bq);
        ov[(size_t)l*CH] = __float2half_rn(scv*av + bv);
    }
}

// ---------------- 5. combine tile partials ----------------
__global__ void rowstat2_kernel() {
    int r = blockIdx.x*256 + threadIdx.x;
    float pm[NTILES];
    float m = NEGINF;
    #pragma unroll
    for (int i = 0; i < NTILES; i++) {
        pm[i] = g_pmax[(size_t)r*NTILES + i];
        m = fmaxf(m, pm[i]);
    }
    float sum = 0.f;
    #pragma unroll
    for (int i = 0; i < NTILES; i++)
        sum += g_psum[(size_t)r*NTILES + i] * __expf(pm[i] - m);
    g_rmax[r] = m;
    g_rinv[r] = 1.f/sum;
}

// ---------------- 7. S2 softmax over heads + transpose ----------------
__global__ __launch_bounds__(256) void s2t_kernel() {
    __shared__ __half sm[8][32][36];
    int t = threadIdx.x;
    int s0 = blockIdx.x*32, l0 = blockIdx.y*32, n = blockIdx.z;
    int row = t >> 3, seg = t & 7;
    #pragma unroll
    for (int h = 0; h < NHEAD; h++) {
        uint2 v = *(const uint2*)(g_qkh +
            (((size_t)(n*NHEAD + h))*LL + l0 + row)*LL + s0 + seg*4);
        *(uint2*)&sm[h][row][seg*4] = v;
    }
    __syncthreads();
    #pragma unroll
    for (int j = 0; j < 4; j++) {
        int e = t*4 + j;
        int l = e >> 5, s = e & 31;
        float v[NHEAD];
        float mx = NEGINF;
        #pragma unroll
        for (int h = 0; h < NHEAD; h++) {
            v[h] = __half2float(sm[h][l][s]);
            mx = fmaxf(mx, v[h]);
        }
        float smm = 0.f;
        #pragma unroll
        for (int h = 0; h < NHEAD; h++) { v[h] = __expf(v[h]-mx); smm += v[h]; }
        float ri = 1.f/smm;
        #pragma unroll
        for (int h = 0; h < NHEAD; h++)
            sm[h][l][s] = __float2half_rn(v[h]*ri);
    }
    __syncthreads();
    #pragma unroll
    for (int h = 0; h < NHEAD; h++) {
        __half tmp[4];
        #pragma unroll
        for (int jj = 0; jj < 4; jj++) tmp[jj] = sm[h][seg*4+jj][row];
        *(uint2*)(g_s2t + (((size_t)(n*NHEAD + h))*LL + s0 + row)*LL + l0 + seg*4) =
            *(uint2*)tmp;
    }
}

// ---------------- 10. fused LN stats + apply + residual + write-out ----------------
__global__ __launch_bounds__(256) void out_fused_kernel(
        const float* __restrict__ x1, const float* __restrict__ x2,
        const float* __restrict__ lg, const float* __restrict__ lb,
        float* __restrict__ out) {
    int xt = blockIdx.x;
    int y  = blockIdx.y;
    int n  = blockIdx.z % BATCH;
    int o  = blockIdx.z / BATCH;
    __shared__ float zsh[32][257];
    __shared__ float smu[32], srs[32];
    int tid = threadIdx.x;
    size_t rbase = (size_t)o*NPIX + (size_t)n*HH*WW + (size_t)y*WW + xt*32;
    #pragma unroll
    for (int j = 0; j < 4; j++) {
        int px = j*8 + (tid >> 5);
        int c = (tid & 31) * 8;
        uint4 raw = *(const uint4*)(g_z2h + (rbase + px)*CH + c);
        const __half2* hp = (const __half2*)&raw;
        #pragma unroll
        for (int q = 0; q < 4; q++) {
            float2 f = __half22float2(hp[q]);
            zsh[px][c + 2*q]     = f.x;
            zsh[px][c + 2*q + 1] = f.y;
        }
    }
    __syncthreads();
    int w = tid >> 5, lane = tid & 31;
    #pragma unroll
    for (int i = 0; i < 4; i++) {
        int px = w*4 + i;
        float s = 0.f, sq = 0.f;
        #pragma unroll
        for (int k = 0; k < 8; k++) { float v = zsh[px][lane + k*32]; s += v; sq += v*v; }
        #pragma unroll
        for (int off = 16; off; off >>= 1) {
            s  += __shfl_xor_sync(0xffffffffu, s,  off);
            sq += __shfl_xor_sync(0xffffffffu, sq, off);
        }
        if (!lane) {
            float mu = s * (1.0f/CH);
            smu[px] = mu;
            srs[px] = rsqrtf(sq * (1.0f/CH) - mu*mu + EPSF);
        }
    }
    __syncthreads();
    const float* xs = o ? x2 : x1;
    int cth = tid >> 5, tx = tid & 31;
    float mu = smu[tx], rs = srs[tx];
    size_t xbase = ((size_t)(n*CH))*HH*WW + (size_t)y*WW + xt*32 + tx;
    float* outb = out + (size_t)o*NPIX*CH;
    #pragma unroll 8
    for (int cc = 0; cc < 32; cc++) {
        int c = cc*8 + cth;
        float val = lg[c]*(zsh[tx][c] - mu)*rs + lb[c];
        size_t gi = xbase + (size_t)c*HH*WW;
        outb[gi] = xs[gi] + val;
    }
}

// ---------------- launch ----------------
extern "C" void kernel_launch(void* const* d_in, const int* in_sizes, int n_in,
                              void* d_out, int out_size) {
    const float* x1     = (const float*)d_in[0];
    const float* x2     = (const float*)d_in[1];
    const float* qk_w   = (const float*)d_in[2];
    const float* qk_g   = (const float*)d_in[3];
    const float* qk_b   = (const float*)d_in[4];
    const float* qk_m   = (const float*)d_in[5];
    const float* qk_v   = (const float*)d_in[6];
    const float* v_w    = (const float*)d_in[7];
    const float* v_g    = (const float*)d_in[8];
    const float* v_b    = (const float*)d_in[9];
    const float* v_m    = (const float*)d_in[10];
    const float* v_v    = (const float*)d_in[11];
    const float* ln1_g  = (const float*)d_in[12];
    const float* ln1_b  = (const float*)d_in[13];
    const float* ln2_g  = (const float*)d_in[14];
    const float* ln2_b  = (const float*)d_in[15];
    const float* merge_w= (const float*)d_in[16];
    const float* mlp_w1 = (const float*)d_in[17];
    const float* mlp_w2 = (const float*)d_in[18];
    float* out = (float*)d_out;

    __half *pm, *pmmh, *pmmw, *pz1, *pz2h, *pmw, *pw1b, *pw2;
    cudaGetSymbolAddress((void**)&pm,   g_m);
    cudaGetSymbolAddress((void**)&pmmh, g_mmh);
    cudaGetSymbolAddress((void**)&pmmw, g_mmw);
    cudaGetSymbolAddress((void**)&pz1,  g_z1);
    cudaGetSymbolAddress((void**)&pz2h, g_z2h);
    cudaGetSymbolAddress((void**)&pmw,  g_mwh);
    cudaGetSymbolAddress((void**)&pw1b, g_w1b);
    cudaGetSymbolAddress((void**)&pw2,  g_w2h);

    cudaFuncSetAttribute(hgemm_kernel,    cudaFuncAttributeMaxDynamicSharedMemorySize, GEMM_SMEM);
    cudaFuncSetAttribute(hgemm_up_kernel, cudaFuncAttributeMaxDynamicSharedMemorySize, GEMMUP_SMEM);
    cudaFuncSetAttribute(pux_kernel,      cudaFuncAttributeMaxDynamicSharedMemorySize, PUX_SMEM);

    // one-time host resources for the fork/join (no device memory involved)
    static cudaStream_t sB = nullptr;
    static cudaEvent_t evFork = nullptr, evJoin = nullptr;
    if (!sB) {
        cudaStreamCreateWithFlags(&sB, cudaStreamNonBlocking);
        cudaEventCreateWithFlags(&evFork, cudaEventDisableTiming);
        cudaEventCreateWithFlags(&evJoin, cudaEventDisableTiming);
    }

    roundh3_kernel<<<(C2*C2+255)/256, 256>>>(merge_w, mlp_w1, mlp_w2);

    pux_kernel<<<dim3(CH/32, HP, 2*BATCH), 256, PUX_SMEM>>>(x1, x2);
    lnfin_kernel<<<(2*BATCH*LL)/256, 256>>>();

    dwbn2_kernel<<<dim3(CH/8, BATCH, 2), 256>>>(qk_w, qk_g, qk_b, qk_m, qk_v,
                                                v_w, v_g, v_b, v_m, v_v, ln1_g, ln1_b);

    // attention: fork after qkmma into two independent chains
    qkmma_kernel<<<dim3(LL/128, LL/128, BATCH*NHEAD), 256>>>();
    cudaEventRecord(evFork, 0);
    cudaStreamWaitEvent(sB, evFork, 0);

    // chain B (stream sB): S2 softmax+transpose -> m2
    s2t_kernel<<<dim3(LL/32, LL/32, BATCH), 256, 0, sB>>>();
    av_kernel<<<dim3(LL/128, BATCH*NHEAD), 256, 0, sB>>>(1);
    cudaEventRecord(evJoin, sB);

    // chain A (legacy stream): row stats -> m1
    rowstat2_kernel<<<BATCH*NHEAD*LL/256, 256>>>();
    av_kernel<<<dim3(LL/128, BATCH*NHEAD), 256>>>(0);

    // join before merge (needs g_m[0] and g_m[1])
    cudaStreamWaitEvent(0, evJoin, 0);

    // merge linear -> fp16 mm
    hgemm_kernel<<<dim3(CH/128, (2*BATCH*LL)/128), 256, GEMM_SMEM>>>(
        pm, pmw, pmmh, 2*BATCH*LL, CH, CH, 0, 1);
    // mmw = mm @ W1b^T
    hgemm_kernel<<<dim3(C2/128, (2*BATCH*LL)/128), 256, GEMM_SMEM>>>(
        pmmh, pw1b, pmmw, 2*BATCH*LL, C2, CH, 0, 1);

    // MLP1: x-half GEMM + upsample-add + relu
    hgemm_up_kernel<<<dim3(C2/128, NROWS/128), 256, GEMMUP_SMEM>>>();
    // MLP2 (z2 fp16)
    hgemm_kernel<<<dim3(CH/128, NROWS/128), 256, GEMM_SMEM>>>(
        pz1, pw2, pz2h, NROWS, CH, C2, 0, 1);

    out_fused_kernel<<<dim3(WW/32, HH, 2*BATCH), 256>>>(x1, x2, ln2_g, ln2_b, out);
}

// round 17
// speedup vs baseline: 1.1287x; 1.0025x over previous
#include <cuda_runtime.h>
#include <cuda_fp16.h>
#include <cstdint>

#define BATCH 4
#define CH 256
#define HH 128
#define WW 128
#define HP 32
#define WP 32
#define LL 1024
#define NHEAD 8
#define DH 32
#define C2 512
#define NPIX (BATCH*HH*WW)
#define NROWS (2*NPIX)
#define EPSF 1e-5f
#define TSCALE 0.17677669529663687f
#define NEGINF (-3.402823466e38f)
#define NTILES 16

// ---------------- scratch ----------------
__device__ float  g_p[2][BATCH*CH*LL];
__device__ float  g_lnps[2*BATCH*8*LL];
__device__ float  g_lnpq[2*BATCH*8*LL];
__device__ float  g_mu1[2*BATCH*LL];
__device__ float  g_rs1[2*BATCH*LL];
__device__ __half g_qh[2][(size_t)BATCH*LL*CH];
__device__ __half g_vh[2][(size_t)BATCH*LL*CH];
__device__ __half g_qkh[(size_t)BATCH*NHEAD*LL*LL];
__device__ __half g_s2t[(size_t)BATCH*NHEAD*LL*LL];
__device__ float  g_pmax[(size_t)BATCH*NHEAD*LL*NTILES];
__device__ float  g_psum[(size_t)BATCH*NHEAD*LL*NTILES];
__device__ float  g_rmax[BATCH*NHEAD*LL];
__device__ float  g_rinv[BATCH*NHEAD*LL];
__device__ __half g_m[2][(size_t)BATCH*LL*CH];
__device__ __half g_mmh[(size_t)2*BATCH*LL*CH];
__device__ __half g_mmw[(size_t)2*BATCH*LL*C2];
__device__ __half g_u[(size_t)NROWS*CH];
__device__ __half g_z1[(size_t)NROWS*C2];
__device__ __half g_z2h[(size_t)NROWS*CH];
__device__ __half g_mwh[CH*CH];
__device__ __half g_w1a[C2*CH];
__device__ __half g_w1b[C2*CH];
__device__ __half g_w2h[CH*C2];

// ================= helpers =================
__device__ __forceinline__ uint32_t smem_u32(const void* p) {
    uint32_t a;
    asm("{ .reg .u64 t; cvta.to.shared.u64 t, %1; cvt.u32.u64 %0, t; }" : "=r"(a) : "l"(p));
    return a;
}
#define CP_ASYNC16(dst, src) \
    asm volatile("cp.async.cg.shared.global [%0], [%1], 16;" :: "r"(dst), "l"(src) : "memory")
#define CP_COMMIT() asm volatile("cp.async.commit_group;" ::: "memory")
#define CP_WAIT(n)  asm volatile("cp.async.wait_group %0;" :: "n"(n) : "memory")
#define LDSM_X4(r0, r1, r2, r3, addr) \
    asm volatile("ldmatrix.sync.aligned.m8n8.x4.shared.b16 {%0,%1,%2,%3}, [%4];" \
        : "=r"(r0), "=r"(r1), "=r"(r2), "=r"(r3) : "r"(addr))
#define LDSM_X4_T(r0, r1, r2, r3, addr) \
    asm volatile("ldmatrix.sync.aligned.m8n8.x4.trans.shared.b16 {%0,%1,%2,%3}, [%4];" \
        : "=r"(r0), "=r"(r1), "=r"(r2), "=r"(r3) : "r"(addr))

__device__ __forceinline__ void mma_f16(float* d, const uint32_t* a, uint32_t b0, uint32_t b1) {
    asm volatile(
        "mma.sync.aligned.m16n8k16.row.col.f32.f16.f16.f32 "
        "{%0,%1,%2,%3}, {%4,%5,%6,%7}, {%8,%9}, {%0,%1,%2,%3};"
        : "+f"(d[0]), "+f"(d[1]), "+f"(d[2]), "+f"(d[3])
        : "r"(a[0]), "r"(a[1]), "r"(a[2]), "r"(a[3]), "r"(b0), "r"(b1));
}

// ================= fp16 mma GEMM (validated: CTA 128x128, 3-stage) =================
#define BKH 64
#define PADH 72
#define TILEH (128*PADH)
#define TILE_BYTES (TILEH*2)
#define STAGE_BYTES (2*TILE_BYTES)
#define GEMM_SMEM (3*STAGE_BYTES)

__global__ __launch_bounds__(256) void hgemm_kernel(
        const __half* __restrict__ A, const __half* __restrict__ Bw, void* __restrict__ C,
        int M, int N, int K, int relu, int outHalf) {
    extern __shared__ __half smh[];
    int tid = threadIdx.x, wid = tid >> 5, lane = tid & 31;
    int g = lane >> 2, t = lane & 3;
    int r = lane & 7, quad = lane >> 3;
    int wm = wid >> 1, wn = wid & 1;
    size_t am0 = (size_t)blockIdx.y * 128;
    size_t bn0 = (size_t)blockIdx.x * 128;
    uint32_t smembase = smem_u32(smh);

    uint32_t a_off[2], b_off[4];
    #pragma unroll
    for (int mt = 0; mt < 2; mt++)
        a_off[mt] = (uint32_t)(((wm*32 + mt*16 + (quad&1)*8 + r)*PADH + (quad>>1)*8) * 2);
    #pragma unroll
    for (int p = 0; p < 4; p++)
        b_off[p] = (uint32_t)(((wn*64 + p*16 + (quad>>1)*8 + r)*PADH + (quad&1)*8) * 2);

    int nchunk = K >> 6;
    float acc[2][8][4];
    #pragma unroll
    for (int mt = 0; mt < 2; mt++)
        #pragma unroll
        for (int nt = 0; nt < 8; nt++)
            #pragma unroll
            for (int i = 0; i < 4; i++) acc[mt][nt][i] = 0.f;

    auto issue = [&](int ch, int st) {
        const __half* Ag = A + am0 * K + ch*BKH;
        const __half* Bg = Bw + bn0 * K + ch*BKH;
        uint32_t base = smembase + st*STAGE_BYTES;
        #pragma unroll
        for (int j = 0; j < 4; j++) {
            int idx = tid + j * 256;
            int row = idx >> 3, seg = idx & 7;
            uint32_t d = (uint32_t)((row*PADH + seg*8) * 2);
            CP_ASYNC16(base + d,              Ag + (size_t)row*K + seg*8);
            CP_ASYNC16(base + TILE_BYTES + d, Bg + (size_t)row*K + seg*8);
        }
        CP_COMMIT();
    };

    issue(0, 0);
    if (nchunk > 1) issue(1, 1);

    for (int i = 0; i < nchunk; i++) {
        int s = i % 3;
        if (i + 2 < nchunk) { issue(i + 2, (i + 2) % 3); CP_WAIT(2); }
        else if (i + 1 < nchunk) { CP_WAIT(1); }
        else { CP_WAIT(0); }
        __syncthreads();

        uint32_t abase = smembase + s*STAGE_BYTES;
        uint32_t bbase = abase + TILE_BYTES;
        #pragma unroll
        for (int ks = 0; ks < 4; ks++) {
            uint32_t koff = (uint32_t)(ks * 32);
            uint32_t af[2][4];
            LDSM_X4(af[0][0], af[0][1], af[0][2], af[0][3], abase + a_off[0] + koff);
            LDSM_X4(af[1][0], af[1][1], af[1][2], af[1][3], abase + a_off[1] + koff);
            #pragma unroll
            for (int p = 0; p < 4; p++) {
                uint32_t b0, b1, b2, b3;
                LDSM_X4(b0, b1, b2, b3, bbase + b_off[p] + koff);
                mma_f16(acc[0][2*p],   af[0], b0, b1);
                mma_f16(acc[1][2*p],   af[1], b0, b1);
                mma_f16(acc[0][2*p+1], af[0], b2, b3);
                mma_f16(acc[1][2*p+1], af[1], b2, b3);
            }
        }
        __syncthreads();
    }

    #pragma unroll
    for (int mt = 0; mt < 2; mt++) {
        size_t row = am0 + wm*32 + mt*16 + g;
        #pragma unroll
        for (int nt = 0; nt < 8; nt++) {
            size_t col = bn0 + wn*64 + nt*8 + 2*t;
            float v0 = acc[mt][nt][0], v1 = acc[mt][nt][1];
            float v2 = acc[mt][nt][2], v3 = acc[mt][nt][3];
            if (relu) {
                v0 = fmaxf(v0,0.f); v1 = fmaxf(v1,0.f);
                v2 = fmaxf(v2,0.f); v3 = fmaxf(v3,0.f);
            }
            if (outHalf) {
                __half* Ch = (__half*)C;
                *(__half2*)(Ch + row*N + col)     = __floats2half2_rn(v0, v1);
                *(__half2*)(Ch + (row+8)*N + col) = __floats2half2_rn(v2, v3);
            } else {
                float* Cf = (float*)C;
                *(float2*)(Cf + row*N + col)     = make_float2(v0, v1);
                *(float2*)(Cf + (row+8)*N + col) = make_float2(v2, v3);
            }
        }
    }
}

// ===== MLP1 GEMM with upsample-add epilogue (2-stage, 2 CTAs/SM) =====
#define UP_SMEM (2*32*128*2)
#define GEMMUP_SMEM (2*STAGE_BYTES + UP_SMEM)
__global__ __launch_bounds__(256) void hgemm_up_kernel() {
    extern __shared__ __half smh[];
    __half* S0 = smh + STAGE_BYTES;
    __half* S1 = S0 + 32*128;
    int tid = threadIdx.x, wid = tid >> 5, lane = tid & 31;
    int g = lane >> 2, t = lane & 3;
    int r = lane & 7, quad = lane >> 3;
    int wm = wid >> 1, wn = wid & 1;
    size_t am0 = (size_t)blockIdx.y * 128;
    size_t bn0 = (size_t)blockIdx.x * 128;
    uint32_t smembase = smem_u32(smh);

    int o = blockIdx.y >> 9;
    int n = (blockIdx.y >> 7) & 3;
    int y = blockIdx.y & 127;
    float sy = (y + 0.5f)*0.25f - 0.5f;
    int yy0 = (int)floorf(sy);
    float fy = sy - (float)yy0;
    int y0c = min(max(yy0, 0), HP-1), y1c = min(max(yy0+1, 0), HP-1);

    {
        const __half* mb = g_mmw + ((size_t)(o*BATCH + n))*LL*C2 + bn0;
        #pragma unroll
        for (int j = 0; j < 4; j++) {
            int idx = tid*4 + j;
            int which = idx >> 9, rem = idx & 511;
            int xp = rem >> 4, cseg = (rem & 15)*8;
            int yc = which ? y1c : y0c;
            __half* dst = (which ? S1 : S0) + xp*128 + cseg;
            *(uint4*)dst = *(const uint4*)(mb + (size_t)(yc*WP + xp)*C2 + cseg);
        }
    }

    uint32_t a_off[2], b_off[4];
    #pragma unroll
    for (int mt = 0; mt < 2; mt++)
        a_off[mt] = (uint32_t)(((wm*32 + mt*16 + (quad&1)*8 + r)*PADH + (quad>>1)*8) * 2);
    #pragma unroll
    for (int p = 0; p < 4; p++)
        b_off[p] = (uint32_t)(((wn*64 + p*16 + (quad>>1)*8 + r)*PADH + (quad&1)*8) * 2);

    float acc[2][8][4];
    #pragma unroll
    for (int mt = 0; mt < 2; mt++)
        #pragma unroll
        for (int nt = 0; nt < 8; nt++)
            #pragma unroll
            for (int i = 0; i < 4; i++) acc[mt][nt][i] = 0.f;

    auto issue = [&](int ch, int st) {
        const __half* Ag = g_u + am0 * CH + ch*BKH;
        const __half* Bg = g_w1a + bn0 * CH + ch*BKH;
        uint32_t base = smembase + st*STAGE_BYTES;
        #pragma unroll
        for (int j = 0; j < 4; j++) {
            int idx = tid + j * 256;
            int row = idx >> 3, seg = idx & 7;
            uint32_t d = (uint32_t)((row*PADH + seg*8) * 2);
            CP_ASYNC16(base + d,              Ag + (size_t)row*CH + seg*8);
            CP_ASYNC16(base + TILE_BYTES + d, Bg + (size_t)row*CH + seg*8);
        }
        CP_COMMIT();
    };

    issue(0, 0);
    for (int i = 0; i < 4; i++) {
        int s = i & 1;
        if (i + 1 < 4) { issue(i + 1, (i + 1) & 1); CP_WAIT(1); }
        else { CP_WAIT(0); }
        __syncthreads();
        uint32_t abase = smembase + s*STAGE_BYTES;
        uint32_t bbase = abase + TILE_BYTES;
        #pragma unroll
        for (int ks = 0; ks < 4; ks++) {
            uint32_t koff = (uint32_t)(ks * 32);
            uint32_t af[2][4];
            LDSM_X4(af[0][0], af[0][1], af[0][2], af[0][3], abase + a_off[0] + koff);
            LDSM_X4(af[1][0], af[1][1], af[1][2], af[1][3], abase + a_off[1] + koff);
            #pragma unroll
            for (int p = 0; p < 4; p++) {
                uint32_t b0, b1, b2, b3;
                LDSM_X4(b0, b1, b2, b3, bbase + b_off[p] + koff);
                mma_f16(acc[0][2*p],   af[0], b0, b1);
                mma_f16(acc[1][2*p],   af[1], b0, b1);
                mma_f16(acc[0][2*p+1], af[0], b2, b3);
                mma_f16(acc[1][2*p+1], af[1], b2, b3);
            }
        }
        __syncthreads();
    }

    float w00 = 1.f - fy, w10 = fy;
    #pragma unroll
    for (int mt = 0; mt < 2; mt++) {
        #pragma unroll
        for (int half = 0; half < 2; half++) {
            int x = wm*32 + mt*16 + g + half*8;
            float sx = (x + 0.5f)*0.25f - 0.5f;
            int xx0 = (int)floorf(sx);
            float fx = sx - (float)xx0;
            int x0c = min(max(xx0, 0), WP-1), x1c = min(max(xx0+1, 0), WP-1);
            size_t grow = am0 + x;
            #pragma unroll
            for (int nt = 0; nt < 8; nt++) {
                int col = wn*64 + nt*8 + 2*t;
                float a0 = acc[mt][nt][half*2+0], a1 = acc[mt][nt][half*2+1];
                float u00 = __half2float(S0[x0c*128 + col]);
                float u01 = __half2float(S0[x1c*128 + col]);
                float u10 = __half2float(S1[x0c*128 + col]);
                float u11 = __half2float(S1[x1c*128 + col]);
                float up0 = w00*((1.f-fx)*u00 + fx*u01) + w10*((1.f-fx)*u10 + fx*u11);
                u00 = __half2float(S0[x0c*128 + col+1]);
                u01 = __half2float(S0[x1c*128 + col+1]);
                u10 = __half2float(S1[x0c*128 + col+1]);
                u11 = __half2float(S1[x1c*128 + col+1]);
                float up1 = w00*((1.f-fx)*u00 + fx*u01) + w10*((1.f-fx)*u10 + fx*u11);
                a0 = fmaxf(a0 + up0, 0.f);
                a1 = fmaxf(a1 + up1, 0.f);
                *(__half2*)(g_z1 + grow*C2 + bn0 + col) = __floats2half2_rn(a0, a1);
            }
        }
    }
}

// ================= QK tensor-core GEMM: logits + softmax partials =================
#define PADQ 40
__global__ __launch_bounds__(256) void qkmma_kernel() {
    __shared__ __half qs[2][128*PADQ];
    int tid = threadIdx.x, wid = tid >> 5, lane = tid & 31;
    int g = lane >> 2, t = lane & 3;
    int r = lane & 7, quad = lane >> 3;
    int wm = wid >> 1, wn = wid & 1;
    int n = blockIdx.z >> 3, h = blockIdx.z & 7;
    int l0 = blockIdx.y * 128, s0 = blockIdx.x * 128;
    uint32_t abase = smem_u32(qs[0]);
    uint32_t bbase = smem_u32(qs[1]);

    #pragma unroll
    for (int j = 0; j < 2; j++) {
        int idx = tid + j*256;
        int row = idx >> 2, seg = idx & 3;
        uint32_t d = (uint32_t)((row*PADQ + seg*8) * 2);
        const __half* Aq = g_qh[0] + ((size_t)(n*LL + l0 + row))*CH + h*DH + seg*8;
        const __half* Bq = g_qh[1] + ((size_t)(n*LL + s0 + row))*CH + h*DH + seg*8;
        CP_ASYNC16(abase + d, Aq);
        CP_ASYNC16(bbase + d, Bq);
    }
    CP_COMMIT();
    CP_WAIT(0);
    __syncthreads();

    uint32_t a_off[2], b_off[4];
    #pragma unroll
    for (int mt = 0; mt < 2; mt++)
        a_off[mt] = (uint32_t)(((wm*32 + mt*16 + (quad&1)*8 + r)*PADQ + (quad>>1)*8) * 2);
    #pragma unroll
    for (int p = 0; p < 4; p++)
        b_off[p] = (uint32_t)(((wn*64 + p*16 + (quad>>1)*8 + r)*PADQ + (quad&1)*8) * 2);

    float acc[2][8][4];
    #pragma unroll
    for (int mt = 0; mt < 2; mt++)
        #pragma unroll
        for (int nt = 0; nt < 8; nt++)
            #pragma unroll
            for (int i = 0; i < 4; i++) acc[mt][nt][i] = 0.f;

    #pragma unroll
    for (int ks = 0; ks < 2; ks++) {
        uint32_t koff = (uint32_t)(ks * 32);
        uint32_t af[2][4];
        LDSM_X4(af[0][0], af[0][1], af[0][2], af[0][3], abase + a_off[0] + koff);
        LDSM_X4(af[1][0], af[1][1], af[1][2], af[1][3], abase + a_off[1] + koff);
        #pragma unroll
        for (int p = 0; p < 4; p++) {
            uint32_t b0, b1, b2, b3;
            LDSM_X4(b0, b1, b2, b3, bbase + b_off[p] + koff);
            mma_f16(acc[0][2*p],   af[0], b0, b1);
            mma_f16(acc[1][2*p],   af[1], b0, b1);
            mma_f16(acc[0][2*p+1], af[0], b2, b3);
            mma_f16(acc[1][2*p+1], af[1], b2, b3);
        }
    }

    size_t qkbase = ((size_t)(n*NHEAD + h))*LL;
    int tile = blockIdx.x*2 + wn;
    #pragma unroll
    for (int mt = 0; mt < 2; mt++) {
        int row0 = l0 + wm*32 + mt*16 + g;
        float mx0 = NEGINF, mx1 = NEGINF;
        float vals[8][4];
        #pragma unroll
        for (int nt = 0; nt < 8; nt++) {
            #pragma unroll
            for (int i = 0; i < 4; i++) vals[nt][i] = TSCALE*acc[mt][nt][i];
            int col = s0 + wn*64 + nt*8 + 2*t;
            *(__half2*)(g_qkh + (qkbase + row0)*LL + col)   = __floats2half2_rn(vals[nt][0], vals[nt][1]);
            *(__half2*)(g_qkh + (qkbase + row0+8)*LL + col) = __floats2half2_rn(vals[nt][2], vals[nt][3]);
            mx0 = fmaxf(mx0, fmaxf(vals[nt][0], vals[nt][1]));
            mx1 = fmaxf(mx1, fmaxf(vals[nt][2], vals[nt][3]));
        }
        #pragma unroll
        for (int off = 1; off <= 2; off <<= 1) {
            mx0 = fmaxf(mx0, __shfl_xor_sync(0xffffffffu, mx0, off));
            mx1 = fmaxf(mx1, __shfl_xor_sync(0xffffffffu, mx1, off));
        }
        float sm0 = 0.f, sm1 = 0.f;
        #pragma unroll
        for (int nt = 0; nt < 8; nt++) {
            sm0 += __expf(vals[nt][0]-mx0) + __expf(vals[nt][1]-mx0);
            sm1 += __expf(vals[nt][2]-mx1) + __expf(vals[nt][3]-mx1);
        }
        #pragma unroll
        for (int off = 1; off <= 2; off <<= 1) {
            sm0 += __shfl_xor_sync(0xffffffffu, sm0, off);
            sm1 += __shfl_xor_sync(0xffffffffu, sm1, off);
        }
        if (t == 0) {
            g_pmax[(qkbase + row0)*NTILES + tile]   = mx0;
            g_psum[(qkbase + row0)*NTILES + tile]   = sm0;
            g_pmax[(qkbase + row0+8)*NTILES + tile] = mx1;
            g_psum[(qkbase + row0+8)*NTILES + tile] = sm1;
        }
    }
}

// ================= unified AV tensor-core GEMM (m1 / m2) =================
#define PADA 72
#define PADB 40
__global__ __launch_bounds__(256) void av_kernel(int which) {
    __shared__ __half As[128*PADA];
    __shared__ __half Bs[64*PADB];
    __shared__ float mxs[128], ris[128];
    int t = threadIdx.x, wid = t >> 5, lane = t & 31;
    int r = lane & 7, quad = lane >> 3;
    int n = blockIdx.y >> 3, h = blockIdx.y & 7;
    int m0 = blockIdx.x * 128;
    size_t lbase = ((size_t)(n*NHEAD + h))*LL + m0;
    const __half* Asrc = (which == 0 ? g_qkh : g_s2t);
    const __half* Bsrc = g_vh[which ^ 1] + ((size_t)(n*LL))*CH + h*DH;
    uint32_t asm_b = smem_u32(As), bsm_b = smem_u32(Bs);

    if (which == 0 && t < 128) {
        mxs[t] = g_rmax[lbase + t];
        ris[t] = g_rinv[lbase + t];
    }
    __syncthreads();

    uint32_t a_off = (uint32_t)(((wid*16 + (quad&1)*8 + r)*PADA + (quad>>1)*8) * 2);
    float acc[4][4];
    #pragma unroll
    for (int nt = 0; nt < 4; nt++)
        #pragma unroll
        for (int i = 0; i < 4; i++) acc[nt][i] = 0.f;

    for (int k0 = 0; k0 < LL; k0 += 64) {
        {
            int row = t >> 1, half0 = (t & 1)*32;
            const __half* src = Asrc + (lbase + row)*LL + k0 + half0;
            __half* dst = As + row*PADA + half0;
            if (which == 0) {
                float mx = mxs[row], ri = ris[row];
                #pragma unroll
                for (int j = 0; j < 4; j++) {
                    uint4 raw = *(const uint4*)(src + j*8);
                    __half2* hp = (__half2*)&raw;
                    __half2 o[4];
                    #pragma unroll
                    for (int q = 0; q < 4; q++) {
                        float2 f = __half22float2(hp[q]);
                        o[q] = __floats2half2_rn(__expf(f.x - mx)*ri, __expf(f.y - mx)*ri);
                    }
                    *(uint4*)(dst + j*8) = *(uint4*)o;
                }
            } else {
                #pragma unroll
                for (int j = 0; j < 4; j++)
                    *(uint4*)(dst + j*8) = *(const uint4*)(src + j*8);
            }
        }
        {
            int row = t >> 2, seg = (t & 3)*8;
            *(uint4*)(Bs + row*PADB + seg) = *(const uint4*)(Bsrc + (size_t)(k0 + row)*CH + seg);
        }
        __syncthreads();

        #pragma unroll
        for (int ks = 0; ks < 4; ks++) {
            uint32_t af[4];
            LDSM_X4(af[0], af[1], af[2], af[3], asm_b + a_off + (uint32_t)(ks*32));
            #pragma unroll
            for (int p = 0; p < 2; p++) {
                uint32_t b0, b1, b2, b3;
                uint32_t boff = (uint32_t)(((ks*16 + (quad&1)*8 + r)*PADB + p*16 + (quad>>1)*8) * 2);
                LDSM_X4_T(b0, b1, b2, b3, bsm_b + boff);
                mma_f16(acc[2*p],   af, b0, b1);
                mma_f16(acc[2*p+1], af, b2, b3);
            }
        }
        __syncthreads();
    }

    int rrow = lane >> 2, ccol = (lane & 3)*2;
    #pragma unroll
    for (int nt = 0; nt < 4; nt++) {
        size_t orow = (size_t)(n*LL + m0 + wid*16 + rrow);
        __half* dst = g_m[which] + orow*CH + h*DH + nt*8 + ccol;
        *(__half2*)dst            = __floats2half2_rn(acc[nt][0], acc[nt][1]);
        *(__half2*)(dst + 8*CH)   = __floats2half2_rn(acc[nt][2], acc[nt][3]);
    }
}

// ---------------- weight fp16 prepass (splits W1 halves) ----------------
__global__ void roundh3_kernel(const float* __restrict__ mw, const float* __restrict__ w1,
                               const float* __restrict__ w2) {
    int i = blockIdx.x*256 + threadIdx.x;
    if (i < CH*CH) g_mwh[i] = __float2half_rn(mw[i]);
    if (i < CH*C2) g_w2h[i] = __float2half_rn(w2[i]);
    if (i < C2*C2) {
        int nrow = i >> 9, k = i & 511;
        __half v = __float2half_rn(w1[i]);
        if (k < CH) g_w1a[nrow*CH + k] = v;
        else        g_w1b[nrow*CH + k - CH] = v;
    }
}

// ---------------- 1. fused maxpool + xcopy + LN partials ----------------
#define PUX_PITCH 516
#define PUX_SMEM ((32*PUX_PITCH + 32*33)*4)
__global__ __launch_bounds__(256) void pux_kernel(const float* __restrict__ x1,
                                                  const float* __restrict__ x2) {
    extern __shared__ float sh[];
    float* po = sh + 32*PUX_PITCH;
    int ct = blockIdx.x;
    int y4 = blockIdx.y;
    int n  = blockIdx.z & 3;
    int o  = blockIdx.z >> 2;
    const float* xs = o ? x2 : x1;
    int tid = threadIdx.x;
    int c0 = ct*32;
    #pragma unroll
    for (int i = 0; i < 16; i++) {
        int f = tid + i*256;
        int cc = f >> 7, rem = f & 127;
        int yy = rem >> 5, c4 = rem & 31;
        float4 v = *(const float4*)(xs +
            (((size_t)(n*CH + c0+cc))*HH + y4*4+yy)*WW + c4*4);
        *(float4*)&sh[cc*PUX_PITCH + yy*128 + c4*4] = v;
    }
    __syncthreads();
    {
        int c = tid >> 3, xo = (tid & 7)*4;
        float4 out;
        float* pov = &out.x;
        #pragma unroll
        for (int k = 0; k < 4; k++) {
            int px = xo + k;
            float m = NEGINF;
            #pragma unroll
            for (int yy = 0; yy < 4; yy++) {
                float4 v = *(const float4*)&sh[c*PUX_PITCH + yy*128 + px*4];
                m = fmaxf(m, fmaxf(fmaxf(v.x, v.y), fmaxf(v.z, v.w)));
            }
            pov[k] = m;
            po[c*33 + px] = m;
        }
        *(float4*)(g_p[o] + ((size_t)(n*CH + c0 + c))*LL + y4*32 + xo) = out;
    }
    __syncthreads();
    if (tid < 32) {
        float s = 0.f, sq = 0.f;
        #pragma unroll
        for (int c = 0; c < 32; c++) { float v = po[c*33 + tid]; s += v; sq += v*v; }
        int sp = y4*32 + tid;
        size_t pidx = (((size_t)(o*BATCH + n))*8 + ct)*LL + sp;
        g_lnps[pidx] = s;
        g_lnpq[pidx] = sq;
    }
    size_t rbase = (size_t)o*NPIX + (size_t)n*HH*WW + (size_t)(y4*4)*WW;
    #pragma unroll
    for (int j = 0; j < 2; j++) {
        int p = tid + j*256;
        __half2 hb[16];
        #pragma unroll
        for (int cc = 0; cc < 32; cc += 2)
            hb[cc>>1] = __floats2half2_rn(sh[cc*PUX_PITCH + p], sh[(cc+1)*PUX_PITCH + p]);
        uint4* dst = (uint4*)(g_u + (rbase + p)*CH + c0);
        const uint4* src = (const uint4*)hb;
        dst[0] = src[0]; dst[1] = src[1]; dst[2] = src[2]; dst[3] = src[3];
    }
}

// ---------------- 2. finalize LN stats ----------------
__global__ void lnfin_kernel() {
    int gi = blockIdx.x*256 + threadIdx.x;
    int on = gi / LL, sp = gi % LL;
    float s = 0.f, sq = 0.f;
    #pragma unroll
    for (int ctt = 0; ctt < 8; ctt++) {
        size_t pidx = (((size_t)on)*8 + ctt)*LL + sp;
        s += g_lnps[pidx]; sq += g_lnpq[pidx];
    }
    float mu = s * (1.0f/CH);
    g_mu1[gi] = mu;
    g_rs1[gi] = rsqrtf(sq * (1.0f/CH) - mu*mu + EPSF);
}

// ---------------- 3. dwconv3x3 + BN (LN inline), q/k/v fp16 out ----------------
__global__ __launch_bounds__(256) void dwbn2_kernel(
        const float* __restrict__ qw, const float* __restrict__ qg, const float* __restrict__ qb,
        const float* __restrict__ qm, const float* __restrict__ qvv,
        const float* __restrict__ vw, const float* __restrict__ vg, const float* __restrict__ vb,
        const float* __restrict__ vm, const float* __restrict__ vvv,
        const float* __restrict__ l1g, const float* __restrict__ l1b) {
    int c0 = blockIdx.x * 8;
    int n  = blockIdx.y;
    int o  = blockIdx.z;
    __shared__ float sp[8*1028];
    int t = threadIdx.x;
    const float* mub = g_mu1 + (size_t)(o*BATCH + n)*LL;
    const float* rsb = g_rs1 + (size_t)(o*BATCH + n)*LL;
    #pragma unroll
    for (int cc = 0; cc < 8; cc++) {
        float gc = l1g[c0+cc], bc = l1b[c0+cc];
        #pragma unroll
        for (int it = 0; it < 4; it++) {
            int spi = t + it*256;
            float raw = g_p[o][((size_t)(n*CH + c0+cc))*LL + spi];
            sp[cc*1028 + spi] = gc*(raw - mub[spi])*rsb[spi] + bc;
        }
    }
    __syncthreads();

    int cc = t & 7, jq = t >> 3;
    int c = c0 + cc;
    float wq[9], wv[9];
    #pragma unroll
    for (int k = 0; k < 9; k++) { wq[k] = qw[c*9+k]; wv[k] = vw[c*9+k]; }
    float scq = qg[c]*rsqrtf(qvv[c]+EPSF), bq = qb[c] - scq*qm[c];
    float scv = vg[c]*rsqrtf(vvv[c]+EPSF), bv = vb[c] - scv*vm[c];
    const float* s = sp + cc*1028;
    __half* oq = g_qh[o] + (size_t)(n*LL)*CH + c;
    __half* ov = g_vh[o] + (size_t)(n*LL)*CH + c;

    for (int i = 0; i < 32; i++) {
        float aq = 0.f, av = 0.f;
        #pragma unroll
        for (int di = 0; di < 3; di++) {
            int ii = i + di - 1;
            if (ii < 0 || ii >= HP) continue;
            #pragma unroll
            for (int dj = 0; dj < 3; dj++) {
                int jj = jq + dj - 1;
                if (jj < 0 || jj >= WP) continue;
                float x = s[ii*32 + jj];
                aq += wq[di*3+dj]*x;
                av += wv[di*3+dj]*x;
            }
        }
        int l = i*32 + jq;
        oq[(size_t)l*CH] = __float2half_rn(scq*aq + bq);
        ov[(size_t)l*CH] = __float2half_rn(scv*av + bv);
    }
}

// ---------------- 5. combine tile partials ----------------
__global__ void rowstat2_kernel() {
    int r = blockIdx.x*256 + threadIdx.x;
    float pm[NTILES];
    float m = NEGINF;
    #pragma unroll
    for (int i = 0; i < NTILES; i++) {
        pm[i] = g_pmax[(size_t)r*NTILES + i];
        m = fmaxf(m, pm[i]);
    }
    float sum = 0.f;
    #pragma unroll
    for (int i = 0; i < NTILES; i++)
        sum += g_psum[(size_t)r*NTILES + i] * __expf(pm[i] - m);
    g_rmax[r] = m;
    g_rinv[r] = 1.f/sum;
}

// ---------------- 7. S2 softmax over heads + transpose ----------------
__global__ __launch_bounds__(256) void s2t_kernel() {
    __shared__ __half sm[8][32][36];
    int t = threadIdx.x;
    int s0 = blockIdx.x*32, l0 = blockIdx.y*32, n = blockIdx.z;
    int row = t >> 3, seg = t & 7;
    #pragma unroll
    for (int h = 0; h < NHEAD; h++) {
        uint2 v = *(const uint2*)(g_qkh +
            (((size_t)(n*NHEAD + h))*LL + l0 + row)*LL + s0 + seg*4);
        *(uint2*)&sm[h][row][seg*4] = v;
    }
    __syncthreads();
    #pragma unroll
    for (int j = 0; j < 4; j++) {
        int e = t*4 + j;
        int l = e >> 5, s = e & 31;
        float v[NHEAD];
        float mx = NEGINF;
        #pragma unroll
        for (int h = 0; h < NHEAD; h++) {
            v[h] = __half2float(sm[h][l][s]);
            mx = fmaxf(mx, v[h]);
        }
        float smm = 0.f;
        #pragma unroll
        for (int h = 0; h < NHEAD; h++) { v[h] = __expf(v[h]-mx); smm += v[h]; }
        float ri = 1.f/smm;
        #pragma unroll
        for (int h = 0; h < NHEAD; h++)
            sm[h][l][s] = __float2half_rn(v[h]*ri);
    }
    __syncthreads();
    #pragma unroll
    for (int h = 0; h < NHEAD; h++) {
        __half tmp[4];
        #pragma unroll
        for (int jj = 0; jj < 4; jj++) tmp[jj] = sm[h][seg*4+jj][row];
        *(uint2*)(g_s2t + (((size_t)(n*NHEAD + h))*LL + s0 + row)*LL + l0 + seg*4) =
            *(uint2*)tmp;
    }
}

// ---------------- 10. fused LN stats + apply + residual + write-out ----------------
__global__ __launch_bounds__(256) void out_fused_kernel(
        const float* __restrict__ x1, const float* __restrict__ x2,
        const float* __restrict__ lg, const float* __restrict__ lb,
        float* __restrict__ out) {
    int xt = blockIdx.x;
    int y  = blockIdx.y;
    int n  = blockIdx.z % BATCH;
    int o  = blockIdx.z / BATCH;
    __shared__ float zsh[32][257];
    __shared__ float smu[32], srs[32];
    int tid = threadIdx.x;
    size_t rbase = (size_t)o*NPIX + (size_t)n*HH*WW + (size_t)y*WW + xt*32;
    #pragma unroll
    for (int j = 0; j < 4; j++) {
        int px = j*8 + (tid >> 5);
        int c = (tid & 31) * 8;
        uint4 raw = *(const uint4*)(g_z2h + (rbase + px)*CH + c);
        const __half2* hp = (const __half2*)&raw;
        #pragma unroll
        for (int q = 0; q < 4; q++) {
            float2 f = __half22float2(hp[q]);
            zsh[px][c + 2*q]     = f.x;
            zsh[px][c + 2*q + 1] = f.y;
        }
    }
    __syncthreads();
    int w = tid >> 5, lane = tid & 31;
    #pragma unroll
    for (int i = 0; i < 4; i++) {
        int px = w*4 + i;
        float s = 0.f, sq = 0.f;
        #pragma unroll
        for (int k = 0; k < 8; k++) { float v = zsh[px][lane + k*32]; s += v; sq += v*v; }
        #pragma unroll
        for (int off = 16; off; off >>= 1) {
            s  += __shfl_xor_sync(0xffffffffu, s,  off);
            sq += __shfl_xor_sync(0xffffffffu, sq, off);
        }
        if (!lane) {
            float mu = s * (1.0f/CH);
            smu[px] = mu;
            srs[px] = rsqrtf(sq * (1.0f/CH) - mu*mu + EPSF);
        }
    }
    __syncthreads();
    const float* xs = o ? x2 : x1;
    int cth = tid >> 5, tx = tid & 31;
    float mu = smu[tx], rs = srs[tx];
    size_t xbase = ((size_t)(n*CH))*HH*WW + (size_t)y*WW + xt*32 + tx;
    float* outb = out + (size_t)o*NPIX*CH;
    #pragma unroll 8
    for (int cc = 0; cc < 32; cc++) {
        int c = cc*8 + cth;
        float val = lg[c]*(zsh[tx][c] - mu)*rs + lb[c];
        size_t gi = xbase + (size_t)c*HH*WW;
        outb[gi] = xs[gi] + val;
    }
}

// ---------------- launch ----------------
extern "C" void kernel_launch(void* const* d_in, const int* in_sizes, int n_in,
                              void* d_out, int out_size) {
    const float* x1     = (const float*)d_in[0];
    const float* x2     = (const float*)d_in[1];
    const float* qk_w   = (const float*)d_in[2];
    const float* qk_g   = (const float*)d_in[3];
    const float* qk_b   = (const float*)d_in[4];
    const float* qk_m   = (const float*)d_in[5];
    const float* qk_v   = (const float*)d_in[6];
    const float* v_w    = (const float*)d_in[7];
    const float* v_g    = (const float*)d_in[8];
    const float* v_b    = (const float*)d_in[9];
    const float* v_m    = (const float*)d_in[10];
    const float* v_v    = (const float*)d_in[11];
    const float* ln1_g  = (const float*)d_in[12];
    const float* ln1_b  = (const float*)d_in[13];
    const float* ln2_g  = (const float*)d_in[14];
    const float* ln2_b  = (const float*)d_in[15];
    const float* merge_w= (const float*)d_in[16];
    const float* mlp_w1 = (const float*)d_in[17];
    const float* mlp_w2 = (const float*)d_in[18];
    float* out = (float*)d_out;

    __half *pm, *pmmh, *pmmw, *pz1, *pz2h, *pmw, *pw1b, *pw2;
    cudaGetSymbolAddress((void**)&pm,   g_m);
    cudaGetSymbolAddress((void**)&pmmh, g_mmh);
    cudaGetSymbolAddress((void**)&pmmw, g_mmw);
    cudaGetSymbolAddress((void**)&pz1,  g_z1);
    cudaGetSymbolAddress((void**)&pz2h, g_z2h);
    cudaGetSymbolAddress((void**)&pmw,  g_mwh);
    cudaGetSymbolAddress((void**)&pw1b, g_w1b);
    cudaGetSymbolAddress((void**)&pw2,  g_w2h);

    const size_t MOFF  = (size_t)BATCH*LL*CH;    // per-o offset in g_m / g_mmh
    const size_t MWOFF = (size_t)BATCH*LL*C2;    // per-o offset in g_mmw

    cudaFuncSetAttribute(hgemm_kernel,    cudaFuncAttributeMaxDynamicSharedMemorySize, GEMM_SMEM);
    cudaFuncSetAttribute(hgemm_up_kernel, cudaFuncAttributeMaxDynamicSharedMemorySize, GEMMUP_SMEM);
    cudaFuncSetAttribute(pux_kernel,      cudaFuncAttributeMaxDynamicSharedMemorySize, PUX_SMEM);

    static cudaStream_t sB = nullptr;
    static cudaEvent_t evFork = nullptr, evJoin = nullptr;
    if (!sB) {
        cudaStreamCreateWithFlags(&sB, cudaStreamNonBlocking);
        cudaEventCreateWithFlags(&evFork, cudaEventDisableTiming);
        cudaEventCreateWithFlags(&evJoin, cudaEventDisableTiming);
    }

    roundh3_kernel<<<(C2*C2+255)/256, 256>>>(merge_w, mlp_w1, mlp_w2);

    pux_kernel<<<dim3(CH/32, HP, 2*BATCH), 256, PUX_SMEM>>>(x1, x2);
    lnfin_kernel<<<(2*BATCH*LL)/256, 256>>>();

    dwbn2_kernel<<<dim3(CH/8, BATCH, 2), 256>>>(qk_w, qk_g, qk_b, qk_m, qk_v,
                                                v_w, v_g, v_b, v_m, v_v, ln1_g, ln1_b);

    // attention: fork after qkmma into two independent chains
    qkmma_kernel<<<dim3(LL/128, LL/128, BATCH*NHEAD), 256>>>();
    cudaEventRecord(evFork, 0);
    cudaStreamWaitEvent(sB, evFork, 0);

    // chain B (stream sB): S2 softmax+transpose -> m2 -> merge(o=1) -> mmw(o=1)
    s2t_kernel<<<dim3(LL/32, LL/32, BATCH), 256, 0, sB>>>();
    av_kernel<<<dim3(LL/128, BATCH*NHEAD), 256, 0, sB>>>(1);
    hgemm_kernel<<<dim3(CH/128, (BATCH*LL)/128), 256, GEMM_SMEM, sB>>>(
        pm + MOFF, pmw, pmmh + MOFF, BATCH*LL, CH, CH, 0, 1);
    hgemm_kernel<<<dim3(C2/128, (BATCH*LL)/128), 256, GEMM_SMEM, sB>>>(
        pmmh + MOFF, pw1b, pmmw + MWOFF, BATCH*LL, C2, CH, 0, 1);
    cudaEventRecord(evJoin, sB);

    // chain A (legacy stream): row stats -> m1 -> merge(o=0) -> mmw(o=0)
    rowstat2_kernel<<<BATCH*NHEAD*LL/256, 256>>>();
    av_kernel<<<dim3(LL/128, BATCH*NHEAD), 256>>>(0);
    hgemm_kernel<<<dim3(CH/128, (BATCH*LL)/128), 256, GEMM_SMEM>>>(
        pm, pmw, pmmh, BATCH*LL, CH, CH, 0, 1);
    hgemm_kernel<<<dim3(C2/128, (BATCH*LL)/128), 256, GEMM_SMEM>>>(
        pmmh, pw1b, pmmw, BATCH*LL, C2, CH, 0, 1);

    // join before MLP1 (needs both halves of g_mmw)
    cudaStreamWaitEvent(0, evJoin, 0);

    // MLP1: x-half GEMM + upsample-add + relu
    hgemm_up_kernel<<<dim3(C2/128, NROWS/128), 256, GEMMUP_SMEM>>>();
    // MLP2 (z2 fp16)
    hgemm_kernel<<<dim3(CH/128, NROWS/128), 256, GEMM_SMEM>>>(
        pz1, pw2, pz2h, NROWS, CH, C2, 0, 1);

    out_fused_kernel<<<dim3(WW/32, HH, 2*BATCH), 256>>>(x1, x2, ln2_g, ln2_b, out);
}